// round 6
// baseline (speedup 1.0000x reference)
#include <cuda_runtime.h>
#include <cuda_bf16.h>
#include <cstdint>

// Problem constants
#define BB 8
#define NN 8192
#define SS 2048
#define D1 256
#define D2 512
#define CIN 768
#define HH 512

typedef __nv_bfloat16 bf16;

// ---------------- scratch (static device globals; no runtime alloc) ----------------
__device__ float g_P2T[(size_t)BB * SS * D2];
__device__ int   g_idx[(size_t)BB * NN * 3];
__device__ float g_wgt[(size_t)BB * NN * 3];
__device__ bf16 g_FThi[(size_t)BB * NN * CIN];
__device__ bf16 g_FTlo[(size_t)BB * NN * CIN];
__device__ bf16 g_W0hi[HH * CIN], g_W0lo[HH * CIN];
__device__ bf16 g_W1hi[HH * HH],  g_W1lo[HH * HH];
__device__ float g_X0[(size_t)BB * HH * NN];           // (b, c, n)
__device__ float g_sum0[HH], g_sq0[HH], g_sum1[HH], g_sq1[HH];
__device__ float g_scale0[HH], g_shift0[HH], g_scale1[HH], g_shift1[HH];

// ======================= low-level helpers =======================
__device__ __forceinline__ uint32_t smem_u32(const void* p) {
    uint32_t a;
    asm("{ .reg .u64 t; cvta.to.shared.u64 t, %1; cvt.u32.u64 %0, t; }" : "=r"(a) : "l"(p));
    return a;
}
__device__ __forceinline__ void ldsm4(uint32_t& r0, uint32_t& r1, uint32_t& r2,
                                      uint32_t& r3, uint32_t a) {
    asm volatile("ldmatrix.sync.aligned.m8n8.x4.shared.b16 {%0,%1,%2,%3},[%4];"
                 : "=r"(r0), "=r"(r1), "=r"(r2), "=r"(r3) : "r"(a));
}
__device__ __forceinline__ void ldsm4t(uint32_t& r0, uint32_t& r1, uint32_t& r2,
                                       uint32_t& r3, uint32_t a) {
    asm volatile("ldmatrix.sync.aligned.m8n8.x4.trans.shared.b16 {%0,%1,%2,%3},[%4];"
                 : "=r"(r0), "=r"(r1), "=r"(r2), "=r"(r3) : "r"(a));
}
__device__ __forceinline__ void mma16816(float* d, const uint32_t* a, const uint32_t* b) {
    asm volatile(
        "mma.sync.aligned.m16n8k16.row.col.f32.bf16.bf16.f32 "
        "{%0,%1,%2,%3},{%4,%5,%6,%7},{%8,%9},{%0,%1,%2,%3};"
        : "+f"(d[0]), "+f"(d[1]), "+f"(d[2]), "+f"(d[3])
        : "r"(a[0]), "r"(a[1]), "r"(a[2]), "r"(a[3]), "r"(b[0]), "r"(b[1]));
}
__device__ __forceinline__ void cpa16(uint32_t dst, const void* src) {
    asm volatile("cp.async.cg.shared.global [%0],[%1],16;" :: "r"(dst), "l"(src));
}
#define CP_COMMIT() asm volatile("cp.async.commit_group;" ::: "memory")
#define CP_WAIT(n) asm volatile("cp.async.wait_group %0;" :: "n"(n) : "memory")

__device__ __forceinline__ void split_bf(float v, bf16& h, bf16& l) {
    h = __float2bfloat16_rn(v);
    l = __float2bfloat16_rn(v - __bfloat162float(h));
}
__device__ __forceinline__ uint32_t pack2(bf16 a, bf16 b) {
    __nv_bfloat162 t = __halves2bfloat162(a, b);
    return *reinterpret_cast<uint32_t*>(&t);
}

// ---------------- top-3 helper ----------------
struct Top3 { float d0, d1, d2; int i0, i1, i2; };
__device__ __forceinline__ void t3_ins(Top3& q, float t, int s) {
    if (t < q.d2) {
        if (t < q.d1) {
            q.d2 = q.d1; q.i2 = q.i1;
            if (t < q.d0) { q.d1 = q.d0; q.i1 = q.i0; q.d0 = t; q.i0 = s; }
            else          { q.d1 = t;    q.i1 = s; }
        } else { q.d2 = t; q.i2 = s; }
    }
}

// ======================= fused prep kernel =======================
// block order: top3 FIRST (long-running), then transposes / converts / zeroing
#define NB_T3 128
#define NB_P2 8192
#define NB_P1 16384
#define NB_C0 (HH * CIN / 1024)
#define NB_C1 (HH * HH / 1024)
#define NB_TOTAL (NB_T3 + NB_P2 + NB_P1 + NB_C0 + NB_C1 + 1)

__global__ __launch_bounds__(256)
void prep_kernel(const float* __restrict__ xyz1, const float* __restrict__ xyz2,
                 const float* __restrict__ p1, const float* __restrict__ p2,
                 const float* __restrict__ w0g, const float* __restrict__ w1g) {
    __shared__ float sh[8192];
    int r = blockIdx.x;
    const int tid = threadIdx.x;

    if (r < NB_T3) {
        // ---- top-3 nearest neighbors ----
        float* sx = sh;
        float* sy = sh + 2048;
        float* sz = sh + 4096;
        float* sn = sh + 6144;
        const int b = r >> 4;
        const int nbase = (r & 15) * 512;

        for (int i = tid; i < SS; i += 256) {
            float x = xyz2[((size_t)b * 3 + 0) * SS + i];
            float y = xyz2[((size_t)b * 3 + 1) * SS + i];
            float z = xyz2[((size_t)b * 3 + 2) * SS + i];
            sx[i] = x; sy[i] = y; sz[i] = z;
            sn[i] = x * x + y * y + z * z;
        }
        __syncthreads();

        const int na = nbase + tid;
        const int nb = nbase + 256 + tid;
        float xa = xyz1[((size_t)b * 3 + 0) * NN + na];
        float ya = xyz1[((size_t)b * 3 + 1) * NN + na];
        float za = xyz1[((size_t)b * 3 + 2) * NN + na];
        float xb = xyz1[((size_t)b * 3 + 0) * NN + nb];
        float yb = xyz1[((size_t)b * 3 + 1) * NN + nb];
        float zb = xyz1[((size_t)b * 3 + 2) * NN + nb];
        float n1a = xa * xa + ya * ya + za * za;
        float n1b = xb * xb + yb * yb + zb * zb;
        float mxa = -2.f * xa, mya = -2.f * ya, mza = -2.f * za;
        float mxb = -2.f * xb, myb = -2.f * yb, mzb = -2.f * zb;

        Top3 qa = {3.4e38f, 3.4e38f, 3.4e38f, 0, 0, 0};
        Top3 qb = {3.4e38f, 3.4e38f, 3.4e38f, 0, 0, 0};

        for (int s = 0; s < SS; s += 4) {
            float4 vx = ((float4*)sx)[s >> 2], vy = ((float4*)sy)[s >> 2];
            float4 vz = ((float4*)sz)[s >> 2], vn = ((float4*)sn)[s >> 2];
            float t;
            t = fmaf(mxa, vx.x, vn.x); t = fmaf(mya, vy.x, t); t = fmaf(mza, vz.x, t); t3_ins(qa, t, s + 0);
            t = fmaf(mxa, vx.y, vn.y); t = fmaf(mya, vy.y, t); t = fmaf(mza, vz.y, t); t3_ins(qa, t, s + 1);
            t = fmaf(mxa, vx.z, vn.z); t = fmaf(mya, vy.z, t); t = fmaf(mza, vz.z, t); t3_ins(qa, t, s + 2);
            t = fmaf(mxa, vx.w, vn.w); t = fmaf(mya, vy.w, t); t = fmaf(mza, vz.w, t); t3_ins(qa, t, s + 3);
            t = fmaf(mxb, vx.x, vn.x); t = fmaf(myb, vy.x, t); t = fmaf(mzb, vz.x, t); t3_ins(qb, t, s + 0);
            t = fmaf(mxb, vx.y, vn.y); t = fmaf(myb, vy.y, t); t = fmaf(mzb, vz.y, t); t3_ins(qb, t, s + 1);
            t = fmaf(mxb, vx.z, vn.z); t = fmaf(myb, vy.z, t); t = fmaf(mzb, vz.z, t); t3_ins(qb, t, s + 2);
            t = fmaf(mxb, vx.w, vn.w); t = fmaf(myb, vy.w, t); t = fmaf(mzb, vz.w, t); t3_ins(qb, t, s + 3);
        }

        {
            size_t base = ((size_t)b * NN + na) * 3;
            float d0 = qa.d0 + n1a, d1 = qa.d1 + n1a, d2 = qa.d2 + n1a;
            float w0 = 1.0f / (d0 + 1e-8f), w1 = 1.0f / (d1 + 1e-8f), w2 = 1.0f / (d2 + 1e-8f);
            float inv = 1.0f / (w0 + w1 + w2);
            g_idx[base + 0] = qa.i0; g_idx[base + 1] = qa.i1; g_idx[base + 2] = qa.i2;
            g_wgt[base + 0] = w0 * inv; g_wgt[base + 1] = w1 * inv; g_wgt[base + 2] = w2 * inv;
        }
        {
            size_t base = ((size_t)b * NN + nb) * 3;
            float d0 = qb.d0 + n1b, d1 = qb.d1 + n1b, d2 = qb.d2 + n1b;
            float w0 = 1.0f / (d0 + 1e-8f), w1 = 1.0f / (d1 + 1e-8f), w2 = 1.0f / (d2 + 1e-8f);
            float inv = 1.0f / (w0 + w1 + w2);
            g_idx[base + 0] = qb.i0; g_idx[base + 1] = qb.i1; g_idx[base + 2] = qb.i2;
            g_wgt[base + 0] = w0 * inv; g_wgt[base + 1] = w1 * inv; g_wgt[base + 2] = w2 * inv;
        }
        return;
    }
    r -= NB_T3;
    if (r < NB_P2) {
        // ---- transpose points2 (B,512,2048) -> P2T (B,2048,512) ----
        int b = r >> 10, y = (r >> 6) & 15, x = r & 63;
        int c0 = y * 32, s0 = x * 32;
        int tx = tid & 31, ty = tid >> 5;
        float (*t)[33] = (float(*)[33])sh;
#pragma unroll
        for (int j = ty; j < 32; j += 8)
            t[j][tx] = p2[((size_t)b * D2 + c0 + j) * SS + s0 + tx];
        __syncthreads();
#pragma unroll
        for (int j = ty; j < 32; j += 8)
            g_P2T[((size_t)b * SS + s0 + j) * D2 + c0 + tx] = t[tx][j];
        return;
    }
    r -= NB_P2;
    if (r < NB_P1) {
        // ---- transpose points1 (B,256,8192) -> FThi/FTlo[:, :, 0:256] ----
        int b = r >> 11, y = (r >> 8) & 7, x = r & 255;
        int c0 = y * 32, n0 = x * 32;
        int tx = tid & 31, ty = tid >> 5;
        float (*t)[33] = (float(*)[33])sh;
#pragma unroll
        for (int j = ty; j < 32; j += 8)
            t[j][tx] = p1[((size_t)b * D1 + c0 + j) * NN + n0 + tx];
        __syncthreads();
#pragma unroll
        for (int j = ty; j < 32; j += 8) {
            bf16 h, l;
            split_bf(t[tx][j], h, l);
            size_t off = ((size_t)b * NN + n0 + j) * CIN + c0 + tx;
            g_FThi[off] = h;
            g_FTlo[off] = l;
        }
        return;
    }
    r -= NB_P1;
    if (r < NB_C0 + NB_C1) {
        // ---- weight split to bf16 hi/lo (vectorized x4) ----
        const float* src;
        bf16 *hi, *lo;
        int i;
        if (r < NB_C0) { src = w0g; hi = g_W0hi; lo = g_W0lo; i = r * 1024 + tid * 4; }
        else { src = w1g; hi = g_W1hi; lo = g_W1lo; i = (r - NB_C0) * 1024 + tid * 4; }
        float4 v = *(const float4*)(src + i);
        bf16 h0, l0, h1, l1, h2, l2, h3, l3;
        split_bf(v.x, h0, l0); split_bf(v.y, h1, l1);
        split_bf(v.z, h2, l2); split_bf(v.w, h3, l3);
        *(uint2*)&hi[i] = make_uint2(pack2(h0, h1), pack2(h2, h3));
        *(uint2*)&lo[i] = make_uint2(pack2(l0, l1), pack2(l2, l3));
        return;
    }
    // ---- zero stats accumulators ----
    if (tid < 256) {
        g_sum0[tid] = 0.f; g_sum0[tid + 256] = 0.f;
        g_sq0[tid] = 0.f;  g_sq0[tid + 256] = 0.f;
        g_sum1[tid] = 0.f; g_sum1[tid + 256] = 0.f;
        g_sq1[tid] = 0.f;  g_sq1[tid + 256] = 0.f;
    }
}

// ---------------- gather + interpolate -> FThi/FTlo[:, :, 256:768] ----------------
__global__ void gather_kernel() {
    int wglob = blockIdx.x * 8 + (threadIdx.x >> 5);
    int lane = threadIdx.x & 31;
    int b = wglob / NN;
    size_t base = (size_t)wglob * 3;
    int i0 = g_idx[base + 0], i1 = g_idx[base + 1], i2 = g_idx[base + 2];
    float w0 = g_wgt[base + 0], w1 = g_wgt[base + 1], w2 = g_wgt[base + 2];
    const float* r0 = g_P2T + ((size_t)b * SS + i0) * D2;
    const float* r1 = g_P2T + ((size_t)b * SS + i1) * D2;
    const float* r2 = g_P2T + ((size_t)b * SS + i2) * D2;
    size_t dbase = (size_t)wglob * CIN + D1;
#pragma unroll
    for (int c = lane * 4; c < D2; c += 128) {
        float4 v0 = *(const float4*)&r0[c];
        float4 v1 = *(const float4*)&r1[c];
        float4 v2 = *(const float4*)&r2[c];
        float o0 = w0 * v0.x + w1 * v1.x + w2 * v2.x;
        float o1 = w0 * v0.y + w1 * v1.y + w2 * v2.y;
        float o2 = w0 * v0.z + w1 * v1.z + w2 * v2.z;
        float o3 = w0 * v0.w + w1 * v1.w + w2 * v2.w;
        bf16 h0, l0, h1, l1, h2, l2, h3, l3;
        split_bf(o0, h0, l0); split_bf(o1, h1, l1);
        split_bf(o2, h2, l2); split_bf(o3, h3, l3);
        *(uint2*)&g_FThi[dbase + c] = make_uint2(pack2(h0, h1), pack2(h2, h3));
        *(uint2*)&g_FTlo[dbase + c] = make_uint2(pack2(l0, l1), pack2(l2, l3));
    }
}

// ======================= HMMA GEMM 1 (A 2-stage + B 3-stage, fused stats) =======================
#define T1 10240                          // bytes per tensor tile (128 x 40 bf16)
#define AS1 (2 * T1)                      // A stage (hi+lo) 20KB
#define BS1 (2 * T1)                      // B stage (hi+lo) 20KB
static constexpr int G1_SMEM = 2 * AS1 + 3 * BS1;   // 102400 -> 2 CTAs/SM

__global__ __launch_bounds__(256)
void hmma_gemm1(const bf16* __restrict__ Ahi, const bf16* __restrict__ Alo,
                const bf16* __restrict__ Bhi_g, const bf16* __restrict__ Blo_g,
                const float* __restrict__ bias, float* __restrict__ out) {
    extern __shared__ char smem[];
    const uint32_t sb = smem_u32(smem);
    const uint32_t sbB = sb + 2 * AS1;
    const int tid = threadIdx.x, lane = tid & 31, wid = tid >> 5;
    const int m0 = blockIdx.x * 128, n0 = blockIdx.y * 128, b = blockIdx.z;
    const int wm = (wid & 3) * 32, wn = (wid >> 2) * 64;

    const bf16* Arow_hi = Ahi + (size_t)m0 * CIN;
    const bf16* Arow_lo = Alo + (size_t)m0 * CIN;
    const bf16* Brow_hi = Bhi_g + ((size_t)b * NN + n0) * CIN;
    const bf16* Brow_lo = Blo_g + ((size_t)b * NN + n0) * CIN;

    float acc[2][8][4];
#pragma unroll
    for (int i = 0; i < 2; i++)
#pragma unroll
        for (int j = 0; j < 8; j++)
#pragma unroll
            for (int q = 0; q < 4; q++) acc[i][j][q] = 0.f;

    const int row_l = tid >> 2, c16 = (tid & 3);
    auto issueA = [&](int kb, uint32_t sbuf) {
#pragma unroll
        for (int t = 0; t < 2; t++) {
            int row = row_l + t * 64;
            uint32_t d = sbuf + row * 80 + c16 * 16;
            cpa16(d,      Arow_hi + (size_t)row * CIN + kb + c16 * 8);
            cpa16(d + T1, Arow_lo + (size_t)row * CIN + kb + c16 * 8);
        }
        CP_COMMIT();
    };
    auto issueB = [&](int kb, uint32_t sbuf) {
#pragma unroll
        for (int t = 0; t < 2; t++) {
            int row = row_l + t * 64;
            uint32_t d = sbuf + row * 80 + c16 * 16;
            cpa16(d,      Brow_hi + (size_t)row * CIN + kb + c16 * 8);
            cpa16(d + T1, Brow_lo + (size_t)row * CIN + kb + c16 * 8);
        }
        CP_COMMIT();
    };

    const int KT = CIN / 32;   // 24
    // prologue: groups in order gB0, gB1, gA0, gB2
    issueB(0, sbB + 0 * BS1);
    issueB(32, sbB + 1 * BS1);
    issueA(0, sb + 0 * AS1);
    issueB(64, sbB + 2 * BS1);

    for (int c = 0; c < KT; c++) {
        // top: issue A(c+1)
        if (c + 1 < KT) issueA((c + 1) * 32, sb + ((c + 1) & 1) * AS1);
        // wait so that group gA(c) (and everything older, incl. gB(c)) is complete
        if (c <= KT - 3)      CP_WAIT(2);
        else if (c == KT - 2) CP_WAIT(1);
        else                  CP_WAIT(0);
        __syncthreads();

        const uint32_t sA = sb + (c & 1) * AS1;
        const uint32_t sB = sbB + (c % 3) * BS1;
#pragma unroll
        for (int ks = 0; ks < 2; ks++) {
            const int k16 = ks * 16;
            uint32_t ah[2][4], al[2][4];
#pragma unroll
            for (int mi = 0; mi < 2; mi++) {
                uint32_t ad = sA + (wm + mi * 16 + (lane & 15)) * 80
                                 + (k16 + ((lane >> 4) << 3)) * 2;
                ldsm4(ah[mi][0], ah[mi][1], ah[mi][2], ah[mi][3], ad);
                ldsm4(al[mi][0], al[mi][1], al[mi][2], al[mi][3], ad + T1);
            }
            uint32_t bh[8][2], bl[8][2];
#pragma unroll
            for (int ng = 0; ng < 4; ng++) {
                uint32_t row = wn + ng * 16 + (lane & 7) + ((lane & 16) >> 1);
                uint32_t col = k16 + (lane & 8);
                uint32_t ad = sB + row * 80 + col * 2;
                uint32_t r0, r1, r2, r3;
                ldsm4(r0, r1, r2, r3, ad);
                bh[2 * ng][0] = r0; bh[2 * ng][1] = r1;
                bh[2 * ng + 1][0] = r2; bh[2 * ng + 1][1] = r3;
                ldsm4(r0, r1, r2, r3, ad + T1);
                bl[2 * ng][0] = r0; bl[2 * ng][1] = r1;
                bl[2 * ng + 1][0] = r2; bl[2 * ng + 1][1] = r3;
            }
#pragma unroll
            for (int mi = 0; mi < 2; mi++)
#pragma unroll
                for (int ni = 0; ni < 8; ni++) {
                    mma16816(acc[mi][ni], ah[mi], bh[ni]);
                    mma16816(acc[mi][ni], ah[mi], bl[ni]);
                    mma16816(acc[mi][ni], al[mi], bh[ni]);
                }
        }
        __syncthreads();
        // bottom: issue B(c+3) into buffer (c+3)%3 == c%3 (just finished reading, post-sync)
        if (c + 3 < KT) issueB((c + 3) * 32, sbB + (c % 3) * BS1);
    }

    // epilogue -> out (b, m, n) + bias, fused channel stats via atomics
    const int gq = lane >> 2, tq = lane & 3;
#pragma unroll
    for (int mi = 0; mi < 2; mi++) {
        int r0 = m0 + wm + mi * 16 + gq;
        float bv0 = bias[r0], bv1 = bias[r0 + 8];
        float* o0 = out + ((size_t)b * HH + r0) * NN;
        float* o1 = o0 + (size_t)8 * NN;
        float s0 = 0.f, q0 = 0.f, s1 = 0.f, q1 = 0.f;
#pragma unroll
        for (int ni = 0; ni < 8; ni++) {
            int cc = n0 + wn + ni * 8 + tq * 2;
            float y0 = acc[mi][ni][0] + bv0, y1 = acc[mi][ni][1] + bv0;
            float y2 = acc[mi][ni][2] + bv1, y3 = acc[mi][ni][3] + bv1;
            *(float2*)&o0[cc] = make_float2(y0, y1);
            *(float2*)&o1[cc] = make_float2(y2, y3);
            s0 += y0 + y1; q0 += y0 * y0 + y1 * y1;
            s1 += y2 + y3; q1 += y2 * y2 + y3 * y3;
        }
#pragma unroll
        for (int o = 1; o <= 2; o <<= 1) {
            s0 += __shfl_xor_sync(~0u, s0, o);
            q0 += __shfl_xor_sync(~0u, q0, o);
            s1 += __shfl_xor_sync(~0u, s1, o);
            q1 += __shfl_xor_sync(~0u, q1, o);
        }
        if (tq == 0) {
            atomicAdd(&g_sum0[r0], s0);     atomicAdd(&g_sq0[r0], q0);
            atomicAdd(&g_sum0[r0 + 8], s1); atomicAdd(&g_sq0[r0 + 8], q1);
        }
    }
}

// ======================= HMMA GEMM 2 (fused BN+ReLU on B, fused stats) =======================
#define AT2 10240
#define AST2 (2 * AT2)
#define BT2 8704                 // 32 * 272
#define BST2 (2 * BT2)
static constexpr int G2_SMEM = 2 * AST2 + 2 * BST2;  // 75776

__global__ __launch_bounds__(256)
void hmma_gemm2(const bf16* __restrict__ Ahi, const bf16* __restrict__ Alo,
                const float* __restrict__ X0,
                const float* __restrict__ scale, const float* __restrict__ shift,
                const float* __restrict__ bias, float* __restrict__ out) {
    extern __shared__ char smem[];
    const uint32_t sb = smem_u32(smem);
    const int tid = threadIdx.x, lane = tid & 31, wid = tid >> 5;
    const int m0 = blockIdx.x * 128, n0 = blockIdx.y * 128, b = blockIdx.z;
    const int wm = (wid & 3) * 32, wn = (wid >> 2) * 64;

    const bf16* Arow_hi = Ahi + (size_t)m0 * HH;
    const bf16* Arow_lo = Alo + (size_t)m0 * HH;
    const float* Xb = X0 + (size_t)b * HH * NN + n0;

    float acc[2][8][4];
#pragma unroll
    for (int i = 0; i < 2; i++)
#pragma unroll
        for (int j = 0; j < 8; j++)
#pragma unroll
            for (int q = 0; q < 4; q++) acc[i][j][q] = 0.f;

    const int brow = tid >> 3, bcol = (tid & 7) * 16;
    float x[16];
    float scl, shf;

    const int row_l = tid >> 2, c16 = (tid & 3);
    {
#pragma unroll
        for (int t = 0; t < 2; t++) {
            int row = row_l + t * 64;
            uint32_t d = sb + row * 80 + c16 * 16;
            cpa16(d,       Arow_hi + (size_t)row * HH + c16 * 8);
            cpa16(d + AT2, Arow_lo + (size_t)row * HH + c16 * 8);
        }
        CP_COMMIT();
        const float* src = Xb + (size_t)brow * NN + bcol;
#pragma unroll
        for (int j = 0; j < 4; j++) {
            float4 v = *(const float4*)(src + j * 4);
            x[4 * j] = v.x; x[4 * j + 1] = v.y; x[4 * j + 2] = v.z; x[4 * j + 3] = v.w;
        }
        scl = scale[brow];
        shf = shift[brow];
    }

    const uint32_t sBbase = sb + 2 * AST2;
    const int KT = HH / 32;  // 16
    for (int c = 0; c < KT; c++) {
        const int buf = c & 1;
        {
            uint32_t doff = (buf * BST2 + brow * 272 + bcol * 2) + 2 * AST2;
#pragma unroll
            for (int j = 0; j < 4; j++) {
                float y0 = fmaxf(fmaf(x[4 * j + 0], scl, shf), 0.f);
                float y1 = fmaxf(fmaf(x[4 * j + 1], scl, shf), 0.f);
                float y2 = fmaxf(fmaf(x[4 * j + 2], scl, shf), 0.f);
                float y3 = fmaxf(fmaf(x[4 * j + 3], scl, shf), 0.f);
                bf16 h0, l0, h1, l1, h2, l2, h3, l3;
                split_bf(y0, h0, l0); split_bf(y1, h1, l1);
                split_bf(y2, h2, l2); split_bf(y3, h3, l3);
                *(uint2*)(smem + doff + j * 8) = make_uint2(pack2(h0, h1), pack2(h2, h3));
                *(uint2*)(smem + doff + BT2 + j * 8) = make_uint2(pack2(l0, l1), pack2(l2, l3));
            }
        }
        if (c + 1 < KT) {
            const int kb = (c + 1) * 32;
            const uint32_t s2 = sb + (buf ^ 1) * AST2;
#pragma unroll
            for (int t = 0; t < 2; t++) {
                int row = row_l + t * 64;
                uint32_t d = s2 + row * 80 + c16 * 16;
                cpa16(d,       Arow_hi + (size_t)row * HH + kb + c16 * 8);
                cpa16(d + AT2, Arow_lo + (size_t)row * HH + kb + c16 * 8);
            }
            CP_COMMIT();
            const float* src = Xb + (size_t)(kb + brow) * NN + bcol;
#pragma unroll
            for (int j = 0; j < 4; j++) {
                float4 v = *(const float4*)(src + j * 4);
                x[4 * j] = v.x; x[4 * j + 1] = v.y; x[4 * j + 2] = v.z; x[4 * j + 3] = v.w;
            }
            scl = scale[kb + brow];
            shf = shift[kb + brow];
            CP_WAIT(1);
        } else {
            CP_WAIT(0);
        }
        __syncthreads();

        const uint32_t sA = sb + buf * AST2;
        const uint32_t sB = sBbase + buf * BST2;
#pragma unroll
        for (int ks = 0; ks < 2; ks++) {
            const int k16 = ks * 16;
            uint32_t ah[2][4], al[2][4];
#pragma unroll
            for (int mi = 0; mi < 2; mi++) {
                uint32_t ad = sA + (wm + mi * 16 + (lane & 15)) * 80
                                 + (k16 + ((lane >> 4) << 3)) * 2;
                ldsm4(ah[mi][0], ah[mi][1], ah[mi][2], ah[mi][3], ad);
                ldsm4(al[mi][0], al[mi][1], al[mi][2], al[mi][3], ad + AT2);
            }
            uint32_t bh[8][2], bl[8][2];
#pragma unroll
            for (int ng = 0; ng < 4; ng++) {
                uint32_t row = k16 + (lane & 7) + (lane & 8);
                uint32_t col = wn + ng * 16 + ((lane >> 4) << 3);
                uint32_t ad = sB + row * 272 + col * 2;
                uint32_t r0, r1, r2, r3;
                ldsm4t(r0, r1, r2, r3, ad);
                bh[2 * ng][0] = r0; bh[2 * ng][1] = r1;
                bh[2 * ng + 1][0] = r2; bh[2 * ng + 1][1] = r3;
                ldsm4t(r0, r1, r2, r3, ad + BT2);
                bl[2 * ng][0] = r0; bl[2 * ng][1] = r1;
                bl[2 * ng + 1][0] = r2; bl[2 * ng + 1][1] = r3;
            }
#pragma unroll
            for (int mi = 0; mi < 2; mi++)
#pragma unroll
                for (int ni = 0; ni < 8; ni++) {
                    mma16816(acc[mi][ni], ah[mi], bh[ni]);
                    mma16816(acc[mi][ni], ah[mi], bl[ni]);
                    mma16816(acc[mi][ni], al[mi], bh[ni]);
                }
        }
        __syncthreads();
    }

    const int gq = lane >> 2, tq = lane & 3;
#pragma unroll
    for (int mi = 0; mi < 2; mi++) {
        int r0 = m0 + wm + mi * 16 + gq;
        float bv0 = bias[r0], bv1 = bias[r0 + 8];
        float* o0 = out + ((size_t)b * HH + r0) * NN;
        float* o1 = o0 + (size_t)8 * NN;
        float s0 = 0.f, q0 = 0.f, s1 = 0.f, q1 = 0.f;
#pragma unroll
        for (int ni = 0; ni < 8; ni++) {
            int cc = n0 + wn + ni * 8 + tq * 2;
            float y0 = acc[mi][ni][0] + bv0, y1 = acc[mi][ni][1] + bv0;
            float y2 = acc[mi][ni][2] + bv1, y3 = acc[mi][ni][3] + bv1;
            *(float2*)&o0[cc] = make_float2(y0, y1);
            *(float2*)&o1[cc] = make_float2(y2, y3);
            s0 += y0 + y1; q0 += y0 * y0 + y1 * y1;
            s1 += y2 + y3; q1 += y2 * y2 + y3 * y3;
        }
#pragma unroll
        for (int o = 1; o <= 2; o <<= 1) {
            s0 += __shfl_xor_sync(~0u, s0, o);
            q0 += __shfl_xor_sync(~0u, q0, o);
            s1 += __shfl_xor_sync(~0u, s1, o);
            q1 += __shfl_xor_sync(~0u, q1, o);
        }
        if (tq == 0) {
            atomicAdd(&g_sum1[r0], s0);     atomicAdd(&g_sq1[r0], q0);
            atomicAdd(&g_sum1[r0 + 8], s1); atomicAdd(&g_sq1[r0 + 8], q1);
        }
    }
}

// ---------------- stats finalize ----------------
__global__ void stats_final_kernel(const float* __restrict__ gsum,
                                   const float* __restrict__ gsq,
                                   const float* __restrict__ g,
                                   const float* __restrict__ be,
                                   float* __restrict__ scale,
                                   float* __restrict__ shift) {
    const int c = threadIdx.x;
    const float inv = 1.f / (float)(BB * NN);
    float m = gsum[c] * inv;
    float var = gsq[c] * inv - m * m;
    float sc = g[c] * rsqrtf(var + 1e-5f);
    scale[c] = sc;
    shift[c] = be[c] - m * sc;
}

__global__ void apply_bn_kernel(float* __restrict__ X) {
    const size_t total4 = (size_t)BB * HH * NN / 4;
    for (size_t i = (size_t)blockIdx.x * blockDim.x + threadIdx.x; i < total4;
         i += (size_t)gridDim.x * blockDim.x) {
        float4 v = ((float4*)X)[i];
        int c = (int)((i * 4) >> 13) & (HH - 1);
        float s = g_scale1[c], h = g_shift1[c];
        v.x = fmaxf(fmaf(v.x, s, h), 0.f);
        v.y = fmaxf(fmaf(v.y, s, h), 0.f);
        v.z = fmaxf(fmaf(v.z, s, h), 0.f);
        v.w = fmaxf(fmaf(v.w, s, h), 0.f);
        ((float4*)X)[i] = v;
    }
}

// ======================= launcher =======================
extern "C" void kernel_launch(void* const* d_in, const int* in_sizes, int n_in,
                              void* d_out, int out_size) {
    const float* xyz1    = (const float*)d_in[0];
    const float* xyz2    = (const float*)d_in[1];
    const float* points1 = (const float*)d_in[2];
    const float* points2 = (const float*)d_in[3];
    const float* w0 = (const float*)d_in[4];
    const float* b0 = (const float*)d_in[5];
    const float* g0 = (const float*)d_in[6];
    const float* be0 = (const float*)d_in[7];
    const float* w1 = (const float*)d_in[8];
    const float* b1 = (const float*)d_in[9];
    const float* g1 = (const float*)d_in[10];
    const float* be1 = (const float*)d_in[11];
    float* out = (float*)d_out;

    float *p_scale0, *p_shift0, *p_scale1, *p_shift1, *p_X0;
    float *p_sum0, *p_sq0, *p_sum1, *p_sq1;
    bf16 *p_W0hi, *p_W0lo, *p_W1hi, *p_W1lo, *p_FThi, *p_FTlo;
    cudaGetSymbolAddress((void**)&p_scale0, g_scale0);
    cudaGetSymbolAddress((void**)&p_shift0, g_shift0);
    cudaGetSymbolAddress((void**)&p_scale1, g_scale1);
    cudaGetSymbolAddress((void**)&p_shift1, g_shift1);
    cudaGetSymbolAddress((void**)&p_X0, g_X0);
    cudaGetSymbolAddress((void**)&p_sum0, g_sum0);
    cudaGetSymbolAddress((void**)&p_sq0, g_sq0);
    cudaGetSymbolAddress((void**)&p_sum1, g_sum1);
    cudaGetSymbolAddress((void**)&p_sq1, g_sq1);
    cudaGetSymbolAddress((void**)&p_W0hi, g_W0hi);
    cudaGetSymbolAddress((void**)&p_W0lo, g_W0lo);
    cudaGetSymbolAddress((void**)&p_W1hi, g_W1hi);
    cudaGetSymbolAddress((void**)&p_W1lo, g_W1lo);
    cudaGetSymbolAddress((void**)&p_FThi, g_FThi);
    cudaGetSymbolAddress((void**)&p_FTlo, g_FTlo);

    cudaFuncSetAttribute(hmma_gemm1, cudaFuncAttributeMaxDynamicSharedMemorySize, G1_SMEM);
    cudaFuncSetAttribute(hmma_gemm2, cudaFuncAttributeMaxDynamicSharedMemorySize, G2_SMEM);

    prep_kernel<<<NB_TOTAL, 256>>>(xyz1, xyz2, points1, points2, w0, w1);
    gather_kernel<<<BB * NN / 8, 256>>>();

    hmma_gemm1<<<dim3(HH / 128, NN / 128, BB), 256, G1_SMEM>>>(
        p_W0hi, p_W0lo, p_FThi, p_FTlo, b0, p_X0);
    stats_final_kernel<<<1, HH>>>(p_sum0, p_sq0, g0, be0, p_scale0, p_shift0);

    hmma_gemm2<<<dim3(HH / 128, NN / 128, BB), 256, G2_SMEM>>>(
        p_W1hi, p_W1lo, p_X0, p_scale0, p_shift0, b1, out);
    stats_final_kernel<<<1, HH>>>(p_sum1, p_sq1, g1, be1, p_scale1, p_shift1);
    apply_bn_kernel<<<4096, 256>>>(out);
}

// round 7
// speedup vs baseline: 1.0219x; 1.0219x over previous
#include <cuda_runtime.h>
#include <cuda_bf16.h>
#include <cstdint>

// Problem constants
#define BB 8
#define NN 8192
#define SS 2048
#define D1 256
#define D2 512
#define CIN 768
#define HH 512

typedef __nv_bfloat16 bf16;

// ---------------- scratch (static device globals; no runtime alloc) ----------------
__device__ float g_P2T[(size_t)BB * SS * D2];
__device__ int   g_idx[(size_t)BB * NN * 3];
__device__ float g_wgt[(size_t)BB * NN * 3];
__device__ bf16 g_FThi[(size_t)BB * NN * CIN];
__device__ bf16 g_FTlo[(size_t)BB * NN * CIN];
__device__ bf16 g_W0hi[HH * CIN], g_W0lo[HH * CIN];
__device__ bf16 g_W1hi[HH * HH],  g_W1lo[HH * HH];
__device__ float g_X0[(size_t)BB * HH * NN];           // (b, c, n)
__device__ float g_sum0[HH], g_sq0[HH], g_sum1[HH], g_sq1[HH];
__device__ float g_scale0[HH], g_shift0[HH], g_scale1[HH], g_shift1[HH];

// ======================= low-level helpers =======================
__device__ __forceinline__ uint32_t smem_u32(const void* p) {
    uint32_t a;
    asm("{ .reg .u64 t; cvta.to.shared.u64 t, %1; cvt.u32.u64 %0, t; }" : "=r"(a) : "l"(p));
    return a;
}
__device__ __forceinline__ void ldsm4(uint32_t& r0, uint32_t& r1, uint32_t& r2,
                                      uint32_t& r3, uint32_t a) {
    asm volatile("ldmatrix.sync.aligned.m8n8.x4.shared.b16 {%0,%1,%2,%3},[%4];"
                 : "=r"(r0), "=r"(r1), "=r"(r2), "=r"(r3) : "r"(a));
}
__device__ __forceinline__ void ldsm4t(uint32_t& r0, uint32_t& r1, uint32_t& r2,
                                       uint32_t& r3, uint32_t a) {
    asm volatile("ldmatrix.sync.aligned.m8n8.x4.trans.shared.b16 {%0,%1,%2,%3},[%4];"
                 : "=r"(r0), "=r"(r1), "=r"(r2), "=r"(r3) : "r"(a));
}
__device__ __forceinline__ void mma16816(float* d, const uint32_t* a, const uint32_t* b) {
    asm volatile(
        "mma.sync.aligned.m16n8k16.row.col.f32.bf16.bf16.f32 "
        "{%0,%1,%2,%3},{%4,%5,%6,%7},{%8,%9},{%0,%1,%2,%3};"
        : "+f"(d[0]), "+f"(d[1]), "+f"(d[2]), "+f"(d[3])
        : "r"(a[0]), "r"(a[1]), "r"(a[2]), "r"(a[3]), "r"(b[0]), "r"(b[1]));
}
__device__ __forceinline__ void cpa16(uint32_t dst, const void* src) {
    asm volatile("cp.async.cg.shared.global [%0],[%1],16;" :: "r"(dst), "l"(src));
}
#define CP_COMMIT() asm volatile("cp.async.commit_group;" ::: "memory")
#define CP_WAIT(n) asm volatile("cp.async.wait_group %0;" :: "n"(n) : "memory")

__device__ __forceinline__ void split_bf(float v, bf16& h, bf16& l) {
    h = __float2bfloat16_rn(v);
    l = __float2bfloat16_rn(v - __bfloat162float(h));
}
__device__ __forceinline__ uint32_t pack2(bf16 a, bf16 b) {
    __nv_bfloat162 t = __halves2bfloat162(a, b);
    return *reinterpret_cast<uint32_t*>(&t);
}

// ---------------- top-3 helper ----------------
struct Top3 { float d0, d1, d2; int i0, i1, i2; };
__device__ __forceinline__ void t3_ins(Top3& q, float t, int s) {
    if (t < q.d2) {
        if (t < q.d1) {
            q.d2 = q.d1; q.i2 = q.i1;
            if (t < q.d0) { q.d1 = q.d0; q.i1 = q.i0; q.d0 = t; q.i0 = s; }
            else          { q.d1 = t;    q.i1 = s; }
        } else { q.d2 = t; q.i2 = s; }
    }
}

// ======================= fused prep kernel =======================
// block order: top3 FIRST (long-running), then transposes / converts / zeroing
#define NB_T3 128
#define NB_P2 8192
#define NB_P1 16384
#define NB_C0 (HH * CIN / 1024)
#define NB_C1 (HH * HH / 1024)
#define NB_TOTAL (NB_T3 + NB_P2 + NB_P1 + NB_C0 + NB_C1 + 1)

__global__ __launch_bounds__(256)
void prep_kernel(const float* __restrict__ xyz1, const float* __restrict__ xyz2,
                 const float* __restrict__ p1, const float* __restrict__ p2,
                 const float* __restrict__ w0g, const float* __restrict__ w1g) {
    __shared__ float sh[8192];
    int r = blockIdx.x;
    const int tid = threadIdx.x;

    if (r < NB_T3) {
        // ---- top-3 nearest neighbors ----
        float* sx = sh;
        float* sy = sh + 2048;
        float* sz = sh + 4096;
        float* sn = sh + 6144;
        const int b = r >> 4;
        const int nbase = (r & 15) * 512;

        for (int i = tid; i < SS; i += 256) {
            float x = xyz2[((size_t)b * 3 + 0) * SS + i];
            float y = xyz2[((size_t)b * 3 + 1) * SS + i];
            float z = xyz2[((size_t)b * 3 + 2) * SS + i];
            sx[i] = x; sy[i] = y; sz[i] = z;
            sn[i] = x * x + y * y + z * z;
        }
        __syncthreads();

        const int na = nbase + tid;
        const int nb = nbase + 256 + tid;
        float xa = xyz1[((size_t)b * 3 + 0) * NN + na];
        float ya = xyz1[((size_t)b * 3 + 1) * NN + na];
        float za = xyz1[((size_t)b * 3 + 2) * NN + na];
        float xb = xyz1[((size_t)b * 3 + 0) * NN + nb];
        float yb = xyz1[((size_t)b * 3 + 1) * NN + nb];
        float zb = xyz1[((size_t)b * 3 + 2) * NN + nb];
        float n1a = xa * xa + ya * ya + za * za;
        float n1b = xb * xb + yb * yb + zb * zb;
        float mxa = -2.f * xa, mya = -2.f * ya, mza = -2.f * za;
        float mxb = -2.f * xb, myb = -2.f * yb, mzb = -2.f * zb;

        Top3 qa = {3.4e38f, 3.4e38f, 3.4e38f, 0, 0, 0};
        Top3 qb = {3.4e38f, 3.4e38f, 3.4e38f, 0, 0, 0};

        for (int s = 0; s < SS; s += 4) {
            float4 vx = ((float4*)sx)[s >> 2], vy = ((float4*)sy)[s >> 2];
            float4 vz = ((float4*)sz)[s >> 2], vn = ((float4*)sn)[s >> 2];
            float t;
            t = fmaf(mxa, vx.x, vn.x); t = fmaf(mya, vy.x, t); t = fmaf(mza, vz.x, t); t3_ins(qa, t, s + 0);
            t = fmaf(mxa, vx.y, vn.y); t = fmaf(mya, vy.y, t); t = fmaf(mza, vz.y, t); t3_ins(qa, t, s + 1);
            t = fmaf(mxa, vx.z, vn.z); t = fmaf(mya, vy.z, t); t = fmaf(mza, vz.z, t); t3_ins(qa, t, s + 2);
            t = fmaf(mxa, vx.w, vn.w); t = fmaf(mya, vy.w, t); t = fmaf(mza, vz.w, t); t3_ins(qa, t, s + 3);
            t = fmaf(mxb, vx.x, vn.x); t = fmaf(myb, vy.x, t); t = fmaf(mzb, vz.x, t); t3_ins(qb, t, s + 0);
            t = fmaf(mxb, vx.y, vn.y); t = fmaf(myb, vy.y, t); t = fmaf(mzb, vz.y, t); t3_ins(qb, t, s + 1);
            t = fmaf(mxb, vx.z, vn.z); t = fmaf(myb, vy.z, t); t = fmaf(mzb, vz.z, t); t3_ins(qb, t, s + 2);
            t = fmaf(mxb, vx.w, vn.w); t = fmaf(myb, vy.w, t); t = fmaf(mzb, vz.w, t); t3_ins(qb, t, s + 3);
        }

        {
            size_t base = ((size_t)b * NN + na) * 3;
            float d0 = qa.d0 + n1a, d1 = qa.d1 + n1a, d2 = qa.d2 + n1a;
            float w0 = 1.0f / (d0 + 1e-8f), w1 = 1.0f / (d1 + 1e-8f), w2 = 1.0f / (d2 + 1e-8f);
            float inv = 1.0f / (w0 + w1 + w2);
            g_idx[base + 0] = qa.i0; g_idx[base + 1] = qa.i1; g_idx[base + 2] = qa.i2;
            g_wgt[base + 0] = w0 * inv; g_wgt[base + 1] = w1 * inv; g_wgt[base + 2] = w2 * inv;
        }
        {
            size_t base = ((size_t)b * NN + nb) * 3;
            float d0 = qb.d0 + n1b, d1 = qb.d1 + n1b, d2 = qb.d2 + n1b;
            float w0 = 1.0f / (d0 + 1e-8f), w1 = 1.0f / (d1 + 1e-8f), w2 = 1.0f / (d2 + 1e-8f);
            float inv = 1.0f / (w0 + w1 + w2);
            g_idx[base + 0] = qb.i0; g_idx[base + 1] = qb.i1; g_idx[base + 2] = qb.i2;
            g_wgt[base + 0] = w0 * inv; g_wgt[base + 1] = w1 * inv; g_wgt[base + 2] = w2 * inv;
        }
        return;
    }
    r -= NB_T3;
    if (r < NB_P2) {
        // ---- transpose points2 (B,512,2048) -> P2T (B,2048,512) ----
        int b = r >> 10, y = (r >> 6) & 15, x = r & 63;
        int c0 = y * 32, s0 = x * 32;
        int tx = tid & 31, ty = tid >> 5;
        float (*t)[33] = (float(*)[33])sh;
#pragma unroll
        for (int j = ty; j < 32; j += 8)
            t[j][tx] = p2[((size_t)b * D2 + c0 + j) * SS + s0 + tx];
        __syncthreads();
#pragma unroll
        for (int j = ty; j < 32; j += 8)
            g_P2T[((size_t)b * SS + s0 + j) * D2 + c0 + tx] = t[tx][j];
        return;
    }
    r -= NB_P2;
    if (r < NB_P1) {
        // ---- transpose points1 (B,256,8192) -> FThi/FTlo[:, :, 0:256] ----
        int b = r >> 11, y = (r >> 8) & 7, x = r & 255;
        int c0 = y * 32, n0 = x * 32;
        int tx = tid & 31, ty = tid >> 5;
        float (*t)[33] = (float(*)[33])sh;
#pragma unroll
        for (int j = ty; j < 32; j += 8)
            t[j][tx] = p1[((size_t)b * D1 + c0 + j) * NN + n0 + tx];
        __syncthreads();
#pragma unroll
        for (int j = ty; j < 32; j += 8) {
            bf16 h, l;
            split_bf(t[tx][j], h, l);
            size_t off = ((size_t)b * NN + n0 + j) * CIN + c0 + tx;
            g_FThi[off] = h;
            g_FTlo[off] = l;
        }
        return;
    }
    r -= NB_P1;
    if (r < NB_C0 + NB_C1) {
        // ---- weight split to bf16 hi/lo (vectorized x4) ----
        const float* src;
        bf16 *hi, *lo;
        int i;
        if (r < NB_C0) { src = w0g; hi = g_W0hi; lo = g_W0lo; i = r * 1024 + tid * 4; }
        else { src = w1g; hi = g_W1hi; lo = g_W1lo; i = (r - NB_C0) * 1024 + tid * 4; }
        float4 v = *(const float4*)(src + i);
        bf16 h0, l0, h1, l1, h2, l2, h3, l3;
        split_bf(v.x, h0, l0); split_bf(v.y, h1, l1);
        split_bf(v.z, h2, l2); split_bf(v.w, h3, l3);
        *(uint2*)&hi[i] = make_uint2(pack2(h0, h1), pack2(h2, h3));
        *(uint2*)&lo[i] = make_uint2(pack2(l0, l1), pack2(l2, l3));
        return;
    }
    // ---- zero stats accumulators ----
    if (tid < 256) {
        g_sum0[tid] = 0.f; g_sum0[tid + 256] = 0.f;
        g_sq0[tid] = 0.f;  g_sq0[tid + 256] = 0.f;
        g_sum1[tid] = 0.f; g_sum1[tid + 256] = 0.f;
        g_sq1[tid] = 0.f;  g_sq1[tid + 256] = 0.f;
    }
}

// ---------------- gather + interpolate -> FThi/FTlo[:, :, 256:768] ----------------
__global__ void gather_kernel() {
    int wglob = blockIdx.x * 8 + (threadIdx.x >> 5);
    int lane = threadIdx.x & 31;
    int b = wglob / NN;
    size_t base = (size_t)wglob * 3;
    int i0 = g_idx[base + 0], i1 = g_idx[base + 1], i2 = g_idx[base + 2];
    float w0 = g_wgt[base + 0], w1 = g_wgt[base + 1], w2 = g_wgt[base + 2];
    const float* r0 = g_P2T + ((size_t)b * SS + i0) * D2;
    const float* r1 = g_P2T + ((size_t)b * SS + i1) * D2;
    const float* r2 = g_P2T + ((size_t)b * SS + i2) * D2;
    size_t dbase = (size_t)wglob * CIN + D1;
#pragma unroll
    for (int c = lane * 4; c < D2; c += 128) {
        float4 v0 = *(const float4*)&r0[c];
        float4 v1 = *(const float4*)&r1[c];
        float4 v2 = *(const float4*)&r2[c];
        float o0 = w0 * v0.x + w1 * v1.x + w2 * v2.x;
        float o1 = w0 * v0.y + w1 * v1.y + w2 * v2.y;
        float o2 = w0 * v0.z + w1 * v1.z + w2 * v2.z;
        float o3 = w0 * v0.w + w1 * v1.w + w2 * v2.w;
        bf16 h0, l0, h1, l1, h2, l2, h3, l3;
        split_bf(o0, h0, l0); split_bf(o1, h1, l1);
        split_bf(o2, h2, l2); split_bf(o3, h3, l3);
        *(uint2*)&g_FThi[dbase + c] = make_uint2(pack2(h0, h1), pack2(h2, h3));
        *(uint2*)&g_FTlo[dbase + c] = make_uint2(pack2(l0, l1), pack2(l2, l3));
    }
}

// ======================= HMMA GEMM 1 (K-chunk 16, ring-4, 1 sync/stage) =======================
#define TK1 6144                           // tile bytes: 128 rows x 48B (16 bf16 + 8 pad)
#define STG1 (4 * TK1)                     // stage: Ahi,Alo,Bhi,Blo = 24576
static constexpr int G1_SMEM = 4 * STG1;   // 98304 -> 2 CTAs/SM

__global__ __launch_bounds__(256)
void hmma_gemm1(const bf16* __restrict__ Ahi, const bf16* __restrict__ Alo,
                const bf16* __restrict__ Bhi_g, const bf16* __restrict__ Blo_g,
                const float* __restrict__ bias, float* __restrict__ out) {
    extern __shared__ char smem[];
    const uint32_t sb = smem_u32(smem);
    const int tid = threadIdx.x, lane = tid & 31, wid = tid >> 5;
    const int m0 = blockIdx.x * 128, n0 = blockIdx.y * 128, b = blockIdx.z;
    const int wm = (wid & 3) * 32, wn = (wid >> 2) * 64;

    const bf16* Arow_hi = Ahi + (size_t)m0 * CIN;
    const bf16* Arow_lo = Alo + (size_t)m0 * CIN;
    const bf16* Brow_hi = Bhi_g + ((size_t)b * NN + n0) * CIN;
    const bf16* Brow_lo = Blo_g + ((size_t)b * NN + n0) * CIN;

    float acc[2][8][4];
#pragma unroll
    for (int i = 0; i < 2; i++)
#pragma unroll
        for (int j = 0; j < 8; j++)
#pragma unroll
            for (int q = 0; q < 4; q++) acc[i][j][q] = 0.f;

    const int row_l = tid >> 1, cseg = tid & 1;
    auto issue = [&](int kc) {                    // one 16-wide K chunk, one commit group
        const int kb = kc * 16 + cseg * 8;
        const uint32_t d = sb + (kc & 3) * STG1 + row_l * 48 + cseg * 16;
        cpa16(d,           Arow_hi + (size_t)row_l * CIN + kb);
        cpa16(d + TK1,     Arow_lo + (size_t)row_l * CIN + kb);
        cpa16(d + 2 * TK1, Brow_hi + (size_t)row_l * CIN + kb);
        cpa16(d + 3 * TK1, Brow_lo + (size_t)row_l * CIN + kb);
        CP_COMMIT();
    };

    const int KT = CIN / 16;   // 48
    issue(0); issue(1); issue(2);

    for (int c = 0; c < KT; c++) {
        if (c + 2 < KT)      CP_WAIT(2);
        else if (c + 1 < KT) CP_WAIT(1);
        else                 CP_WAIT(0);
        __syncthreads();
        if (c + 3 < KT) issue(c + 3);   // writes buffer (c+3)&3 == (c-1)&3: freed by the sync

        const uint32_t sA = sb + (c & 3) * STG1;
        const uint32_t sB = sA + 2 * TK1;
        uint32_t ah[2][4], al[2][4];
#pragma unroll
        for (int mi = 0; mi < 2; mi++) {
            uint32_t ad = sA + (wm + mi * 16 + (lane & 15)) * 48 + ((lane >> 4) << 4);
            ldsm4(ah[mi][0], ah[mi][1], ah[mi][2], ah[mi][3], ad);
            ldsm4(al[mi][0], al[mi][1], al[mi][2], al[mi][3], ad + TK1);
        }
        uint32_t bh[8][2], bl[8][2];
#pragma unroll
        for (int ng = 0; ng < 4; ng++) {
            uint32_t row = wn + ng * 16 + (lane & 7) + ((lane & 16) >> 1);
            uint32_t ad = sB + row * 48 + ((lane & 8) << 1);
            uint32_t r0, r1, r2, r3;
            ldsm4(r0, r1, r2, r3, ad);
            bh[2 * ng][0] = r0; bh[2 * ng][1] = r1;
            bh[2 * ng + 1][0] = r2; bh[2 * ng + 1][1] = r3;
            ldsm4(r0, r1, r2, r3, ad + TK1);
            bl[2 * ng][0] = r0; bl[2 * ng][1] = r1;
            bl[2 * ng + 1][0] = r2; bl[2 * ng + 1][1] = r3;
        }
#pragma unroll
        for (int mi = 0; mi < 2; mi++)
#pragma unroll
            for (int ni = 0; ni < 8; ni++) {
                mma16816(acc[mi][ni], ah[mi], bh[ni]);
                mma16816(acc[mi][ni], ah[mi], bl[ni]);
                mma16816(acc[mi][ni], al[mi], bh[ni]);
            }
    }

    // epilogue -> out (b, m, n) + bias, fused channel stats via atomics
    const int gq = lane >> 2, tq = lane & 3;
#pragma unroll
    for (int mi = 0; mi < 2; mi++) {
        int r0 = m0 + wm + mi * 16 + gq;
        float bv0 = bias[r0], bv1 = bias[r0 + 8];
        float* o0 = out + ((size_t)b * HH + r0) * NN;
        float* o1 = o0 + (size_t)8 * NN;
        float s0 = 0.f, q0 = 0.f, s1 = 0.f, q1 = 0.f;
#pragma unroll
        for (int ni = 0; ni < 8; ni++) {
            int cc = n0 + wn + ni * 8 + tq * 2;
            float y0 = acc[mi][ni][0] + bv0, y1 = acc[mi][ni][1] + bv0;
            float y2 = acc[mi][ni][2] + bv1, y3 = acc[mi][ni][3] + bv1;
            *(float2*)&o0[cc] = make_float2(y0, y1);
            *(float2*)&o1[cc] = make_float2(y2, y3);
            s0 += y0 + y1; q0 += y0 * y0 + y1 * y1;
            s1 += y2 + y3; q1 += y2 * y2 + y3 * y3;
        }
#pragma unroll
        for (int o = 1; o <= 2; o <<= 1) {
            s0 += __shfl_xor_sync(~0u, s0, o);
            q0 += __shfl_xor_sync(~0u, q0, o);
            s1 += __shfl_xor_sync(~0u, s1, o);
            q1 += __shfl_xor_sync(~0u, q1, o);
        }
        if (tq == 0) {
            atomicAdd(&g_sum0[r0], s0);     atomicAdd(&g_sq0[r0], q0);
            atomicAdd(&g_sum0[r0 + 8], s1); atomicAdd(&g_sq0[r0 + 8], q1);
        }
    }
}

// ======================= HMMA GEMM 2 (fused BN+ReLU on B, fused stats) =======================
#define AT2 10240
#define AST2 (2 * AT2)
#define BT2 8704                 // 32 * 272
#define BST2 (2 * BT2)
static constexpr int G2_SMEM = 2 * AST2 + 2 * BST2;  // 75776

__global__ __launch_bounds__(256)
void hmma_gemm2(const bf16* __restrict__ Ahi, const bf16* __restrict__ Alo,
                const float* __restrict__ X0,
                const float* __restrict__ scale, const float* __restrict__ shift,
                const float* __restrict__ bias, float* __restrict__ out) {
    extern __shared__ char smem[];
    const uint32_t sb = smem_u32(smem);
    const int tid = threadIdx.x, lane = tid & 31, wid = tid >> 5;
    const int m0 = blockIdx.x * 128, n0 = blockIdx.y * 128, b = blockIdx.z;
    const int wm = (wid & 3) * 32, wn = (wid >> 2) * 64;

    const bf16* Arow_hi = Ahi + (size_t)m0 * HH;
    const bf16* Arow_lo = Alo + (size_t)m0 * HH;
    const float* Xb = X0 + (size_t)b * HH * NN + n0;

    float acc[2][8][4];
#pragma unroll
    for (int i = 0; i < 2; i++)
#pragma unroll
        for (int j = 0; j < 8; j++)
#pragma unroll
            for (int q = 0; q < 4; q++) acc[i][j][q] = 0.f;

    const int brow = tid >> 3, bcol = (tid & 7) * 16;
    float x[16];
    float scl, shf;

    const int row_l = tid >> 2, c16 = (tid & 3);
    {
#pragma unroll
        for (int t = 0; t < 2; t++) {
            int row = row_l + t * 64;
            uint32_t d = sb + row * 80 + c16 * 16;
            cpa16(d,       Arow_hi + (size_t)row * HH + c16 * 8);
            cpa16(d + AT2, Arow_lo + (size_t)row * HH + c16 * 8);
        }
        CP_COMMIT();
        const float* src = Xb + (size_t)brow * NN + bcol;
#pragma unroll
        for (int j = 0; j < 4; j++) {
            float4 v = *(const float4*)(src + j * 4);
            x[4 * j] = v.x; x[4 * j + 1] = v.y; x[4 * j + 2] = v.z; x[4 * j + 3] = v.w;
        }
        scl = scale[brow];
        shf = shift[brow];
    }

    const uint32_t sBbase = sb + 2 * AST2;
    const int KT = HH / 32;  // 16
    for (int c = 0; c < KT; c++) {
        const int buf = c & 1;
        {
            uint32_t doff = (buf * BST2 + brow * 272 + bcol * 2) + 2 * AST2;
#pragma unroll
            for (int j = 0; j < 4; j++) {
                float y0 = fmaxf(fmaf(x[4 * j + 0], scl, shf), 0.f);
                float y1 = fmaxf(fmaf(x[4 * j + 1], scl, shf), 0.f);
                float y2 = fmaxf(fmaf(x[4 * j + 2], scl, shf), 0.f);
                float y3 = fmaxf(fmaf(x[4 * j + 3], scl, shf), 0.f);
                bf16 h0, l0, h1, l1, h2, l2, h3, l3;
                split_bf(y0, h0, l0); split_bf(y1, h1, l1);
                split_bf(y2, h2, l2); split_bf(y3, h3, l3);
                *(uint2*)(smem + doff + j * 8) = make_uint2(pack2(h0, h1), pack2(h2, h3));
                *(uint2*)(smem + doff + BT2 + j * 8) = make_uint2(pack2(l0, l1), pack2(l2, l3));
            }
        }
        if (c + 1 < KT) {
            const int kb = (c + 1) * 32;
            const uint32_t s2 = sb + (buf ^ 1) * AST2;
#pragma unroll
            for (int t = 0; t < 2; t++) {
                int row = row_l + t * 64;
                uint32_t d = s2 + row * 80 + c16 * 16;
                cpa16(d,       Arow_hi + (size_t)row * HH + kb + c16 * 8);
                cpa16(d + AT2, Arow_lo + (size_t)row * HH + kb + c16 * 8);
            }
            CP_COMMIT();
            const float* src = Xb + (size_t)(kb + brow) * NN + bcol;
#pragma unroll
            for (int j = 0; j < 4; j++) {
                float4 v = *(const float4*)(src + j * 4);
                x[4 * j] = v.x; x[4 * j + 1] = v.y; x[4 * j + 2] = v.z; x[4 * j + 3] = v.w;
            }
            scl = scale[kb + brow];
            shf = shift[kb + brow];
            CP_WAIT(1);
        } else {
            CP_WAIT(0);
        }
        __syncthreads();

        const uint32_t sA = sb + buf * AST2;
        const uint32_t sB = sBbase + buf * BST2;
#pragma unroll
        for (int ks = 0; ks < 2; ks++) {
            const int k16 = ks * 16;
            uint32_t ah[2][4], al[2][4];
#pragma unroll
            for (int mi = 0; mi < 2; mi++) {
                uint32_t ad = sA + (wm + mi * 16 + (lane & 15)) * 80
                                 + (k16 + ((lane >> 4) << 3)) * 2;
                ldsm4(ah[mi][0], ah[mi][1], ah[mi][2], ah[mi][3], ad);
                ldsm4(al[mi][0], al[mi][1], al[mi][2], al[mi][3], ad + AT2);
            }
            uint32_t bh[8][2], bl[8][2];
#pragma unroll
            for (int ng = 0; ng < 4; ng++) {
                uint32_t row = k16 + (lane & 7) + (lane & 8);
                uint32_t col = wn + ng * 16 + ((lane >> 4) << 3);
                uint32_t ad = sB + row * 272 + col * 2;
                uint32_t r0, r1, r2, r3;
                ldsm4t(r0, r1, r2, r3, ad);
                bh[2 * ng][0] = r0; bh[2 * ng][1] = r1;
                bh[2 * ng + 1][0] = r2; bh[2 * ng + 1][1] = r3;
                ldsm4t(r0, r1, r2, r3, ad + BT2);
                bl[2 * ng][0] = r0; bl[2 * ng][1] = r1;
                bl[2 * ng + 1][0] = r2; bl[2 * ng + 1][1] = r3;
            }
#pragma unroll
            for (int mi = 0; mi < 2; mi++)
#pragma unroll
                for (int ni = 0; ni < 8; ni++) {
                    mma16816(acc[mi][ni], ah[mi], bh[ni]);
                    mma16816(acc[mi][ni], ah[mi], bl[ni]);
                    mma16816(acc[mi][ni], al[mi], bh[ni]);
                }
        }
        __syncthreads();
    }

    const int gq = lane >> 2, tq = lane & 3;
#pragma unroll
    for (int mi = 0; mi < 2; mi++) {
        int r0 = m0 + wm + mi * 16 + gq;
        float bv0 = bias[r0], bv1 = bias[r0 + 8];
        float* o0 = out + ((size_t)b * HH + r0) * NN;
        float* o1 = o0 + (size_t)8 * NN;
        float s0 = 0.f, q0 = 0.f, s1 = 0.f, q1 = 0.f;
#pragma unroll
        for (int ni = 0; ni < 8; ni++) {
            int cc = n0 + wn + ni * 8 + tq * 2;
            float y0 = acc[mi][ni][0] + bv0, y1 = acc[mi][ni][1] + bv0;
            float y2 = acc[mi][ni][2] + bv1, y3 = acc[mi][ni][3] + bv1;
            *(float2*)&o0[cc] = make_float2(y0, y1);
            *(float2*)&o1[cc] = make_float2(y2, y3);
            s0 += y0 + y1; q0 += y0 * y0 + y1 * y1;
            s1 += y2 + y3; q1 += y2 * y2 + y3 * y3;
        }
#pragma unroll
        for (int o = 1; o <= 2; o <<= 1) {
            s0 += __shfl_xor_sync(~0u, s0, o);
            q0 += __shfl_xor_sync(~0u, q0, o);
            s1 += __shfl_xor_sync(~0u, s1, o);
            q1 += __shfl_xor_sync(~0u, q1, o);
        }
        if (tq == 0) {
            atomicAdd(&g_sum1[r0], s0);     atomicAdd(&g_sq1[r0], q0);
            atomicAdd(&g_sum1[r0 + 8], s1); atomicAdd(&g_sq1[r0 + 8], q1);
        }
    }
}

// ---------------- stats finalize ----------------
__global__ void stats_final_kernel(const float* __restrict__ gsum,
                                   const float* __restrict__ gsq,
                                   const float* __restrict__ g,
                                   const float* __restrict__ be,
                                   float* __restrict__ scale,
                                   float* __restrict__ shift) {
    const int c = threadIdx.x;
    const float inv = 1.f / (float)(BB * NN);
    float m = gsum[c] * inv;
    float var = gsq[c] * inv - m * m;
    float sc = g[c] * rsqrtf(var + 1e-5f);
    scale[c] = sc;
    shift[c] = be[c] - m * sc;
}

__global__ void apply_bn_kernel(float* __restrict__ X) {
    const size_t total4 = (size_t)BB * HH * NN / 4;
    for (size_t i = (size_t)blockIdx.x * blockDim.x + threadIdx.x; i < total4;
         i += (size_t)gridDim.x * blockDim.x) {
        float4 v = ((float4*)X)[i];
        int c = (int)((i * 4) >> 13) & (HH - 1);
        float s = g_scale1[c], h = g_shift1[c];
        v.x = fmaxf(fmaf(v.x, s, h), 0.f);
        v.y = fmaxf(fmaf(v.y, s, h), 0.f);
        v.z = fmaxf(fmaf(v.z, s, h), 0.f);
        v.w = fmaxf(fmaf(v.w, s, h), 0.f);
        ((float4*)X)[i] = v;
    }
}

// ======================= launcher =======================
extern "C" void kernel_launch(void* const* d_in, const int* in_sizes, int n_in,
                              void* d_out, int out_size) {
    const float* xyz1    = (const float*)d_in[0];
    const float* xyz2    = (const float*)d_in[1];
    const float* points1 = (const float*)d_in[2];
    const float* points2 = (const float*)d_in[3];
    const float* w0 = (const float*)d_in[4];
    const float* b0 = (const float*)d_in[5];
    const float* g0 = (const float*)d_in[6];
    const float* be0 = (const float*)d_in[7];
    const float* w1 = (const float*)d_in[8];
    const float* b1 = (const float*)d_in[9];
    const float* g1 = (const float*)d_in[10];
    const float* be1 = (const float*)d_in[11];
    float* out = (float*)d_out;

    float *p_scale0, *p_shift0, *p_scale1, *p_shift1, *p_X0;
    float *p_sum0, *p_sq0, *p_sum1, *p_sq1;
    bf16 *p_W0hi, *p_W0lo, *p_W1hi, *p_W1lo, *p_FThi, *p_FTlo;
    cudaGetSymbolAddress((void**)&p_scale0, g_scale0);
    cudaGetSymbolAddress((void**)&p_shift0, g_shift0);
    cudaGetSymbolAddress((void**)&p_scale1, g_scale1);
    cudaGetSymbolAddress((void**)&p_shift1, g_shift1);
    cudaGetSymbolAddress((void**)&p_X0, g_X0);
    cudaGetSymbolAddress((void**)&p_sum0, g_sum0);
    cudaGetSymbolAddress((void**)&p_sq0, g_sq0);
    cudaGetSymbolAddress((void**)&p_sum1, g_sum1);
    cudaGetSymbolAddress((void**)&p_sq1, g_sq1);
    cudaGetSymbolAddress((void**)&p_W0hi, g_W0hi);
    cudaGetSymbolAddress((void**)&p_W0lo, g_W0lo);
    cudaGetSymbolAddress((void**)&p_W1hi, g_W1hi);
    cudaGetSymbolAddress((void**)&p_W1lo, g_W1lo);
    cudaGetSymbolAddress((void**)&p_FThi, g_FThi);
    cudaGetSymbolAddress((void**)&p_FTlo, g_FTlo);

    cudaFuncSetAttribute(hmma_gemm1, cudaFuncAttributeMaxDynamicSharedMemorySize, G1_SMEM);
    cudaFuncSetAttribute(hmma_gemm2, cudaFuncAttributeMaxDynamicSharedMemorySize, G2_SMEM);

    prep_kernel<<<NB_TOTAL, 256>>>(xyz1, xyz2, points1, points2, w0, w1);
    gather_kernel<<<BB * NN / 8, 256>>>();

    hmma_gemm1<<<dim3(HH / 128, NN / 128, BB), 256, G1_SMEM>>>(
        p_W0hi, p_W0lo, p_FThi, p_FTlo, b0, p_X0);
    stats_final_kernel<<<1, HH>>>(p_sum0, p_sq0, g0, be0, p_scale0, p_shift0);

    hmma_gemm2<<<dim3(HH / 128, NN / 128, BB), 256, G2_SMEM>>>(
        p_W1hi, p_W1lo, p_X0, p_scale0, p_shift0, b1, out);
    stats_final_kernel<<<1, HH>>>(p_sum1, p_sq1, g1, be1, p_scale1, p_shift1);
    apply_bn_kernel<<<4096, 256>>>(out);
}

// round 8
// speedup vs baseline: 1.0242x; 1.0022x over previous
#include <cuda_runtime.h>
#include <cuda_bf16.h>
#include <cstdint>

// Problem constants
#define BB 8
#define NN 8192
#define SS 2048
#define D1 256
#define D2 512
#define CIN 768
#define HH 512

typedef __nv_bfloat16 bf16;

// ---------------- scratch (static device globals; no runtime alloc) ----------------
__device__ float g_P2T[(size_t)BB * SS * D2];
__device__ int   g_idx[(size_t)BB * NN * 3];
__device__ float g_wgt[(size_t)BB * NN * 3];
__device__ bf16 g_FThi[(size_t)BB * NN * CIN];
__device__ bf16 g_FTlo[(size_t)BB * NN * CIN];
__device__ bf16 g_W0hi[HH * CIN], g_W0lo[HH * CIN];
__device__ bf16 g_W1hi[HH * HH],  g_W1lo[HH * HH];
__device__ float g_X0[(size_t)BB * HH * NN];           // (b, c, n)
__device__ float g_sum0[HH], g_sq0[HH], g_sum1[HH], g_sq1[HH];
__device__ float g_scale0[HH], g_shift0[HH], g_scale1[HH], g_shift1[HH];

// ======================= low-level helpers =======================
__device__ __forceinline__ uint32_t smem_u32(const void* p) {
    uint32_t a;
    asm("{ .reg .u64 t; cvta.to.shared.u64 t, %1; cvt.u32.u64 %0, t; }" : "=r"(a) : "l"(p));
    return a;
}
__device__ __forceinline__ void ldsm4(uint32_t& r0, uint32_t& r1, uint32_t& r2,
                                      uint32_t& r3, uint32_t a) {
    asm volatile("ldmatrix.sync.aligned.m8n8.x4.shared.b16 {%0,%1,%2,%3},[%4];"
                 : "=r"(r0), "=r"(r1), "=r"(r2), "=r"(r3) : "r"(a));
}
__device__ __forceinline__ void ldsm4t(uint32_t& r0, uint32_t& r1, uint32_t& r2,
                                       uint32_t& r3, uint32_t a) {
    asm volatile("ldmatrix.sync.aligned.m8n8.x4.trans.shared.b16 {%0,%1,%2,%3},[%4];"
                 : "=r"(r0), "=r"(r1), "=r"(r2), "=r"(r3) : "r"(a));
}
__device__ __forceinline__ void mma16816(float* d, const uint32_t* a, const uint32_t* b) {
    asm volatile(
        "mma.sync.aligned.m16n8k16.row.col.f32.bf16.bf16.f32 "
        "{%0,%1,%2,%3},{%4,%5,%6,%7},{%8,%9},{%0,%1,%2,%3};"
        : "+f"(d[0]), "+f"(d[1]), "+f"(d[2]), "+f"(d[3])
        : "r"(a[0]), "r"(a[1]), "r"(a[2]), "r"(a[3]), "r"(b[0]), "r"(b[1]));
}
__device__ __forceinline__ void cpa16(uint32_t dst, const void* src) {
    asm volatile("cp.async.cg.shared.global [%0],[%1],16;" :: "r"(dst), "l"(src));
}
#define CP_COMMIT() asm volatile("cp.async.commit_group;" ::: "memory")
#define CP_WAIT(n) asm volatile("cp.async.wait_group %0;" :: "n"(n) : "memory")

__device__ __forceinline__ void split_bf(float v, bf16& h, bf16& l) {
    h = __float2bfloat16_rn(v);
    l = __float2bfloat16_rn(v - __bfloat162float(h));
}
__device__ __forceinline__ uint32_t pack2(bf16 a, bf16 b) {
    __nv_bfloat162 t = __halves2bfloat162(a, b);
    return *reinterpret_cast<uint32_t*>(&t);
}

// ---------------- top-3 helper ----------------
struct Top3 { float d0, d1, d2; int i0, i1, i2; };
__device__ __forceinline__ void t3_ins(Top3& q, float t, int s) {
    if (t < q.d2) {
        if (t < q.d1) {
            q.d2 = q.d1; q.i2 = q.i1;
            if (t < q.d0) { q.d1 = q.d0; q.i1 = q.i0; q.d0 = t; q.i0 = s; }
            else          { q.d1 = t;    q.i1 = s; }
        } else { q.d2 = t; q.i2 = s; }
    }
}

// ======================= fused prep kernel =======================
// block order: top3 FIRST (long-running), then transposes / converts / zeroing
#define NB_T3 128
#define NB_P2 8192
#define NB_P1 16384
#define NB_C0 (HH * CIN / 1024)
#define NB_C1 (HH * HH / 1024)
#define NB_TOTAL (NB_T3 + NB_P2 + NB_P1 + NB_C0 + NB_C1 + 1)

__global__ __launch_bounds__(256)
void prep_kernel(const float* __restrict__ xyz1, const float* __restrict__ xyz2,
                 const float* __restrict__ p1, const float* __restrict__ p2,
                 const float* __restrict__ w0g, const float* __restrict__ w1g) {
    __shared__ float sh[8192];
    int r = blockIdx.x;
    const int tid = threadIdx.x;

    if (r < NB_T3) {
        // ---- top-3 nearest neighbors ----
        float* sx = sh;
        float* sy = sh + 2048;
        float* sz = sh + 4096;
        float* sn = sh + 6144;
        const int b = r >> 4;
        const int nbase = (r & 15) * 512;

        for (int i = tid; i < SS; i += 256) {
            float x = xyz2[((size_t)b * 3 + 0) * SS + i];
            float y = xyz2[((size_t)b * 3 + 1) * SS + i];
            float z = xyz2[((size_t)b * 3 + 2) * SS + i];
            sx[i] = x; sy[i] = y; sz[i] = z;
            sn[i] = x * x + y * y + z * z;
        }
        __syncthreads();

        const int na = nbase + tid;
        const int nb = nbase + 256 + tid;
        float xa = xyz1[((size_t)b * 3 + 0) * NN + na];
        float ya = xyz1[((size_t)b * 3 + 1) * NN + na];
        float za = xyz1[((size_t)b * 3 + 2) * NN + na];
        float xb = xyz1[((size_t)b * 3 + 0) * NN + nb];
        float yb = xyz1[((size_t)b * 3 + 1) * NN + nb];
        float zb = xyz1[((size_t)b * 3 + 2) * NN + nb];
        float n1a = xa * xa + ya * ya + za * za;
        float n1b = xb * xb + yb * yb + zb * zb;
        float mxa = -2.f * xa, mya = -2.f * ya, mza = -2.f * za;
        float mxb = -2.f * xb, myb = -2.f * yb, mzb = -2.f * zb;

        Top3 qa = {3.4e38f, 3.4e38f, 3.4e38f, 0, 0, 0};
        Top3 qb = {3.4e38f, 3.4e38f, 3.4e38f, 0, 0, 0};

        for (int s = 0; s < SS; s += 4) {
            float4 vx = ((float4*)sx)[s >> 2], vy = ((float4*)sy)[s >> 2];
            float4 vz = ((float4*)sz)[s >> 2], vn = ((float4*)sn)[s >> 2];
            float t;
            t = fmaf(mxa, vx.x, vn.x); t = fmaf(mya, vy.x, t); t = fmaf(mza, vz.x, t); t3_ins(qa, t, s + 0);
            t = fmaf(mxa, vx.y, vn.y); t = fmaf(mya, vy.y, t); t = fmaf(mza, vz.y, t); t3_ins(qa, t, s + 1);
            t = fmaf(mxa, vx.z, vn.z); t = fmaf(mya, vy.z, t); t = fmaf(mza, vz.z, t); t3_ins(qa, t, s + 2);
            t = fmaf(mxa, vx.w, vn.w); t = fmaf(mya, vy.w, t); t = fmaf(mza, vz.w, t); t3_ins(qa, t, s + 3);
            t = fmaf(mxb, vx.x, vn.x); t = fmaf(myb, vy.x, t); t = fmaf(mzb, vz.x, t); t3_ins(qb, t, s + 0);
            t = fmaf(mxb, vx.y, vn.y); t = fmaf(myb, vy.y, t); t = fmaf(mzb, vz.y, t); t3_ins(qb, t, s + 1);
            t = fmaf(mxb, vx.z, vn.z); t = fmaf(myb, vy.z, t); t = fmaf(mzb, vz.z, t); t3_ins(qb, t, s + 2);
            t = fmaf(mxb, vx.w, vn.w); t = fmaf(myb, vy.w, t); t = fmaf(mzb, vz.w, t); t3_ins(qb, t, s + 3);
        }

        {
            size_t base = ((size_t)b * NN + na) * 3;
            float d0 = qa.d0 + n1a, d1 = qa.d1 + n1a, d2 = qa.d2 + n1a;
            float w0 = 1.0f / (d0 + 1e-8f), w1 = 1.0f / (d1 + 1e-8f), w2 = 1.0f / (d2 + 1e-8f);
            float inv = 1.0f / (w0 + w1 + w2);
            g_idx[base + 0] = qa.i0; g_idx[base + 1] = qa.i1; g_idx[base + 2] = qa.i2;
            g_wgt[base + 0] = w0 * inv; g_wgt[base + 1] = w1 * inv; g_wgt[base + 2] = w2 * inv;
        }
        {
            size_t base = ((size_t)b * NN + nb) * 3;
            float d0 = qb.d0 + n1b, d1 = qb.d1 + n1b, d2 = qb.d2 + n1b;
            float w0 = 1.0f / (d0 + 1e-8f), w1 = 1.0f / (d1 + 1e-8f), w2 = 1.0f / (d2 + 1e-8f);
            float inv = 1.0f / (w0 + w1 + w2);
            g_idx[base + 0] = qb.i0; g_idx[base + 1] = qb.i1; g_idx[base + 2] = qb.i2;
            g_wgt[base + 0] = w0 * inv; g_wgt[base + 1] = w1 * inv; g_wgt[base + 2] = w2 * inv;
        }
        return;
    }
    r -= NB_T3;
    if (r < NB_P2) {
        // ---- transpose points2 (B,512,2048) -> P2T (B,2048,512) ----
        int b = r >> 10, y = (r >> 6) & 15, x = r & 63;
        int c0 = y * 32, s0 = x * 32;
        int tx = tid & 31, ty = tid >> 5;
        float (*t)[33] = (float(*)[33])sh;
#pragma unroll
        for (int j = ty; j < 32; j += 8)
            t[j][tx] = p2[((size_t)b * D2 + c0 + j) * SS + s0 + tx];
        __syncthreads();
#pragma unroll
        for (int j = ty; j < 32; j += 8)
            g_P2T[((size_t)b * SS + s0 + j) * D2 + c0 + tx] = t[tx][j];
        return;
    }
    r -= NB_P2;
    if (r < NB_P1) {
        // ---- transpose points1 (B,256,8192) -> FThi/FTlo[:, :, 0:256] ----
        int b = r >> 11, y = (r >> 8) & 7, x = r & 255;
        int c0 = y * 32, n0 = x * 32;
        int tx = tid & 31, ty = tid >> 5;
        float (*t)[33] = (float(*)[33])sh;
#pragma unroll
        for (int j = ty; j < 32; j += 8)
            t[j][tx] = p1[((size_t)b * D1 + c0 + j) * NN + n0 + tx];
        __syncthreads();
#pragma unroll
        for (int j = ty; j < 32; j += 8) {
            bf16 h, l;
            split_bf(t[tx][j], h, l);
            size_t off = ((size_t)b * NN + n0 + j) * CIN + c0 + tx;
            g_FThi[off] = h;
            g_FTlo[off] = l;
        }
        return;
    }
    r -= NB_P1;
    if (r < NB_C0 + NB_C1) {
        // ---- weight split to bf16 hi/lo (vectorized x4) ----
        const float* src;
        bf16 *hi, *lo;
        int i;
        if (r < NB_C0) { src = w0g; hi = g_W0hi; lo = g_W0lo; i = r * 1024 + tid * 4; }
        else { src = w1g; hi = g_W1hi; lo = g_W1lo; i = (r - NB_C0) * 1024 + tid * 4; }
        float4 v = *(const float4*)(src + i);
        bf16 h0, l0, h1, l1, h2, l2, h3, l3;
        split_bf(v.x, h0, l0); split_bf(v.y, h1, l1);
        split_bf(v.z, h2, l2); split_bf(v.w, h3, l3);
        *(uint2*)&hi[i] = make_uint2(pack2(h0, h1), pack2(h2, h3));
        *(uint2*)&lo[i] = make_uint2(pack2(l0, l1), pack2(l2, l3));
        return;
    }
    // ---- zero stats accumulators ----
    if (tid < 256) {
        g_sum0[tid] = 0.f; g_sum0[tid + 256] = 0.f;
        g_sq0[tid] = 0.f;  g_sq0[tid + 256] = 0.f;
        g_sum1[tid] = 0.f; g_sum1[tid + 256] = 0.f;
        g_sq1[tid] = 0.f;  g_sq1[tid + 256] = 0.f;
    }
}

// ---------------- gather + interpolate -> FThi/FTlo[:, :, 256:768] ----------------
__global__ void gather_kernel() {
    int wglob = blockIdx.x * 8 + (threadIdx.x >> 5);
    int lane = threadIdx.x & 31;
    int b = wglob / NN;
    size_t base = (size_t)wglob * 3;
    int i0 = g_idx[base + 0], i1 = g_idx[base + 1], i2 = g_idx[base + 2];
    float w0 = g_wgt[base + 0], w1 = g_wgt[base + 1], w2 = g_wgt[base + 2];
    const float* r0 = g_P2T + ((size_t)b * SS + i0) * D2;
    const float* r1 = g_P2T + ((size_t)b * SS + i1) * D2;
    const float* r2 = g_P2T + ((size_t)b * SS + i2) * D2;
    size_t dbase = (size_t)wglob * CIN + D1;
#pragma unroll
    for (int c = lane * 4; c < D2; c += 128) {
        float4 v0 = *(const float4*)&r0[c];
        float4 v1 = *(const float4*)&r1[c];
        float4 v2 = *(const float4*)&r2[c];
        float o0 = w0 * v0.x + w1 * v1.x + w2 * v2.x;
        float o1 = w0 * v0.y + w1 * v1.y + w2 * v2.y;
        float o2 = w0 * v0.z + w1 * v1.z + w2 * v2.z;
        float o3 = w0 * v0.w + w1 * v1.w + w2 * v2.w;
        bf16 h0, l0, h1, l1, h2, l2, h3, l3;
        split_bf(o0, h0, l0); split_bf(o1, h1, l1);
        split_bf(o2, h2, l2); split_bf(o3, h3, l3);
        *(uint2*)&g_FThi[dbase + c] = make_uint2(pack2(h0, h1), pack2(h2, h3));
        *(uint2*)&g_FTlo[dbase + c] = make_uint2(pack2(l0, l1), pack2(l2, l3));
    }
}

// ======================= HMMA GEMM 1 (2-stage, ONE sync/iter, fused stats) =======================
#define T1 10240                          // bytes per tile (128 x 40 bf16)
#define ST1 (4 * T1)                      // bytes per stage (Ahi,Alo,Bhi,Blo)
static constexpr int G1_SMEM = 2 * ST1;   // 81920 -> 2 CTAs/SM

__global__ __launch_bounds__(256)
void hmma_gemm1(const bf16* __restrict__ Ahi, const bf16* __restrict__ Alo,
                const bf16* __restrict__ Bhi_g, const bf16* __restrict__ Blo_g,
                const float* __restrict__ bias, float* __restrict__ out) {
    extern __shared__ char smem[];
    const uint32_t sb = smem_u32(smem);
    const int tid = threadIdx.x, lane = tid & 31, wid = tid >> 5;
    const int m0 = blockIdx.x * 128, n0 = blockIdx.y * 128, b = blockIdx.z;
    const int wm = (wid & 3) * 32, wn = (wid >> 2) * 64;

    const bf16* Arow_hi = Ahi + (size_t)m0 * CIN;
    const bf16* Arow_lo = Alo + (size_t)m0 * CIN;
    const bf16* Brow_hi = Bhi_g + ((size_t)b * NN + n0) * CIN;
    const bf16* Brow_lo = Blo_g + ((size_t)b * NN + n0) * CIN;

    float acc[2][8][4];
#pragma unroll
    for (int i = 0; i < 2; i++)
#pragma unroll
        for (int j = 0; j < 8; j++)
#pragma unroll
            for (int q = 0; q < 4; q++) acc[i][j][q] = 0.f;

    const int row_l = tid >> 2, c16 = (tid & 3);
    auto issue = [&](int kb, uint32_t sbuf) {
#pragma unroll
        for (int t = 0; t < 2; t++) {
            int row = row_l + t * 64;
            uint32_t d = sbuf + row * 80 + c16 * 16;
            cpa16(d,          Arow_hi + (size_t)row * CIN + kb + c16 * 8);
            cpa16(d + T1,     Arow_lo + (size_t)row * CIN + kb + c16 * 8);
            cpa16(d + 2 * T1, Brow_hi + (size_t)row * CIN + kb + c16 * 8);
            cpa16(d + 3 * T1, Brow_lo + (size_t)row * CIN + kb + c16 * 8);
        }
        CP_COMMIT();
    };

    const int KT = CIN / 32;   // 24
    issue(0, sb);

    for (int c = 0; c < KT; c++) {
        const int buf = c & 1;
        CP_WAIT(0);            // group c complete (only outstanding group)
        __syncthreads();       // all warps done reading buf^1 (compute c-1)
        if (c + 1 < KT) issue((c + 1) * 32, sb + (buf ^ 1) * ST1);  // safe post-sync

        const uint32_t sA = sb + buf * ST1;
        const uint32_t sB = sA + 2 * T1;
#pragma unroll
        for (int ks = 0; ks < 2; ks++) {
            const int k16 = ks * 16;
            uint32_t ah[2][4], al[2][4];
#pragma unroll
            for (int mi = 0; mi < 2; mi++) {
                uint32_t ad = sA + (wm + mi * 16 + (lane & 15)) * 80
                                 + (k16 + ((lane >> 4) << 3)) * 2;
                ldsm4(ah[mi][0], ah[mi][1], ah[mi][2], ah[mi][3], ad);
                ldsm4(al[mi][0], al[mi][1], al[mi][2], al[mi][3], ad + T1);
            }
            uint32_t bh[8][2], bl[8][2];
#pragma unroll
            for (int ng = 0; ng < 4; ng++) {
                uint32_t row = wn + ng * 16 + (lane & 7) + ((lane & 16) >> 1);
                uint32_t col = k16 + (lane & 8);
                uint32_t ad = sB + row * 80 + col * 2;
                uint32_t r0, r1, r2, r3;
                ldsm4(r0, r1, r2, r3, ad);
                bh[2 * ng][0] = r0; bh[2 * ng][1] = r1;
                bh[2 * ng + 1][0] = r2; bh[2 * ng + 1][1] = r3;
                ldsm4(r0, r1, r2, r3, ad + T1);
                bl[2 * ng][0] = r0; bl[2 * ng][1] = r1;
                bl[2 * ng + 1][0] = r2; bl[2 * ng + 1][1] = r3;
            }
#pragma unroll
            for (int mi = 0; mi < 2; mi++)
#pragma unroll
                for (int ni = 0; ni < 8; ni++) {
                    mma16816(acc[mi][ni], ah[mi], bh[ni]);
                    mma16816(acc[mi][ni], ah[mi], bl[ni]);
                    mma16816(acc[mi][ni], al[mi], bh[ni]);
                }
        }
        // no trailing barrier: next iter's leading sync covers the write hazard
    }

    // epilogue -> out (b, m, n) + bias, fused channel stats via atomics
    const int gq = lane >> 2, tq = lane & 3;
#pragma unroll
    for (int mi = 0; mi < 2; mi++) {
        int r0 = m0 + wm + mi * 16 + gq;
        float bv0 = bias[r0], bv1 = bias[r0 + 8];
        float* o0 = out + ((size_t)b * HH + r0) * NN;
        float* o1 = o0 + (size_t)8 * NN;
        float s0 = 0.f, q0 = 0.f, s1 = 0.f, q1 = 0.f;
#pragma unroll
        for (int ni = 0; ni < 8; ni++) {
            int cc = n0 + wn + ni * 8 + tq * 2;
            float y0 = acc[mi][ni][0] + bv0, y1 = acc[mi][ni][1] + bv0;
            float y2 = acc[mi][ni][2] + bv1, y3 = acc[mi][ni][3] + bv1;
            *(float2*)&o0[cc] = make_float2(y0, y1);
            *(float2*)&o1[cc] = make_float2(y2, y3);
            s0 += y0 + y1; q0 += y0 * y0 + y1 * y1;
            s1 += y2 + y3; q1 += y2 * y2 + y3 * y3;
        }
#pragma unroll
        for (int o = 1; o <= 2; o <<= 1) {
            s0 += __shfl_xor_sync(~0u, s0, o);
            q0 += __shfl_xor_sync(~0u, q0, o);
            s1 += __shfl_xor_sync(~0u, s1, o);
            q1 += __shfl_xor_sync(~0u, q1, o);
        }
        if (tq == 0) {
            atomicAdd(&g_sum0[r0], s0);     atomicAdd(&g_sq0[r0], q0);
            atomicAdd(&g_sum0[r0 + 8], s1); atomicAdd(&g_sq0[r0 + 8], q1);
        }
    }
}

// ======================= HMMA GEMM 2 (fused BN+ReLU on B, ONE sync/iter, fused stats) =======================
#define AT2 10240
#define AST2 (2 * AT2)
#define BT2 8704                 // 32 * 272
#define BST2 (2 * BT2)
static constexpr int G2_SMEM = 2 * AST2 + 2 * BST2;  // 75776

__global__ __launch_bounds__(256)
void hmma_gemm2(const bf16* __restrict__ Ahi, const bf16* __restrict__ Alo,
                const float* __restrict__ X0,
                const float* __restrict__ scale, const float* __restrict__ shift,
                const float* __restrict__ bias, float* __restrict__ out) {
    extern __shared__ char smem[];
    const uint32_t sb = smem_u32(smem);
    const int tid = threadIdx.x, lane = tid & 31, wid = tid >> 5;
    const int m0 = blockIdx.x * 128, n0 = blockIdx.y * 128, b = blockIdx.z;
    const int wm = (wid & 3) * 32, wn = (wid >> 2) * 64;

    const bf16* Arow_hi = Ahi + (size_t)m0 * HH;
    const bf16* Arow_lo = Alo + (size_t)m0 * HH;
    const float* Xb = X0 + (size_t)b * HH * NN + n0;

    float acc[2][8][4];
#pragma unroll
    for (int i = 0; i < 2; i++)
#pragma unroll
        for (int j = 0; j < 8; j++)
#pragma unroll
            for (int q = 0; q < 4; q++) acc[i][j][q] = 0.f;

    const int brow = tid >> 3, bcol = (tid & 7) * 16;
    float x[16];
    float scl, shf;

    const int row_l = tid >> 2, c16 = (tid & 3);
    auto issueA = [&](int kb, uint32_t sbuf) {
#pragma unroll
        for (int t = 0; t < 2; t++) {
            int row = row_l + t * 64;
            uint32_t d = sbuf + row * 80 + c16 * 16;
            cpa16(d,       Arow_hi + (size_t)row * HH + kb + c16 * 8);
            cpa16(d + AT2, Arow_lo + (size_t)row * HH + kb + c16 * 8);
        }
        CP_COMMIT();
    };

    // prologue: A group 0 + x regs for chunk 0
    {
        issueA(0, sb);
        const float* src = Xb + (size_t)brow * NN + bcol;
#pragma unroll
        for (int j = 0; j < 4; j++) {
            float4 v = *(const float4*)(src + j * 4);
            x[4 * j] = v.x; x[4 * j + 1] = v.y; x[4 * j + 2] = v.z; x[4 * j + 3] = v.w;
        }
        scl = scale[brow];
        shf = shift[brow];
    }

    const uint32_t sBbase = sb + 2 * AST2;
    const int KT = HH / 32;  // 16
    for (int c = 0; c < KT; c++) {
        const int buf = c & 1;
        // STS-transform chunk c into B buf (written buffer last read at compute c-2;
        // separated by the sync of iteration c-1)
        {
            uint32_t doff = (buf * BST2 + brow * 272 + bcol * 2) + 2 * AST2;
#pragma unroll
            for (int j = 0; j < 4; j++) {
                float y0 = fmaxf(fmaf(x[4 * j + 0], scl, shf), 0.f);
                float y1 = fmaxf(fmaf(x[4 * j + 1], scl, shf), 0.f);
                float y2 = fmaxf(fmaf(x[4 * j + 2], scl, shf), 0.f);
                float y3 = fmaxf(fmaf(x[4 * j + 3], scl, shf), 0.f);
                bf16 h0, l0, h1, l1, h2, l2, h3, l3;
                split_bf(y0, h0, l0); split_bf(y1, h1, l1);
                split_bf(y2, h2, l2); split_bf(y3, h3, l3);
                *(uint2*)(smem + doff + j * 8) = make_uint2(pack2(h0, h1), pack2(h2, h3));
                *(uint2*)(smem + doff + BT2 + j * 8) = make_uint2(pack2(l0, l1), pack2(l2, l3));
            }
        }
        CP_WAIT(0);            // A group c complete
        __syncthreads();       // STS visible; all warps done with compute(c-1)
        if (c + 1 < KT) {
            const int kb = (c + 1) * 32;
            issueA(kb, sb + (buf ^ 1) * AST2);   // safe post-sync (read at c-1 done)
            const float* src = Xb + (size_t)(kb + brow) * NN + bcol;
#pragma unroll
            for (int j = 0; j < 4; j++) {
                float4 v = *(const float4*)(src + j * 4);
                x[4 * j] = v.x; x[4 * j + 1] = v.y; x[4 * j + 2] = v.z; x[4 * j + 3] = v.w;
            }
            scl = scale[kb + brow];
            shf = shift[kb + brow];
        }

        const uint32_t sA = sb + buf * AST2;
        const uint32_t sB = sBbase + buf * BST2;
#pragma unroll
        for (int ks = 0; ks < 2; ks++) {
            const int k16 = ks * 16;
            uint32_t ah[2][4], al[2][4];
#pragma unroll
            for (int mi = 0; mi < 2; mi++) {
                uint32_t ad = sA + (wm + mi * 16 + (lane & 15)) * 80
                                 + (k16 + ((lane >> 4) << 3)) * 2;
                ldsm4(ah[mi][0], ah[mi][1], ah[mi][2], ah[mi][3], ad);
                ldsm4(al[mi][0], al[mi][1], al[mi][2], al[mi][3], ad + AT2);
            }
            uint32_t bh[8][2], bl[8][2];
#pragma unroll
            for (int ng = 0; ng < 4; ng++) {
                uint32_t row = k16 + (lane & 7) + (lane & 8);
                uint32_t col = wn + ng * 16 + ((lane >> 4) << 3);
                uint32_t ad = sB + row * 272 + col * 2;
                uint32_t r0, r1, r2, r3;
                ldsm4t(r0, r1, r2, r3, ad);
                bh[2 * ng][0] = r0; bh[2 * ng][1] = r1;
                bh[2 * ng + 1][0] = r2; bh[2 * ng + 1][1] = r3;
                ldsm4t(r0, r1, r2, r3, ad + BT2);
                bl[2 * ng][0] = r0; bl[2 * ng][1] = r1;
                bl[2 * ng + 1][0] = r2; bl[2 * ng + 1][1] = r3;
            }
#pragma unroll
            for (int mi = 0; mi < 2; mi++)
#pragma unroll
                for (int ni = 0; ni < 8; ni++) {
                    mma16816(acc[mi][ni], ah[mi], bh[ni]);
                    mma16816(acc[mi][ni], ah[mi], bl[ni]);
                    mma16816(acc[mi][ni], al[mi], bh[ni]);
                }
        }
        // no trailing barrier
    }

    const int gq = lane >> 2, tq = lane & 3;
#pragma unroll
    for (int mi = 0; mi < 2; mi++) {
        int r0 = m0 + wm + mi * 16 + gq;
        float bv0 = bias[r0], bv1 = bias[r0 + 8];
        float* o0 = out + ((size_t)b * HH + r0) * NN;
        float* o1 = o0 + (size_t)8 * NN;
        float s0 = 0.f, q0 = 0.f, s1 = 0.f, q1 = 0.f;
#pragma unroll
        for (int ni = 0; ni < 8; ni++) {
            int cc = n0 + wn + ni * 8 + tq * 2;
            float y0 = acc[mi][ni][0] + bv0, y1 = acc[mi][ni][1] + bv0;
            float y2 = acc[mi][ni][2] + bv1, y3 = acc[mi][ni][3] + bv1;
            *(float2*)&o0[cc] = make_float2(y0, y1);
            *(float2*)&o1[cc] = make_float2(y2, y3);
            s0 += y0 + y1; q0 += y0 * y0 + y1 * y1;
            s1 += y2 + y3; q1 += y2 * y2 + y3 * y3;
        }
#pragma unroll
        for (int o = 1; o <= 2; o <<= 1) {
            s0 += __shfl_xor_sync(~0u, s0, o);
            q0 += __shfl_xor_sync(~0u, q0, o);
            s1 += __shfl_xor_sync(~0u, s1, o);
            q1 += __shfl_xor_sync(~0u, q1, o);
        }
        if (tq == 0) {
            atomicAdd(&g_sum1[r0], s0);     atomicAdd(&g_sq1[r0], q0);
            atomicAdd(&g_sum1[r0 + 8], s1); atomicAdd(&g_sq1[r0 + 8], q1);
        }
    }
}

// ---------------- stats finalize ----------------
__global__ void stats_final_kernel(const float* __restrict__ gsum,
                                   const float* __restrict__ gsq,
                                   const float* __restrict__ g,
                                   const float* __restrict__ be,
                                   float* __restrict__ scale,
                                   float* __restrict__ shift) {
    const int c = threadIdx.x;
    const float inv = 1.f / (float)(BB * NN);
    float m = gsum[c] * inv;
    float var = gsq[c] * inv - m * m;
    float sc = g[c] * rsqrtf(var + 1e-5f);
    scale[c] = sc;
    shift[c] = be[c] - m * sc;
}

__global__ void apply_bn_kernel(float* __restrict__ X) {
    const size_t total4 = (size_t)BB * HH * NN / 4;
    for (size_t i = (size_t)blockIdx.x * blockDim.x + threadIdx.x; i < total4;
         i += (size_t)gridDim.x * blockDim.x) {
        float4 v = ((float4*)X)[i];
        int c = (int)((i * 4) >> 13) & (HH - 1);
        float s = g_scale1[c], h = g_shift1[c];
        v.x = fmaxf(fmaf(v.x, s, h), 0.f);
        v.y = fmaxf(fmaf(v.y, s, h), 0.f);
        v.z = fmaxf(fmaf(v.z, s, h), 0.f);
        v.w = fmaxf(fmaf(v.w, s, h), 0.f);
        ((float4*)X)[i] = v;
    }
}

// ======================= launcher =======================
extern "C" void kernel_launch(void* const* d_in, const int* in_sizes, int n_in,
                              void* d_out, int out_size) {
    const float* xyz1    = (const float*)d_in[0];
    const float* xyz2    = (const float*)d_in[1];
    const float* points1 = (const float*)d_in[2];
    const float* points2 = (const float*)d_in[3];
    const float* w0 = (const float*)d_in[4];
    const float* b0 = (const float*)d_in[5];
    const float* g0 = (const float*)d_in[6];
    const float* be0 = (const float*)d_in[7];
    const float* w1 = (const float*)d_in[8];
    const float* b1 = (const float*)d_in[9];
    const float* g1 = (const float*)d_in[10];
    const float* be1 = (const float*)d_in[11];
    float* out = (float*)d_out;

    float *p_scale0, *p_shift0, *p_scale1, *p_shift1, *p_X0;
    float *p_sum0, *p_sq0, *p_sum1, *p_sq1;
    bf16 *p_W0hi, *p_W0lo, *p_W1hi, *p_W1lo, *p_FThi, *p_FTlo;
    cudaGetSymbolAddress((void**)&p_scale0, g_scale0);
    cudaGetSymbolAddress((void**)&p_shift0, g_shift0);
    cudaGetSymbolAddress((void**)&p_scale1, g_scale1);
    cudaGetSymbolAddress((void**)&p_shift1, g_shift1);
    cudaGetSymbolAddress((void**)&p_X0, g_X0);
    cudaGetSymbolAddress((void**)&p_sum0, g_sum0);
    cudaGetSymbolAddress((void**)&p_sq0, g_sq0);
    cudaGetSymbolAddress((void**)&p_sum1, g_sum1);
    cudaGetSymbolAddress((void**)&p_sq1, g_sq1);
    cudaGetSymbolAddress((void**)&p_W0hi, g_W0hi);
    cudaGetSymbolAddress((void**)&p_W0lo, g_W0lo);
    cudaGetSymbolAddress((void**)&p_W1hi, g_W1hi);
    cudaGetSymbolAddress((void**)&p_W1lo, g_W1lo);
    cudaGetSymbolAddress((void**)&p_FThi, g_FThi);
    cudaGetSymbolAddress((void**)&p_FTlo, g_FTlo);

    cudaFuncSetAttribute(hmma_gemm1, cudaFuncAttributeMaxDynamicSharedMemorySize, G1_SMEM);
    cudaFuncSetAttribute(hmma_gemm2, cudaFuncAttributeMaxDynamicSharedMemorySize, G2_SMEM);

    prep_kernel<<<NB_TOTAL, 256>>>(xyz1, xyz2, points1, points2, w0, w1);
    gather_kernel<<<BB * NN / 8, 256>>>();

    hmma_gemm1<<<dim3(HH / 128, NN / 128, BB), 256, G1_SMEM>>>(
        p_W0hi, p_W0lo, p_FThi, p_FTlo, b0, p_X0);
    stats_final_kernel<<<1, HH>>>(p_sum0, p_sq0, g0, be0, p_scale0, p_shift0);

    hmma_gemm2<<<dim3(HH / 128, NN / 128, BB), 256, G2_SMEM>>>(
        p_W1hi, p_W1lo, p_X0, p_scale0, p_shift0, b1, out);
    stats_final_kernel<<<1, HH>>>(p_sum1, p_sq1, g1, be1, p_scale1, p_shift1);
    apply_bn_kernel<<<4096, 256>>>(out);
}

// round 9
// speedup vs baseline: 1.1543x; 1.1270x over previous
#include <cuda_runtime.h>
#include <cuda_bf16.h>
#include <cstdint>

// Problem constants
#define BB 8
#define NN 8192
#define SS 2048
#define D1 256
#define D2 512
#define CIN 768
#define HH 512

typedef __nv_bfloat16 bf16;

// ---------------- scratch (static device globals; no runtime alloc) ----------------
__device__ float g_P2T[(size_t)BB * SS * D2];
__device__ int   g_idx[(size_t)BB * NN * 3];
__device__ float g_wgt[(size_t)BB * NN * 3];
__device__ bf16 g_FThi[(size_t)BB * NN * CIN];
__device__ bf16 g_FTlo[(size_t)BB * NN * CIN];
__device__ bf16 g_W0hi[HH * CIN], g_W0lo[HH * CIN];
__device__ bf16 g_W1hi[HH * HH],  g_W1lo[HH * HH];
__device__ float g_X0[(size_t)BB * HH * NN];           // (b, c, n)
__device__ float g_sum0[HH], g_sq0[HH], g_sum1[HH], g_sq1[HH];
__device__ float g_scale0[HH], g_shift0[HH], g_scale1[HH], g_shift1[HH];

// ======================= low-level helpers =======================
__device__ __forceinline__ uint32_t smem_u32(const void* p) {
    uint32_t a;
    asm("{ .reg .u64 t; cvta.to.shared.u64 t, %1; cvt.u32.u64 %0, t; }" : "=r"(a) : "l"(p));
    return a;
}
__device__ __forceinline__ void ldsm4(uint32_t& r0, uint32_t& r1, uint32_t& r2,
                                      uint32_t& r3, uint32_t a) {
    asm volatile("ldmatrix.sync.aligned.m8n8.x4.shared.b16 {%0,%1,%2,%3},[%4];"
                 : "=r"(r0), "=r"(r1), "=r"(r2), "=r"(r3) : "r"(a));
}
__device__ __forceinline__ void ldsm4t(uint32_t& r0, uint32_t& r1, uint32_t& r2,
                                       uint32_t& r3, uint32_t a) {
    asm volatile("ldmatrix.sync.aligned.m8n8.x4.trans.shared.b16 {%0,%1,%2,%3},[%4];"
                 : "=r"(r0), "=r"(r1), "=r"(r2), "=r"(r3) : "r"(a));
}
__device__ __forceinline__ void mma16816(float* d, const uint32_t* a, const uint32_t* b) {
    asm volatile(
        "mma.sync.aligned.m16n8k16.row.col.f32.bf16.bf16.f32 "
        "{%0,%1,%2,%3},{%4,%5,%6,%7},{%8,%9},{%0,%1,%2,%3};"
        : "+f"(d[0]), "+f"(d[1]), "+f"(d[2]), "+f"(d[3])
        : "r"(a[0]), "r"(a[1]), "r"(a[2]), "r"(a[3]), "r"(b[0]), "r"(b[1]));
}
__device__ __forceinline__ void cpa16(uint32_t dst, const void* src) {
    asm volatile("cp.async.cg.shared.global [%0],[%1],16;" :: "r"(dst), "l"(src));
}
#define CP_COMMIT() asm volatile("cp.async.commit_group;" ::: "memory")
#define CP_WAIT(n) asm volatile("cp.async.wait_group %0;" :: "n"(n) : "memory")

__device__ __forceinline__ void split_bf(float v, bf16& h, bf16& l) {
    h = __float2bfloat16_rn(v);
    l = __float2bfloat16_rn(v - __bfloat162float(h));
}
__device__ __forceinline__ uint32_t pack2(bf16 a, bf16 b) {
    __nv_bfloat162 t = __halves2bfloat162(a, b);
    return *reinterpret_cast<uint32_t*>(&t);
}

// ---------------- top-3 helper ----------------
struct Top3 { float d0, d1, d2; int i0, i1, i2; };
__device__ __forceinline__ void t3_ins(Top3& q, float t, int s) {
    if (t < q.d2) {
        if (t < q.d1) {
            q.d2 = q.d1; q.i2 = q.i1;
            if (t < q.d0) { q.d1 = q.d0; q.i1 = q.i0; q.d0 = t; q.i0 = s; }
            else          { q.d1 = t;    q.i1 = s; }
        } else { q.d2 = t; q.i2 = s; }
    }
}

// ======================= fused prep kernel =======================
#define NB_T3 128
#define NB_P2 8192
#define NB_P1 16384
#define NB_C0 (HH * CIN / 1024)
#define NB_C1 (HH * HH / 1024)
#define NB_TOTAL (NB_T3 + NB_P2 + NB_P1 + NB_C0 + NB_C1 + 1)

__global__ __launch_bounds__(256)
void prep_kernel(const float* __restrict__ xyz1, const float* __restrict__ xyz2,
                 const float* __restrict__ p1, const float* __restrict__ p2,
                 const float* __restrict__ w0g, const float* __restrict__ w1g) {
    __shared__ float sh[8192];
    int r = blockIdx.x;
    const int tid = threadIdx.x;

    if (r < NB_T3) {
        float* sx = sh;
        float* sy = sh + 2048;
        float* sz = sh + 4096;
        float* sn = sh + 6144;
        const int b = r >> 4;
        const int nbase = (r & 15) * 512;

        for (int i = tid; i < SS; i += 256) {
            float x = xyz2[((size_t)b * 3 + 0) * SS + i];
            float y = xyz2[((size_t)b * 3 + 1) * SS + i];
            float z = xyz2[((size_t)b * 3 + 2) * SS + i];
            sx[i] = x; sy[i] = y; sz[i] = z;
            sn[i] = x * x + y * y + z * z;
        }
        __syncthreads();

        const int na = nbase + tid;
        const int nb = nbase + 256 + tid;
        float xa = xyz1[((size_t)b * 3 + 0) * NN + na];
        float ya = xyz1[((size_t)b * 3 + 1) * NN + na];
        float za = xyz1[((size_t)b * 3 + 2) * NN + na];
        float xb = xyz1[((size_t)b * 3 + 0) * NN + nb];
        float yb = xyz1[((size_t)b * 3 + 1) * NN + nb];
        float zb = xyz1[((size_t)b * 3 + 2) * NN + nb];
        float n1a = xa * xa + ya * ya + za * za;
        float n1b = xb * xb + yb * yb + zb * zb;
        float mxa = -2.f * xa, mya = -2.f * ya, mza = -2.f * za;
        float mxb = -2.f * xb, myb = -2.f * yb, mzb = -2.f * zb;

        Top3 qa = {3.4e38f, 3.4e38f, 3.4e38f, 0, 0, 0};
        Top3 qb = {3.4e38f, 3.4e38f, 3.4e38f, 0, 0, 0};

        for (int s = 0; s < SS; s += 4) {
            float4 vx = ((float4*)sx)[s >> 2], vy = ((float4*)sy)[s >> 2];
            float4 vz = ((float4*)sz)[s >> 2], vn = ((float4*)sn)[s >> 2];
            float t;
            t = fmaf(mxa, vx.x, vn.x); t = fmaf(mya, vy.x, t); t = fmaf(mza, vz.x, t); t3_ins(qa, t, s + 0);
            t = fmaf(mxa, vx.y, vn.y); t = fmaf(mya, vy.y, t); t = fmaf(mza, vz.y, t); t3_ins(qa, t, s + 1);
            t = fmaf(mxa, vx.z, vn.z); t = fmaf(mya, vy.z, t); t = fmaf(mza, vz.z, t); t3_ins(qa, t, s + 2);
            t = fmaf(mxa, vx.w, vn.w); t = fmaf(mya, vy.w, t); t = fmaf(mza, vz.w, t); t3_ins(qa, t, s + 3);
            t = fmaf(mxb, vx.x, vn.x); t = fmaf(myb, vy.x, t); t = fmaf(mzb, vz.x, t); t3_ins(qb, t, s + 0);
            t = fmaf(mxb, vx.y, vn.y); t = fmaf(myb, vy.y, t); t = fmaf(mzb, vz.y, t); t3_ins(qb, t, s + 1);
            t = fmaf(mxb, vx.z, vn.z); t = fmaf(myb, vy.z, t); t = fmaf(mzb, vz.z, t); t3_ins(qb, t, s + 2);
            t = fmaf(mxb, vx.w, vn.w); t = fmaf(myb, vy.w, t); t = fmaf(mzb, vz.w, t); t3_ins(qb, t, s + 3);
        }

        {
            size_t base = ((size_t)b * NN + na) * 3;
            float d0 = qa.d0 + n1a, d1 = qa.d1 + n1a, d2 = qa.d2 + n1a;
            float w0 = 1.0f / (d0 + 1e-8f), w1 = 1.0f / (d1 + 1e-8f), w2 = 1.0f / (d2 + 1e-8f);
            float inv = 1.0f / (w0 + w1 + w2);
            g_idx[base + 0] = qa.i0; g_idx[base + 1] = qa.i1; g_idx[base + 2] = qa.i2;
            g_wgt[base + 0] = w0 * inv; g_wgt[base + 1] = w1 * inv; g_wgt[base + 2] = w2 * inv;
        }
        {
            size_t base = ((size_t)b * NN + nb) * 3;
            float d0 = qb.d0 + n1b, d1 = qb.d1 + n1b, d2 = qb.d2 + n1b;
            float w0 = 1.0f / (d0 + 1e-8f), w1 = 1.0f / (d1 + 1e-8f), w2 = 1.0f / (d2 + 1e-8f);
            float inv = 1.0f / (w0 + w1 + w2);
            g_idx[base + 0] = qb.i0; g_idx[base + 1] = qb.i1; g_idx[base + 2] = qb.i2;
            g_wgt[base + 0] = w0 * inv; g_wgt[base + 1] = w1 * inv; g_wgt[base + 2] = w2 * inv;
        }
        return;
    }
    r -= NB_T3;
    if (r < NB_P2) {
        int b = r >> 10, y = (r >> 6) & 15, x = r & 63;
        int c0 = y * 32, s0 = x * 32;
        int tx = tid & 31, ty = tid >> 5;
        float (*t)[33] = (float(*)[33])sh;
#pragma unroll
        for (int j = ty; j < 32; j += 8)
            t[j][tx] = p2[((size_t)b * D2 + c0 + j) * SS + s0 + tx];
        __syncthreads();
#pragma unroll
        for (int j = ty; j < 32; j += 8)
            g_P2T[((size_t)b * SS + s0 + j) * D2 + c0 + tx] = t[tx][j];
        return;
    }
    r -= NB_P2;
    if (r < NB_P1) {
        int b = r >> 11, y = (r >> 8) & 7, x = r & 255;
        int c0 = y * 32, n0 = x * 32;
        int tx = tid & 31, ty = tid >> 5;
        float (*t)[33] = (float(*)[33])sh;
#pragma unroll
        for (int j = ty; j < 32; j += 8)
            t[j][tx] = p1[((size_t)b * D1 + c0 + j) * NN + n0 + tx];
        __syncthreads();
#pragma unroll
        for (int j = ty; j < 32; j += 8) {
            bf16 h, l;
            split_bf(t[tx][j], h, l);
            size_t off = ((size_t)b * NN + n0 + j) * CIN + c0 + tx;
            g_FThi[off] = h;
            g_FTlo[off] = l;
        }
        return;
    }
    r -= NB_P1;
    if (r < NB_C0 + NB_C1) {
        const float* src;
        bf16 *hi, *lo;
        int i;
        if (r < NB_C0) { src = w0g; hi = g_W0hi; lo = g_W0lo; i = r * 1024 + tid * 4; }
        else { src = w1g; hi = g_W1hi; lo = g_W1lo; i = (r - NB_C0) * 1024 + tid * 4; }
        float4 v = *(const float4*)(src + i);
        bf16 h0, l0, h1, l1, h2, l2, h3, l3;
        split_bf(v.x, h0, l0); split_bf(v.y, h1, l1);
        split_bf(v.z, h2, l2); split_bf(v.w, h3, l3);
        *(uint2*)&hi[i] = make_uint2(pack2(h0, h1), pack2(h2, h3));
        *(uint2*)&lo[i] = make_uint2(pack2(l0, l1), pack2(l2, l3));
        return;
    }
    if (tid < 256) {
        g_sum0[tid] = 0.f; g_sum0[tid + 256] = 0.f;
        g_sq0[tid] = 0.f;  g_sq0[tid + 256] = 0.f;
        g_sum1[tid] = 0.f; g_sum1[tid + 256] = 0.f;
        g_sq1[tid] = 0.f;  g_sq1[tid + 256] = 0.f;
    }
}

// ---------------- gather + interpolate -> FThi/FTlo[:, :, 256:768] ----------------
__global__ void gather_kernel() {
    int wglob = blockIdx.x * 8 + (threadIdx.x >> 5);
    int lane = threadIdx.x & 31;
    int b = wglob / NN;
    size_t base = (size_t)wglob * 3;
    int i0 = g_idx[base + 0], i1 = g_idx[base + 1], i2 = g_idx[base + 2];
    float w0 = g_wgt[base + 0], w1 = g_wgt[base + 1], w2 = g_wgt[base + 2];
    const float* r0 = g_P2T + ((size_t)b * SS + i0) * D2;
    const float* r1 = g_P2T + ((size_t)b * SS + i1) * D2;
    const float* r2 = g_P2T + ((size_t)b * SS + i2) * D2;
    size_t dbase = (size_t)wglob * CIN + D1;
#pragma unroll
    for (int c = lane * 4; c < D2; c += 128) {
        float4 v0 = *(const float4*)&r0[c];
        float4 v1 = *(const float4*)&r1[c];
        float4 v2 = *(const float4*)&r2[c];
        float o0 = w0 * v0.x + w1 * v1.x + w2 * v2.x;
        float o1 = w0 * v0.y + w1 * v1.y + w2 * v2.y;
        float o2 = w0 * v0.z + w1 * v1.z + w2 * v2.z;
        float o3 = w0 * v0.w + w1 * v1.w + w2 * v2.w;
        bf16 h0, l0, h1, l1, h2, l2, h3, l3;
        split_bf(o0, h0, l0); split_bf(o1, h1, l1);
        split_bf(o2, h2, l2); split_bf(o3, h3, l3);
        *(uint2*)&g_FThi[dbase + c] = make_uint2(pack2(h0, h1), pack2(h2, h3));
        *(uint2*)&g_FTlo[dbase + c] = make_uint2(pack2(l0, l1), pack2(l2, l3));
    }
}

// ======================= HMMA GEMM 1 (R5 structure, low-reg inner loop) =======================
#define T1 10240                          // bytes per tile (128 x 40 bf16)
#define ST1 (4 * T1)                      // bytes per stage (Ahi,Alo,Bhi,Blo)
static constexpr int G1_SMEM = 2 * ST1;   // 81920 -> 2 CTAs/SM

__global__ __launch_bounds__(256, 2)
void hmma_gemm1(const bf16* __restrict__ Ahi, const bf16* __restrict__ Alo,
                const bf16* __restrict__ Bhi_g, const bf16* __restrict__ Blo_g,
                const float* __restrict__ bias, float* __restrict__ out) {
    extern __shared__ char smem[];
    const uint32_t sb = smem_u32(smem);
    const int tid = threadIdx.x, lane = tid & 31, wid = tid >> 5;
    const int m0 = blockIdx.x * 128, n0 = blockIdx.y * 128, b = blockIdx.z;
    const int wm = (wid & 3) * 32, wn = (wid >> 2) * 64;

    const bf16* Arow_hi = Ahi + (size_t)m0 * CIN;
    const bf16* Arow_lo = Alo + (size_t)m0 * CIN;
    const bf16* Brow_hi = Bhi_g + ((size_t)b * NN + n0) * CIN;
    const bf16* Brow_lo = Blo_g + ((size_t)b * NN + n0) * CIN;

    float acc[2][8][4];
#pragma unroll
    for (int i = 0; i < 2; i++)
#pragma unroll
        for (int j = 0; j < 8; j++)
#pragma unroll
            for (int q = 0; q < 4; q++) acc[i][j][q] = 0.f;

    const int row_l = tid >> 2, c16 = (tid & 3);
    auto issue = [&](int kb, uint32_t sbuf) {
#pragma unroll
        for (int t = 0; t < 2; t++) {
            int row = row_l + t * 64;
            uint32_t d = sbuf + row * 80 + c16 * 16;
            cpa16(d,          Arow_hi + (size_t)row * CIN + kb + c16 * 8);
            cpa16(d + T1,     Arow_lo + (size_t)row * CIN + kb + c16 * 8);
            cpa16(d + 2 * T1, Brow_hi + (size_t)row * CIN + kb + c16 * 8);
            cpa16(d + 3 * T1, Brow_lo + (size_t)row * CIN + kb + c16 * 8);
        }
        CP_COMMIT();
    };

    const int KT = CIN / 32;   // 24
    issue(0, sb);

    for (int c = 0; c < KT; c++) {
        const int buf = c & 1;
        if (c + 1 < KT) {
            issue((c + 1) * 32, sb + (buf ^ 1) * ST1);
            CP_WAIT(1);
        } else {
            CP_WAIT(0);
        }
        __syncthreads();

        const uint32_t sA = sb + buf * ST1;
        const uint32_t sB = sA + 2 * T1;
#pragma unroll
        for (int ks = 0; ks < 2; ks++) {
            const int k16 = ks * 16;
            uint32_t ah[2][4], al[2][4];
#pragma unroll
            for (int mi = 0; mi < 2; mi++) {
                uint32_t ad = sA + (wm + mi * 16 + (lane & 15)) * 80
                                 + (k16 + ((lane >> 4) << 3)) * 2;
                ldsm4(ah[mi][0], ah[mi][1], ah[mi][2], ah[mi][3], ad);
                ldsm4(al[mi][0], al[mi][1], al[mi][2], al[mi][3], ad + T1);
            }
#pragma unroll
            for (int ng = 0; ng < 4; ng++) {
                uint32_t row = wn + ng * 16 + (lane & 7) + ((lane & 16) >> 1);
                uint32_t col = k16 + (lane & 8);
                uint32_t ad = sB + row * 80 + col * 2;
                uint32_t bh[4], bl[4];
                ldsm4(bh[0], bh[1], bh[2], bh[3], ad);
                ldsm4(bl[0], bl[1], bl[2], bl[3], ad + T1);
#pragma unroll
                for (int mi = 0; mi < 2; mi++) {
                    mma16816(acc[mi][2 * ng],     ah[mi], bh);
                    mma16816(acc[mi][2 * ng],     ah[mi], bl);
                    mma16816(acc[mi][2 * ng],     al[mi], bh);
                    mma16816(acc[mi][2 * ng + 1], ah[mi], bh + 2);
                    mma16816(acc[mi][2 * ng + 1], ah[mi], bl + 2);
                    mma16816(acc[mi][2 * ng + 1], al[mi], bh + 2);
                }
            }
        }
        __syncthreads();
    }

    // epilogue -> out (b, m, n) + bias, fused channel stats via atomics
    const int gq = lane >> 2, tq = lane & 3;
#pragma unroll
    for (int mi = 0; mi < 2; mi++) {
        int r0 = m0 + wm + mi * 16 + gq;
        float bv0 = bias[r0], bv1 = bias[r0 + 8];
        float* o0 = out + ((size_t)b * HH + r0) * NN;
        float* o1 = o0 + (size_t)8 * NN;
        float s0 = 0.f, q0 = 0.f, s1 = 0.f, q1 = 0.f;
#pragma unroll
        for (int ni = 0; ni < 8; ni++) {
            int cc = n0 + wn + ni * 8 + tq * 2;
            float y0 = acc[mi][ni][0] + bv0, y1 = acc[mi][ni][1] + bv0;
            float y2 = acc[mi][ni][2] + bv1, y3 = acc[mi][ni][3] + bv1;
            *(float2*)&o0[cc] = make_float2(y0, y1);
            *(float2*)&o1[cc] = make_float2(y2, y3);
            s0 += y0 + y1; q0 += y0 * y0 + y1 * y1;
            s1 += y2 + y3; q1 += y2 * y2 + y3 * y3;
        }
#pragma unroll
        for (int o = 1; o <= 2; o <<= 1) {
            s0 += __shfl_xor_sync(~0u, s0, o);
            q0 += __shfl_xor_sync(~0u, q0, o);
            s1 += __shfl_xor_sync(~0u, s1, o);
            q1 += __shfl_xor_sync(~0u, q1, o);
        }
        if (tq == 0) {
            atomicAdd(&g_sum0[r0], s0);     atomicAdd(&g_sq0[r0], q0);
            atomicAdd(&g_sum0[r0 + 8], s1); atomicAdd(&g_sq0[r0 + 8], q1);
        }
    }
}

// ======================= HMMA GEMM 2 (R5 structure, low-reg inner loop) =======================
#define AT2 10240
#define AST2 (2 * AT2)
#define BT2 8704                 // 32 * 272
#define BST2 (2 * BT2)
static constexpr int G2_SMEM = 2 * AST2 + 2 * BST2;  // 75776

__global__ __launch_bounds__(256, 2)
void hmma_gemm2(const bf16* __restrict__ Ahi, const bf16* __restrict__ Alo,
                const float* __restrict__ X0,
                const float* __restrict__ scale, const float* __restrict__ shift,
                const float* __restrict__ bias, float* __restrict__ out) {
    extern __shared__ char smem[];
    const uint32_t sb = smem_u32(smem);
    const int tid = threadIdx.x, lane = tid & 31, wid = tid >> 5;
    const int m0 = blockIdx.x * 128, n0 = blockIdx.y * 128, b = blockIdx.z;
    const int wm = (wid & 3) * 32, wn = (wid >> 2) * 64;

    const bf16* Arow_hi = Ahi + (size_t)m0 * HH;
    const bf16* Arow_lo = Alo + (size_t)m0 * HH;
    const float* Xb = X0 + (size_t)b * HH * NN + n0;

    float acc[2][8][4];
#pragma unroll
    for (int i = 0; i < 2; i++)
#pragma unroll
        for (int j = 0; j < 8; j++)
#pragma unroll
            for (int q = 0; q < 4; q++) acc[i][j][q] = 0.f;

    const int brow = tid >> 3, bcol = (tid & 7) * 16;
    float x[16];
    float scl, shf;

    const int row_l = tid >> 2, c16 = (tid & 3);
    {
#pragma unroll
        for (int t = 0; t < 2; t++) {
            int row = row_l + t * 64;
            uint32_t d = sb + row * 80 + c16 * 16;
            cpa16(d,       Arow_hi + (size_t)row * HH + c16 * 8);
            cpa16(d + AT2, Arow_lo + (size_t)row * HH + c16 * 8);
        }
        CP_COMMIT();
        const float* src = Xb + (size_t)brow * NN + bcol;
#pragma unroll
        for (int j = 0; j < 4; j++) {
            float4 v = *(const float4*)(src + j * 4);
            x[4 * j] = v.x; x[4 * j + 1] = v.y; x[4 * j + 2] = v.z; x[4 * j + 3] = v.w;
        }
        scl = scale[brow];
        shf = shift[brow];
    }

    const uint32_t sBbase = sb + 2 * AST2;
    const int KT = HH / 32;  // 16
    for (int c = 0; c < KT; c++) {
        const int buf = c & 1;
        {
            uint32_t doff = (buf * BST2 + brow * 272 + bcol * 2) + 2 * AST2;
#pragma unroll
            for (int j = 0; j < 4; j++) {
                float y0 = fmaxf(fmaf(x[4 * j + 0], scl, shf), 0.f);
                float y1 = fmaxf(fmaf(x[4 * j + 1], scl, shf), 0.f);
                float y2 = fmaxf(fmaf(x[4 * j + 2], scl, shf), 0.f);
                float y3 = fmaxf(fmaf(x[4 * j + 3], scl, shf), 0.f);
                bf16 h0, l0, h1, l1, h2, l2, h3, l3;
                split_bf(y0, h0, l0); split_bf(y1, h1, l1);
                split_bf(y2, h2, l2); split_bf(y3, h3, l3);
                *(uint2*)(smem + doff + j * 8) = make_uint2(pack2(h0, h1), pack2(h2, h3));
                *(uint2*)(smem + doff + BT2 + j * 8) = make_uint2(pack2(l0, l1), pack2(l2, l3));
            }
        }
        if (c + 1 < KT) {
            const int kb = (c + 1) * 32;
            const uint32_t s2 = sb + (buf ^ 1) * AST2;
#pragma unroll
            for (int t = 0; t < 2; t++) {
                int row = row_l + t * 64;
                uint32_t d = s2 + row * 80 + c16 * 16;
                cpa16(d,       Arow_hi + (size_t)row * HH + kb + c16 * 8);
                cpa16(d + AT2, Arow_lo + (size_t)row * HH + kb + c16 * 8);
            }
            CP_COMMIT();
            const float* src = Xb + (size_t)(kb + brow) * NN + bcol;
#pragma unroll
            for (int j = 0; j < 4; j++) {
                float4 v = *(const float4*)(src + j * 4);
                x[4 * j] = v.x; x[4 * j + 1] = v.y; x[4 * j + 2] = v.z; x[4 * j + 3] = v.w;
            }
            scl = scale[kb + brow];
            shf = shift[kb + brow];
            CP_WAIT(1);
        } else {
            CP_WAIT(0);
        }
        __syncthreads();

        const uint32_t sA = sb + buf * AST2;
        const uint32_t sB = sBbase + buf * BST2;
#pragma unroll
        for (int ks = 0; ks < 2; ks++) {
            const int k16 = ks * 16;
            uint32_t ah[2][4], al[2][4];
#pragma unroll
            for (int mi = 0; mi < 2; mi++) {
                uint32_t ad = sA + (wm + mi * 16 + (lane & 15)) * 80
                                 + (k16 + ((lane >> 4) << 3)) * 2;
                ldsm4(ah[mi][0], ah[mi][1], ah[mi][2], ah[mi][3], ad);
                ldsm4(al[mi][0], al[mi][1], al[mi][2], al[mi][3], ad + AT2);
            }
#pragma unroll
            for (int ng = 0; ng < 4; ng++) {
                uint32_t row = k16 + (lane & 7) + (lane & 8);
                uint32_t col = wn + ng * 16 + ((lane >> 4) << 3);
                uint32_t ad = sB + row * 272 + col * 2;
                uint32_t bh[4], bl[4];
                ldsm4t(bh[0], bh[1], bh[2], bh[3], ad);
                ldsm4t(bl[0], bl[1], bl[2], bl[3], ad + BT2);
#pragma unroll
                for (int mi = 0; mi < 2; mi++) {
                    mma16816(acc[mi][2 * ng],     ah[mi], bh);
                    mma16816(acc[mi][2 * ng],     ah[mi], bl);
                    mma16816(acc[mi][2 * ng],     al[mi], bh);
                    mma16816(acc[mi][2 * ng + 1], ah[mi], bh + 2);
                    mma16816(acc[mi][2 * ng + 1], ah[mi], bl + 2);
                    mma16816(acc[mi][2 * ng + 1], al[mi], bh + 2);
                }
            }
        }
        __syncthreads();
    }

    const int gq = lane >> 2, tq = lane & 3;
#pragma unroll
    for (int mi = 0; mi < 2; mi++) {
        int r0 = m0 + wm + mi * 16 + gq;
        float bv0 = bias[r0], bv1 = bias[r0 + 8];
        float* o0 = out + ((size_t)b * HH + r0) * NN;
        float* o1 = o0 + (size_t)8 * NN;
        float s0 = 0.f, q0 = 0.f, s1 = 0.f, q1 = 0.f;
#pragma unroll
        for (int ni = 0; ni < 8; ni++) {
            int cc = n0 + wn + ni * 8 + tq * 2;
            float y0 = acc[mi][ni][0] + bv0, y1 = acc[mi][ni][1] + bv0;
            float y2 = acc[mi][ni][2] + bv1, y3 = acc[mi][ni][3] + bv1;
            *(float2*)&o0[cc] = make_float2(y0, y1);
            *(float2*)&o1[cc] = make_float2(y2, y3);
            s0 += y0 + y1; q0 += y0 * y0 + y1 * y1;
            s1 += y2 + y3; q1 += y2 * y2 + y3 * y3;
        }
#pragma unroll
        for (int o = 1; o <= 2; o <<= 1) {
            s0 += __shfl_xor_sync(~0u, s0, o);
            q0 += __shfl_xor_sync(~0u, q0, o);
            s1 += __shfl_xor_sync(~0u, s1, o);
            q1 += __shfl_xor_sync(~0u, q1, o);
        }
        if (tq == 0) {
            atomicAdd(&g_sum1[r0], s0);     atomicAdd(&g_sq1[r0], q0);
            atomicAdd(&g_sum1[r0 + 8], s1); atomicAdd(&g_sq1[r0 + 8], q1);
        }
    }
}

// ---------------- stats finalize ----------------
__global__ void stats_final_kernel(const float* __restrict__ gsum,
                                   const float* __restrict__ gsq,
                                   const float* __restrict__ g,
                                   const float* __restrict__ be,
                                   float* __restrict__ scale,
                                   float* __restrict__ shift) {
    const int c = threadIdx.x;
    const float inv = 1.f / (float)(BB * NN);
    float m = gsum[c] * inv;
    float var = gsq[c] * inv - m * m;
    float sc = g[c] * rsqrtf(var + 1e-5f);
    scale[c] = sc;
    shift[c] = be[c] - m * sc;
}

__global__ void apply_bn_kernel(float* __restrict__ X) {
    const size_t total4 = (size_t)BB * HH * NN / 4;
    for (size_t i = (size_t)blockIdx.x * blockDim.x + threadIdx.x; i < total4;
         i += (size_t)gridDim.x * blockDim.x) {
        float4 v = ((float4*)X)[i];
        int c = (int)((i * 4) >> 13) & (HH - 1);
        float s = g_scale1[c], h = g_shift1[c];
        v.x = fmaxf(fmaf(v.x, s, h), 0.f);
        v.y = fmaxf(fmaf(v.y, s, h), 0.f);
        v.z = fmaxf(fmaf(v.z, s, h), 0.f);
        v.w = fmaxf(fmaf(v.w, s, h), 0.f);
        ((float4*)X)[i] = v;
    }
}

// ======================= launcher =======================
extern "C" void kernel_launch(void* const* d_in, const int* in_sizes, int n_in,
                              void* d_out, int out_size) {
    const float* xyz1    = (const float*)d_in[0];
    const float* xyz2    = (const float*)d_in[1];
    const float* points1 = (const float*)d_in[2];
    const float* points2 = (const float*)d_in[3];
    const float* w0 = (const float*)d_in[4];
    const float* b0 = (const float*)d_in[5];
    const float* g0 = (const float*)d_in[6];
    const float* be0 = (const float*)d_in[7];
    const float* w1 = (const float*)d_in[8];
    const float* b1 = (const float*)d_in[9];
    const float* g1 = (const float*)d_in[10];
    const float* be1 = (const float*)d_in[11];
    float* out = (float*)d_out;

    float *p_scale0, *p_shift0, *p_scale1, *p_shift1, *p_X0;
    float *p_sum0, *p_sq0, *p_sum1, *p_sq1;
    bf16 *p_W0hi, *p_W0lo, *p_W1hi, *p_W1lo, *p_FThi, *p_FTlo;
    cudaGetSymbolAddress((void**)&p_scale0, g_scale0);
    cudaGetSymbolAddress((void**)&p_shift0, g_shift0);
    cudaGetSymbolAddress((void**)&p_scale1, g_scale1);
    cudaGetSymbolAddress((void**)&p_shift1, g_shift1);
    cudaGetSymbolAddress((void**)&p_X0, g_X0);
    cudaGetSymbolAddress((void**)&p_sum0, g_sum0);
    cudaGetSymbolAddress((void**)&p_sq0, g_sq0);
    cudaGetSymbolAddress((void**)&p_sum1, g_sum1);
    cudaGetSymbolAddress((void**)&p_sq1, g_sq1);
    cudaGetSymbolAddress((void**)&p_W0hi, g_W0hi);
    cudaGetSymbolAddress((void**)&p_W0lo, g_W0lo);
    cudaGetSymbolAddress((void**)&p_W1hi, g_W1hi);
    cudaGetSymbolAddress((void**)&p_W1lo, g_W1lo);
    cudaGetSymbolAddress((void**)&p_FThi, g_FThi);
    cudaGetSymbolAddress((void**)&p_FTlo, g_FTlo);

    cudaFuncSetAttribute(hmma_gemm1, cudaFuncAttributeMaxDynamicSharedMemorySize, G1_SMEM);
    cudaFuncSetAttribute(hmma_gemm2, cudaFuncAttributeMaxDynamicSharedMemorySize, G2_SMEM);

    prep_kernel<<<NB_TOTAL, 256>>>(xyz1, xyz2, points1, points2, w0, w1);
    gather_kernel<<<BB * NN / 8, 256>>>();

    hmma_gemm1<<<dim3(HH / 128, NN / 128, BB), 256, G1_SMEM>>>(
        p_W0hi, p_W0lo, p_FThi, p_FTlo, b0, p_X0);
    stats_final_kernel<<<1, HH>>>(p_sum0, p_sq0, g0, be0, p_scale0, p_shift0);

    hmma_gemm2<<<dim3(HH / 128, NN / 128, BB), 256, G2_SMEM>>>(
        p_W1hi, p_W1lo, p_X0, p_scale0, p_shift0, b1, out);
    stats_final_kernel<<<1, HH>>>(p_sum1, p_sq1, g1, be1, p_scale1, p_shift1);
    apply_bn_kernel<<<4096, 256>>>(out);
}

// round 10
// speedup vs baseline: 1.5005x; 1.3000x over previous
#include <cuda_runtime.h>
#include <cuda_fp16.h>
#include <cstdint>

// Problem constants
#define BB 8
#define NN 8192
#define SS 2048
#define D1 256
#define D2 512
#define CIN 768
#define HH 512
#define WSCALE 256.0f
#define INV_WSCALE (1.0f / 256.0f)
#define INV_WSCALE2 (1.0f / 65536.0f)

typedef __half h16;

// ---------------- scratch (static device globals; no runtime alloc) ----------------
__device__ float g_P2T[(size_t)BB * SS * D2];
__device__ int   g_idx[(size_t)BB * NN * 3];
__device__ float g_wgt[(size_t)BB * NN * 3];
__device__ h16  g_FT[(size_t)BB * NN * CIN];           // single fp16
__device__ h16  g_W0hi[HH * CIN], g_W0lo[HH * CIN];    // fp16, scaled by 256
__device__ h16  g_W1hi[HH * HH],  g_W1lo[HH * HH];     // fp16, scaled by 256
__device__ float g_X0[(size_t)BB * HH * NN];           // (b, c, n), scaled by 256
__device__ float g_sum0[HH], g_sq0[HH], g_sum1[HH], g_sq1[HH];
__device__ float g_scale0[HH], g_shift0[HH], g_scale1[HH], g_shift1[HH];

// ======================= low-level helpers =======================
__device__ __forceinline__ uint32_t smem_u32(const void* p) {
    uint32_t a;
    asm("{ .reg .u64 t; cvta.to.shared.u64 t, %1; cvt.u32.u64 %0, t; }" : "=r"(a) : "l"(p));
    return a;
}
__device__ __forceinline__ void ldsm4(uint32_t& r0, uint32_t& r1, uint32_t& r2,
                                      uint32_t& r3, uint32_t a) {
    asm volatile("ldmatrix.sync.aligned.m8n8.x4.shared.b16 {%0,%1,%2,%3},[%4];"
                 : "=r"(r0), "=r"(r1), "=r"(r2), "=r"(r3) : "r"(a));
}
__device__ __forceinline__ void ldsm4t(uint32_t& r0, uint32_t& r1, uint32_t& r2,
                                       uint32_t& r3, uint32_t a) {
    asm volatile("ldmatrix.sync.aligned.m8n8.x4.trans.shared.b16 {%0,%1,%2,%3},[%4];"
                 : "=r"(r0), "=r"(r1), "=r"(r2), "=r"(r3) : "r"(a));
}
__device__ __forceinline__ void mma16816(float* d, const uint32_t* a, const uint32_t* b) {
    asm volatile(
        "mma.sync.aligned.m16n8k16.row.col.f32.f16.f16.f32 "
        "{%0,%1,%2,%3},{%4,%5,%6,%7},{%8,%9},{%0,%1,%2,%3};"
        : "+f"(d[0]), "+f"(d[1]), "+f"(d[2]), "+f"(d[3])
        : "r"(a[0]), "r"(a[1]), "r"(a[2]), "r"(a[3]), "r"(b[0]), "r"(b[1]));
}
__device__ __forceinline__ void cpa16(uint32_t dst, const void* src) {
    asm volatile("cp.async.cg.shared.global [%0],[%1],16;" :: "r"(dst), "l"(src));
}
#define CP_COMMIT() asm volatile("cp.async.commit_group;" ::: "memory")
#define CP_WAIT(n) asm volatile("cp.async.wait_group %0;" :: "n"(n) : "memory")

__device__ __forceinline__ void split_h(float v, h16& h, h16& l) {
    h = __float2half_rn(v);
    l = __float2half_rn(v - __half2float(h));
}
__device__ __forceinline__ uint32_t pack2h(h16 a, h16 b) {
    __half2 t = __halves2half2(a, b);
    return *reinterpret_cast<uint32_t*>(&t);
}

// ---------------- top-3 helper ----------------
struct Top3 { float d0, d1, d2; int i0, i1, i2; };
__device__ __forceinline__ void t3_ins(Top3& q, float t, int s) {
    if (t < q.d2) {
        if (t < q.d1) {
            q.d2 = q.d1; q.i2 = q.i1;
            if (t < q.d0) { q.d1 = q.d0; q.i1 = q.i0; q.d0 = t; q.i0 = s; }
            else          { q.d1 = t;    q.i1 = s; }
        } else { q.d2 = t; q.i2 = s; }
    }
}

// ======================= fused prep kernel =======================
#define NB_T3 128
#define NB_P2 8192
#define NB_P1 16384
#define NB_C0 (HH * CIN / 1024)
#define NB_C1 (HH * HH / 1024)
#define NB_TOTAL (NB_T3 + NB_P2 + NB_P1 + NB_C0 + NB_C1 + 1)

__global__ __launch_bounds__(256)
void prep_kernel(const float* __restrict__ xyz1, const float* __restrict__ xyz2,
                 const float* __restrict__ p1, const float* __restrict__ p2,
                 const float* __restrict__ w0g, const float* __restrict__ w1g) {
    __shared__ float sh[8192];
    int r = blockIdx.x;
    const int tid = threadIdx.x;

    if (r < NB_T3) {
        float* sx = sh;
        float* sy = sh + 2048;
        float* sz = sh + 4096;
        float* sn = sh + 6144;
        const int b = r >> 4;
        const int nbase = (r & 15) * 512;

        for (int i = tid; i < SS; i += 256) {
            float x = xyz2[((size_t)b * 3 + 0) * SS + i];
            float y = xyz2[((size_t)b * 3 + 1) * SS + i];
            float z = xyz2[((size_t)b * 3 + 2) * SS + i];
            sx[i] = x; sy[i] = y; sz[i] = z;
            sn[i] = x * x + y * y + z * z;
        }
        __syncthreads();

        const int na = nbase + tid;
        const int nb = nbase + 256 + tid;
        float xa = xyz1[((size_t)b * 3 + 0) * NN + na];
        float ya = xyz1[((size_t)b * 3 + 1) * NN + na];
        float za = xyz1[((size_t)b * 3 + 2) * NN + na];
        float xb = xyz1[((size_t)b * 3 + 0) * NN + nb];
        float yb = xyz1[((size_t)b * 3 + 1) * NN + nb];
        float zb = xyz1[((size_t)b * 3 + 2) * NN + nb];
        float n1a = xa * xa + ya * ya + za * za;
        float n1b = xb * xb + yb * yb + zb * zb;
        float mxa = -2.f * xa, mya = -2.f * ya, mza = -2.f * za;
        float mxb = -2.f * xb, myb = -2.f * yb, mzb = -2.f * zb;

        Top3 qa = {3.4e38f, 3.4e38f, 3.4e38f, 0, 0, 0};
        Top3 qb = {3.4e38f, 3.4e38f, 3.4e38f, 0, 0, 0};

        for (int s = 0; s < SS; s += 4) {
            float4 vx = ((float4*)sx)[s >> 2], vy = ((float4*)sy)[s >> 2];
            float4 vz = ((float4*)sz)[s >> 2], vn = ((float4*)sn)[s >> 2];
            float t;
            t = fmaf(mxa, vx.x, vn.x); t = fmaf(mya, vy.x, t); t = fmaf(mza, vz.x, t); t3_ins(qa, t, s + 0);
            t = fmaf(mxa, vx.y, vn.y); t = fmaf(mya, vy.y, t); t = fmaf(mza, vz.y, t); t3_ins(qa, t, s + 1);
            t = fmaf(mxa, vx.z, vn.z); t = fmaf(mya, vy.z, t); t = fmaf(mza, vz.z, t); t3_ins(qa, t, s + 2);
            t = fmaf(mxa, vx.w, vn.w); t = fmaf(mya, vy.w, t); t = fmaf(mza, vz.w, t); t3_ins(qa, t, s + 3);
            t = fmaf(mxb, vx.x, vn.x); t = fmaf(myb, vy.x, t); t = fmaf(mzb, vz.x, t); t3_ins(qb, t, s + 0);
            t = fmaf(mxb, vx.y, vn.y); t = fmaf(myb, vy.y, t); t = fmaf(mzb, vz.y, t); t3_ins(qb, t, s + 1);
            t = fmaf(mxb, vx.z, vn.z); t = fmaf(myb, vy.z, t); t = fmaf(mzb, vz.z, t); t3_ins(qb, t, s + 2);
            t = fmaf(mxb, vx.w, vn.w); t = fmaf(myb, vy.w, t); t = fmaf(mzb, vz.w, t); t3_ins(qb, t, s + 3);
        }

        {
            size_t base = ((size_t)b * NN + na) * 3;
            float d0 = qa.d0 + n1a, d1 = qa.d1 + n1a, d2 = qa.d2 + n1a;
            float w0 = 1.0f / (d0 + 1e-8f), w1 = 1.0f / (d1 + 1e-8f), w2 = 1.0f / (d2 + 1e-8f);
            float inv = 1.0f / (w0 + w1 + w2);
            g_idx[base + 0] = qa.i0; g_idx[base + 1] = qa.i1; g_idx[base + 2] = qa.i2;
            g_wgt[base + 0] = w0 * inv; g_wgt[base + 1] = w1 * inv; g_wgt[base + 2] = w2 * inv;
        }
        {
            size_t base = ((size_t)b * NN + nb) * 3;
            float d0 = qb.d0 + n1b, d1 = qb.d1 + n1b, d2 = qb.d2 + n1b;
            float w0 = 1.0f / (d0 + 1e-8f), w1 = 1.0f / (d1 + 1e-8f), w2 = 1.0f / (d2 + 1e-8f);
            float inv = 1.0f / (w0 + w1 + w2);
            g_idx[base + 0] = qb.i0; g_idx[base + 1] = qb.i1; g_idx[base + 2] = qb.i2;
            g_wgt[base + 0] = w0 * inv; g_wgt[base + 1] = w1 * inv; g_wgt[base + 2] = w2 * inv;
        }
        return;
    }
    r -= NB_T3;
    if (r < NB_P2) {
        int b = r >> 10, y = (r >> 6) & 15, x = r & 63;
        int c0 = y * 32, s0 = x * 32;
        int tx = tid & 31, ty = tid >> 5;
        float (*t)[33] = (float(*)[33])sh;
#pragma unroll
        for (int j = ty; j < 32; j += 8)
            t[j][tx] = p2[((size_t)b * D2 + c0 + j) * SS + s0 + tx];
        __syncthreads();
#pragma unroll
        for (int j = ty; j < 32; j += 8)
            g_P2T[((size_t)b * SS + s0 + j) * D2 + c0 + tx] = t[tx][j];
        return;
    }
    r -= NB_P2;
    if (r < NB_P1) {
        int b = r >> 11, y = (r >> 8) & 7, x = r & 255;
        int c0 = y * 32, n0 = x * 32;
        int tx = tid & 31, ty = tid >> 5;
        float (*t)[33] = (float(*)[33])sh;
#pragma unroll
        for (int j = ty; j < 32; j += 8)
            t[j][tx] = p1[((size_t)b * D1 + c0 + j) * NN + n0 + tx];
        __syncthreads();
#pragma unroll
        for (int j = ty; j < 32; j += 8) {
            size_t off = ((size_t)b * NN + n0 + j) * CIN + c0 + tx;
            g_FT[off] = __float2half_rn(t[tx][j]);
        }
        return;
    }
    r -= NB_P1;
    if (r < NB_C0 + NB_C1) {
        // ---- weight split to fp16 hi/lo, scaled by 256 ----
        const float* src;
        h16 *hi, *lo;
        int i;
        if (r < NB_C0) { src = w0g; hi = g_W0hi; lo = g_W0lo; i = r * 1024 + tid * 4; }
        else { src = w1g; hi = g_W1hi; lo = g_W1lo; i = (r - NB_C0) * 1024 + tid * 4; }
        float4 v = *(const float4*)(src + i);
        h16 h0, l0, h1, l1, h2, l2, h3, l3;
        split_h(v.x * WSCALE, h0, l0); split_h(v.y * WSCALE, h1, l1);
        split_h(v.z * WSCALE, h2, l2); split_h(v.w * WSCALE, h3, l3);
        *(uint2*)&hi[i] = make_uint2(pack2h(h0, h1), pack2h(h2, h3));
        *(uint2*)&lo[i] = make_uint2(pack2h(l0, l1), pack2h(l2, l3));
        return;
    }
    if (tid < 256) {
        g_sum0[tid] = 0.f; g_sum0[tid + 256] = 0.f;
        g_sq0[tid] = 0.f;  g_sq0[tid + 256] = 0.f;
        g_sum1[tid] = 0.f; g_sum1[tid + 256] = 0.f;
        g_sq1[tid] = 0.f;  g_sq1[tid + 256] = 0.f;
    }
}

// ---------------- gather + interpolate -> g_FT[:, :, 256:768] (fp16) ----------------
__global__ void gather_kernel() {
    int wglob = blockIdx.x * 8 + (threadIdx.x >> 5);
    int lane = threadIdx.x & 31;
    int b = wglob / NN;
    size_t base = (size_t)wglob * 3;
    int i0 = g_idx[base + 0], i1 = g_idx[base + 1], i2 = g_idx[base + 2];
    float w0 = g_wgt[base + 0], w1 = g_wgt[base + 1], w2 = g_wgt[base + 2];
    const float* r0 = g_P2T + ((size_t)b * SS + i0) * D2;
    const float* r1 = g_P2T + ((size_t)b * SS + i1) * D2;
    const float* r2 = g_P2T + ((size_t)b * SS + i2) * D2;
    size_t dbase = (size_t)wglob * CIN + D1;
#pragma unroll
    for (int c = lane * 4; c < D2; c += 128) {
        float4 v0 = *(const float4*)&r0[c];
        float4 v1 = *(const float4*)&r1[c];
        float4 v2 = *(const float4*)&r2[c];
        float o0 = w0 * v0.x + w1 * v1.x + w2 * v2.x;
        float o1 = w0 * v0.y + w1 * v1.y + w2 * v2.y;
        float o2 = w0 * v0.z + w1 * v1.z + w2 * v2.z;
        float o3 = w0 * v0.w + w1 * v1.w + w2 * v2.w;
        *(uint2*)&g_FT[dbase + c] = make_uint2(
            pack2h(__float2half_rn(o0), __float2half_rn(o1)),
            pack2h(__float2half_rn(o2), __float2half_rn(o3)));
    }
}

// ======================= HMMA GEMM 1 (fp16 A-split/B-single) =======================
#define T1 10240                          // bytes per tile (128 rows x 80B)
#define ST1 (3 * T1)                      // stage: Ahi, Alo, B = 30720
static constexpr int G1_SMEM = 2 * ST1;   // 61440 -> 2 CTAs/SM

__global__ __launch_bounds__(256, 2)
void hmma_gemm1(const h16* __restrict__ Ahi, const h16* __restrict__ Alo,
                const h16* __restrict__ Bg,
                const float* __restrict__ bias, float* __restrict__ out) {
    extern __shared__ char smem[];
    const uint32_t sb = smem_u32(smem);
    const int tid = threadIdx.x, lane = tid & 31, wid = tid >> 5;
    const int m0 = blockIdx.x * 128, n0 = blockIdx.y * 128, b = blockIdx.z;
    const int wm = (wid & 3) * 32, wn = (wid >> 2) * 64;

    const h16* Arow_hi = Ahi + (size_t)m0 * CIN;
    const h16* Arow_lo = Alo + (size_t)m0 * CIN;
    const h16* Brow = Bg + ((size_t)b * NN + n0) * CIN;

    float acc[2][8][4];
#pragma unroll
    for (int i = 0; i < 2; i++)
#pragma unroll
        for (int j = 0; j < 8; j++)
#pragma unroll
            for (int q = 0; q < 4; q++) acc[i][j][q] = 0.f;

    const int row_l = tid >> 2, c16 = (tid & 3);
    auto issue = [&](int kb, uint32_t sbuf) {
#pragma unroll
        for (int t = 0; t < 2; t++) {
            int row = row_l + t * 64;
            uint32_t d = sbuf + row * 80 + c16 * 16;
            cpa16(d,          Arow_hi + (size_t)row * CIN + kb + c16 * 8);
            cpa16(d + T1,     Arow_lo + (size_t)row * CIN + kb + c16 * 8);
            cpa16(d + 2 * T1, Brow + (size_t)row * CIN + kb + c16 * 8);
        }
        CP_COMMIT();
    };

    const int KT = CIN / 32;   // 24
    issue(0, sb);

    for (int c = 0; c < KT; c++) {
        const int buf = c & 1;
        if (c + 1 < KT) {
            issue((c + 1) * 32, sb + (buf ^ 1) * ST1);
            CP_WAIT(1);
        } else {
            CP_WAIT(0);
        }
        __syncthreads();

        const uint32_t sA = sb + buf * ST1;
        const uint32_t sB = sA + 2 * T1;
#pragma unroll
        for (int ks = 0; ks < 2; ks++) {
            const int k16 = ks * 16;
            uint32_t ah[2][4], al[2][4];
#pragma unroll
            for (int mi = 0; mi < 2; mi++) {
                uint32_t ad = sA + (wm + mi * 16 + (lane & 15)) * 80
                                 + (k16 + ((lane >> 4) << 3)) * 2;
                ldsm4(ah[mi][0], ah[mi][1], ah[mi][2], ah[mi][3], ad);
                ldsm4(al[mi][0], al[mi][1], al[mi][2], al[mi][3], ad + T1);
            }
#pragma unroll
            for (int ng = 0; ng < 4; ng++) {
                uint32_t row = wn + ng * 16 + (lane & 7) + ((lane & 16) >> 1);
                uint32_t col = k16 + (lane & 8);
                uint32_t ad = sB + row * 80 + col * 2;
                uint32_t bh[4];
                ldsm4(bh[0], bh[1], bh[2], bh[3], ad);
#pragma unroll
                for (int mi = 0; mi < 2; mi++) {
                    mma16816(acc[mi][2 * ng],     ah[mi], bh);
                    mma16816(acc[mi][2 * ng],     al[mi], bh);
                    mma16816(acc[mi][2 * ng + 1], ah[mi], bh + 2);
                    mma16816(acc[mi][2 * ng + 1], al[mi], bh + 2);
                }
            }
        }
        __syncthreads();
    }

    // epilogue -> out (b, m, n) + 256*bias, fused channel stats (scaled)
    const int gq = lane >> 2, tq = lane & 3;
#pragma unroll
    for (int mi = 0; mi < 2; mi++) {
        int r0 = m0 + wm + mi * 16 + gq;
        float bv0 = bias[r0] * WSCALE, bv1 = bias[r0 + 8] * WSCALE;
        float* o0 = out + ((size_t)b * HH + r0) * NN;
        float* o1 = o0 + (size_t)8 * NN;
        float s0 = 0.f, q0 = 0.f, s1 = 0.f, q1 = 0.f;
#pragma unroll
        for (int ni = 0; ni < 8; ni++) {
            int cc = n0 + wn + ni * 8 + tq * 2;
            float y0 = acc[mi][ni][0] + bv0, y1 = acc[mi][ni][1] + bv0;
            float y2 = acc[mi][ni][2] + bv1, y3 = acc[mi][ni][3] + bv1;
            *(float2*)&o0[cc] = make_float2(y0, y1);
            *(float2*)&o1[cc] = make_float2(y2, y3);
            s0 += y0 + y1; q0 += y0 * y0 + y1 * y1;
            s1 += y2 + y3; q1 += y2 * y2 + y3 * y3;
        }
#pragma unroll
        for (int o = 1; o <= 2; o <<= 1) {
            s0 += __shfl_xor_sync(~0u, s0, o);
            q0 += __shfl_xor_sync(~0u, q0, o);
            s1 += __shfl_xor_sync(~0u, s1, o);
            q1 += __shfl_xor_sync(~0u, q1, o);
        }
        if (tq == 0) {
            atomicAdd(&g_sum0[r0], s0);     atomicAdd(&g_sq0[r0], q0);
            atomicAdd(&g_sum0[r0 + 8], s1); atomicAdd(&g_sq0[r0 + 8], q1);
        }
    }
}

// ======================= HMMA GEMM 2 (fp16, fused BN+ReLU on B) =======================
#define AT2 10240
#define AST2 (2 * AT2)           // A stage: hi+lo
#define BT2 8704                 // 32 * 272, single fp16
static constexpr int G2_SMEM = 2 * AST2 + 2 * BT2;  // 58368

__global__ __launch_bounds__(256, 2)
void hmma_gemm2(const h16* __restrict__ Ahi, const h16* __restrict__ Alo,
                const float* __restrict__ X0,
                const float* __restrict__ scale, const float* __restrict__ shift,
                const float* __restrict__ bias, float* __restrict__ out) {
    extern __shared__ char smem[];
    const uint32_t sb = smem_u32(smem);
    const int tid = threadIdx.x, lane = tid & 31, wid = tid >> 5;
    const int m0 = blockIdx.x * 128, n0 = blockIdx.y * 128, b = blockIdx.z;
    const int wm = (wid & 3) * 32, wn = (wid >> 2) * 64;

    const h16* Arow_hi = Ahi + (size_t)m0 * HH;
    const h16* Arow_lo = Alo + (size_t)m0 * HH;
    const float* Xb = X0 + (size_t)b * HH * NN + n0;

    float acc[2][8][4];
#pragma unroll
    for (int i = 0; i < 2; i++)
#pragma unroll
        for (int j = 0; j < 8; j++)
#pragma unroll
            for (int q = 0; q < 4; q++) acc[i][j][q] = 0.f;

    const int brow = tid >> 3, bcol = (tid & 7) * 16;
    float x[16];
    float scl, shf;

    const int row_l = tid >> 2, c16 = (tid & 3);
    {
#pragma unroll
        for (int t = 0; t < 2; t++) {
            int row = row_l + t * 64;
            uint32_t d = sb + row * 80 + c16 * 16;
            cpa16(d,       Arow_hi + (size_t)row * HH + c16 * 8);
            cpa16(d + AT2, Arow_lo + (size_t)row * HH + c16 * 8);
        }
        CP_COMMIT();
        const float* src = Xb + (size_t)brow * NN + bcol;
#pragma unroll
        for (int j = 0; j < 4; j++) {
            float4 v = *(const float4*)(src + j * 4);
            x[4 * j] = v.x; x[4 * j + 1] = v.y; x[4 * j + 2] = v.z; x[4 * j + 3] = v.w;
        }
        scl = scale[brow];
        shf = shift[brow];
    }

    const uint32_t sBoff = 2 * AST2;
    const int KT = HH / 32;  // 16
    for (int c = 0; c < KT; c++) {
        const int buf = c & 1;
        {
            uint32_t doff = sBoff + buf * BT2 + brow * 272 + bcol * 2;
#pragma unroll
            for (int j = 0; j < 4; j++) {
                float y0 = fmaxf(fmaf(x[4 * j + 0], scl, shf), 0.f);
                float y1 = fmaxf(fmaf(x[4 * j + 1], scl, shf), 0.f);
                float y2 = fmaxf(fmaf(x[4 * j + 2], scl, shf), 0.f);
                float y3 = fmaxf(fmaf(x[4 * j + 3], scl, shf), 0.f);
                *(uint2*)(smem + doff + j * 8) = make_uint2(
                    pack2h(__float2half_rn(y0), __float2half_rn(y1)),
                    pack2h(__float2half_rn(y2), __float2half_rn(y3)));
            }
        }
        if (c + 1 < KT) {
            const int kb = (c + 1) * 32;
            const uint32_t s2 = sb + (buf ^ 1) * AST2;
#pragma unroll
            for (int t = 0; t < 2; t++) {
                int row = row_l + t * 64;
                uint32_t d = s2 + row * 80 + c16 * 16;
                cpa16(d,       Arow_hi + (size_t)row * HH + kb + c16 * 8);
                cpa16(d + AT2, Arow_lo + (size_t)row * HH + kb + c16 * 8);
            }
            CP_COMMIT();
            const float* src = Xb + (size_t)(kb + brow) * NN + bcol;
#pragma unroll
            for (int j = 0; j < 4; j++) {
                float4 v = *(const float4*)(src + j * 4);
                x[4 * j] = v.x; x[4 * j + 1] = v.y; x[4 * j + 2] = v.z; x[4 * j + 3] = v.w;
            }
            scl = scale[kb + brow];
            shf = shift[kb + brow];
            CP_WAIT(1);
        } else {
            CP_WAIT(0);
        }
        __syncthreads();

        const uint32_t sA = sb + buf * AST2;
        const uint32_t sB = sb + sBoff + buf * BT2;
#pragma unroll
        for (int ks = 0; ks < 2; ks++) {
            const int k16 = ks * 16;
            uint32_t ah[2][4], al[2][4];
#pragma unroll
            for (int mi = 0; mi < 2; mi++) {
                uint32_t ad = sA + (wm + mi * 16 + (lane & 15)) * 80
                                 + (k16 + ((lane >> 4) << 3)) * 2;
                ldsm4(ah[mi][0], ah[mi][1], ah[mi][2], ah[mi][3], ad);
                ldsm4(al[mi][0], al[mi][1], al[mi][2], al[mi][3], ad + AT2);
            }
#pragma unroll
            for (int ng = 0; ng < 4; ng++) {
                uint32_t row = k16 + (lane & 7) + (lane & 8);
                uint32_t col = wn + ng * 16 + ((lane >> 4) << 3);
                uint32_t ad = sB + row * 272 + col * 2;
                uint32_t bh[4];
                ldsm4t(bh[0], bh[1], bh[2], bh[3], ad);
#pragma unroll
                for (int mi = 0; mi < 2; mi++) {
                    mma16816(acc[mi][2 * ng],     ah[mi], bh);
                    mma16816(acc[mi][2 * ng],     al[mi], bh);
                    mma16816(acc[mi][2 * ng + 1], ah[mi], bh + 2);
                    mma16816(acc[mi][2 * ng + 1], al[mi], bh + 2);
                }
            }
        }
        __syncthreads();
    }

    const int gq = lane >> 2, tq = lane & 3;
#pragma unroll
    for (int mi = 0; mi < 2; mi++) {
        int r0 = m0 + wm + mi * 16 + gq;
        float bv0 = bias[r0] * WSCALE, bv1 = bias[r0 + 8] * WSCALE;
        float* o0 = out + ((size_t)b * HH + r0) * NN;
        float* o1 = o0 + (size_t)8 * NN;
        float s0 = 0.f, q0 = 0.f, s1 = 0.f, q1 = 0.f;
#pragma unroll
        for (int ni = 0; ni < 8; ni++) {
            int cc = n0 + wn + ni * 8 + tq * 2;
            float y0 = acc[mi][ni][0] + bv0, y1 = acc[mi][ni][1] + bv0;
            float y2 = acc[mi][ni][2] + bv1, y3 = acc[mi][ni][3] + bv1;
            *(float2*)&o0[cc] = make_float2(y0, y1);
            *(float2*)&o1[cc] = make_float2(y2, y3);
            s0 += y0 + y1; q0 += y0 * y0 + y1 * y1;
            s1 += y2 + y3; q1 += y2 * y2 + y3 * y3;
        }
#pragma unroll
        for (int o = 1; o <= 2; o <<= 1) {
            s0 += __shfl_xor_sync(~0u, s0, o);
            q0 += __shfl_xor_sync(~0u, q0, o);
            s1 += __shfl_xor_sync(~0u, s1, o);
            q1 += __shfl_xor_sync(~0u, q1, o);
        }
        if (tq == 0) {
            atomicAdd(&g_sum1[r0], s0);     atomicAdd(&g_sq1[r0], q0);
            atomicAdd(&g_sum1[r0 + 8], s1); atomicAdd(&g_sq1[r0 + 8], q1);
        }
    }
}

// ---------------- stats finalize (accounts for 256x scaling of z) ----------------
__global__ void stats_final_kernel(const float* __restrict__ gsum,
                                   const float* __restrict__ gsq,
                                   const float* __restrict__ g,
                                   const float* __restrict__ be,
                                   float* __restrict__ scale,
                                   float* __restrict__ shift) {
    const int c = threadIdx.x;
    const float inv = 1.f / (float)(BB * NN);
    float m = gsum[c] * inv * INV_WSCALE;              // true mean
    float ex2 = gsq[c] * inv * INV_WSCALE2;            // true E[z^2]
    float var = ex2 - m * m;                           // true var (+ true eps below)
    float sc = g[c] * rsqrtf(var + 1e-5f);
    scale[c] = sc * INV_WSCALE;                        // applied to SCALED z
    shift[c] = be[c] - m * sc;
}

__global__ void apply_bn_kernel(float* __restrict__ X) {
    const size_t total4 = (size_t)BB * HH * NN / 4;
    for (size_t i = (size_t)blockIdx.x * blockDim.x + threadIdx.x; i < total4;
         i += (size_t)gridDim.x * blockDim.x) {
        float4 v = ((float4*)X)[i];
        int c = (int)((i * 4) >> 13) & (HH - 1);
        float s = g_scale1[c], h = g_shift1[c];
        v.x = fmaxf(fmaf(v.x, s, h), 0.f);
        v.y = fmaxf(fmaf(v.y, s, h), 0.f);
        v.z = fmaxf(fmaf(v.z, s, h), 0.f);
        v.w = fmaxf(fmaf(v.w, s, h), 0.f);
        ((float4*)X)[i] = v;
    }
}

// ======================= launcher =======================
extern "C" void kernel_launch(void* const* d_in, const int* in_sizes, int n_in,
                              void* d_out, int out_size) {
    const float* xyz1    = (const float*)d_in[0];
    const float* xyz2    = (const float*)d_in[1];
    const float* points1 = (const float*)d_in[2];
    const float* points2 = (const float*)d_in[3];
    const float* w0 = (const float*)d_in[4];
    const float* b0 = (const float*)d_in[5];
    const float* g0 = (const float*)d_in[6];
    const float* be0 = (const float*)d_in[7];
    const float* w1 = (const float*)d_in[8];
    const float* b1 = (const float*)d_in[9];
    const float* g1 = (const float*)d_in[10];
    const float* be1 = (const float*)d_in[11];
    float* out = (float*)d_out;

    float *p_scale0, *p_shift0, *p_scale1, *p_shift1, *p_X0;
    float *p_sum0, *p_sq0, *p_sum1, *p_sq1;
    h16 *p_W0hi, *p_W0lo, *p_W1hi, *p_W1lo, *p_FT;
    cudaGetSymbolAddress((void**)&p_scale0, g_scale0);
    cudaGetSymbolAddress((void**)&p_shift0, g_shift0);
    cudaGetSymbolAddress((void**)&p_scale1, g_scale1);
    cudaGetSymbolAddress((void**)&p_shift1, g_shift1);
    cudaGetSymbolAddress((void**)&p_X0, g_X0);
    cudaGetSymbolAddress((void**)&p_sum0, g_sum0);
    cudaGetSymbolAddress((void**)&p_sq0, g_sq0);
    cudaGetSymbolAddress((void**)&p_sum1, g_sum1);
    cudaGetSymbolAddress((void**)&p_sq1, g_sq1);
    cudaGetSymbolAddress((void**)&p_W0hi, g_W0hi);
    cudaGetSymbolAddress((void**)&p_W0lo, g_W0lo);
    cudaGetSymbolAddress((void**)&p_W1hi, g_W1hi);
    cudaGetSymbolAddress((void**)&p_W1lo, g_W1lo);
    cudaGetSymbolAddress((void**)&p_FT, g_FT);

    cudaFuncSetAttribute(hmma_gemm1, cudaFuncAttributeMaxDynamicSharedMemorySize, G1_SMEM);
    cudaFuncSetAttribute(hmma_gemm2, cudaFuncAttributeMaxDynamicSharedMemorySize, G2_SMEM);

    prep_kernel<<<NB_TOTAL, 256>>>(xyz1, xyz2, points1, points2, w0, w1);
    gather_kernel<<<BB * NN / 8, 256>>>();

    hmma_gemm1<<<dim3(HH / 128, NN / 128, BB), 256, G1_SMEM>>>(
        p_W0hi, p_W0lo, p_FT, b0, p_X0);
    stats_final_kernel<<<1, HH>>>(p_sum0, p_sq0, g0, be0, p_scale0, p_shift0);

    hmma_gemm2<<<dim3(HH / 128, NN / 128, BB), 256, G2_SMEM>>>(
        p_W1hi, p_W1lo, p_X0, p_scale0, p_shift0, b1, out);
    stats_final_kernel<<<1, HH>>>(p_sum1, p_sq1, g1, be1, p_scale1, p_shift1);
    apply_bn_kernel<<<4096, 256>>>(out);
}

// round 11
// speedup vs baseline: 1.9544x; 1.3024x over previous
#include <cuda_runtime.h>
#include <cuda_fp16.h>
#include <cstdint>

// Problem constants
#define BB 8
#define NN 8192
#define SS 2048
#define D1 256
#define D2 512
#define CIN 768
#define HH 512

typedef __half h16;

// ---------------- scratch (static device globals; no runtime alloc) ----------------
__device__ float g_P2T[(size_t)BB * SS * D2];
__device__ int   g_idx[(size_t)BB * NN * 3];
__device__ float g_wgt[(size_t)BB * NN * 3];
__device__ h16  g_FT[(size_t)BB * NN * CIN];           // single fp16
__device__ h16  g_W0[HH * CIN];                        // single fp16
__device__ h16  g_W1[HH * HH];                         // single fp16
__device__ float g_X0[(size_t)BB * HH * NN];           // (b, c, n)
__device__ float g_sum0[HH], g_sq0[HH], g_sum1[HH], g_sq1[HH];
__device__ float g_scale0[HH], g_shift0[HH], g_scale1[HH], g_shift1[HH];

// ======================= low-level helpers =======================
__device__ __forceinline__ uint32_t smem_u32(const void* p) {
    uint32_t a;
    asm("{ .reg .u64 t; cvta.to.shared.u64 t, %1; cvt.u32.u64 %0, t; }" : "=r"(a) : "l"(p));
    return a;
}
__device__ __forceinline__ void ldsm4(uint32_t& r0, uint32_t& r1, uint32_t& r2,
                                      uint32_t& r3, uint32_t a) {
    asm volatile("ldmatrix.sync.aligned.m8n8.x4.shared.b16 {%0,%1,%2,%3},[%4];"
                 : "=r"(r0), "=r"(r1), "=r"(r2), "=r"(r3) : "r"(a));
}
__device__ __forceinline__ void ldsm4t(uint32_t& r0, uint32_t& r1, uint32_t& r2,
                                       uint32_t& r3, uint32_t a) {
    asm volatile("ldmatrix.sync.aligned.m8n8.x4.trans.shared.b16 {%0,%1,%2,%3},[%4];"
                 : "=r"(r0), "=r"(r1), "=r"(r2), "=r"(r3) : "r"(a));
}
__device__ __forceinline__ void mma16816(float* d, const uint32_t* a, const uint32_t* b) {
    asm volatile(
        "mma.sync.aligned.m16n8k16.row.col.f32.f16.f16.f32 "
        "{%0,%1,%2,%3},{%4,%5,%6,%7},{%8,%9},{%0,%1,%2,%3};"
        : "+f"(d[0]), "+f"(d[1]), "+f"(d[2]), "+f"(d[3])
        : "r"(a[0]), "r"(a[1]), "r"(a[2]), "r"(a[3]), "r"(b[0]), "r"(b[1]));
}
__device__ __forceinline__ void cpa16(uint32_t dst, const void* src) {
    asm volatile("cp.async.cg.shared.global [%0],[%1],16;" :: "r"(dst), "l"(src));
}
#define CP_COMMIT() asm volatile("cp.async.commit_group;" ::: "memory")
#define CP_WAIT(n) asm volatile("cp.async.wait_group %0;" :: "n"(n) : "memory")

__device__ __forceinline__ uint32_t pack2h(h16 a, h16 b) {
    __half2 t = __halves2half2(a, b);
    return *reinterpret_cast<uint32_t*>(&t);
}

// ---------------- top-3 helper ----------------
struct Top3 { float d0, d1, d2; int i0, i1, i2; };
__device__ __forceinline__ void t3_ins(Top3& q, float t, int s) {
    if (t < q.d2) {
        if (t < q.d1) {
            q.d2 = q.d1; q.i2 = q.i1;
            if (t < q.d0) { q.d1 = q.d0; q.i1 = q.i0; q.d0 = t; q.i0 = s; }
            else          { q.d1 = t;    q.i1 = s; }
        } else { q.d2 = t; q.i2 = s; }
    }
}

// ======================= fused prep kernel =======================
#define NB_T3 128
#define NB_P2 8192
#define NB_P1 16384
#define NB_C0 (HH * CIN / 1024)
#define NB_C1 (HH * HH / 1024)
#define NB_TOTAL (NB_T3 + NB_P2 + NB_P1 + NB_C0 + NB_C1 + 1)

__global__ __launch_bounds__(256)
void prep_kernel(const float* __restrict__ xyz1, const float* __restrict__ xyz2,
                 const float* __restrict__ p1, const float* __restrict__ p2,
                 const float* __restrict__ w0g, const float* __restrict__ w1g) {
    __shared__ float sh[8192];
    int r = blockIdx.x;
    const int tid = threadIdx.x;

    if (r < NB_T3) {
        float* sx = sh;
        float* sy = sh + 2048;
        float* sz = sh + 4096;
        float* sn = sh + 6144;
        const int b = r >> 4;
        const int nbase = (r & 15) * 512;

        for (int i = tid; i < SS; i += 256) {
            float x = xyz2[((size_t)b * 3 + 0) * SS + i];
            float y = xyz2[((size_t)b * 3 + 1) * SS + i];
            float z = xyz2[((size_t)b * 3 + 2) * SS + i];
            sx[i] = x; sy[i] = y; sz[i] = z;
            sn[i] = x * x + y * y + z * z;
        }
        __syncthreads();

        const int na = nbase + tid;
        const int nb = nbase + 256 + tid;
        float xa = xyz1[((size_t)b * 3 + 0) * NN + na];
        float ya = xyz1[((size_t)b * 3 + 1) * NN + na];
        float za = xyz1[((size_t)b * 3 + 2) * NN + na];
        float xb = xyz1[((size_t)b * 3 + 0) * NN + nb];
        float yb = xyz1[((size_t)b * 3 + 1) * NN + nb];
        float zb = xyz1[((size_t)b * 3 + 2) * NN + nb];
        float n1a = xa * xa + ya * ya + za * za;
        float n1b = xb * xb + yb * yb + zb * zb;
        float mxa = -2.f * xa, mya = -2.f * ya, mza = -2.f * za;
        float mxb = -2.f * xb, myb = -2.f * yb, mzb = -2.f * zb;

        Top3 qa = {3.4e38f, 3.4e38f, 3.4e38f, 0, 0, 0};
        Top3 qb = {3.4e38f, 3.4e38f, 3.4e38f, 0, 0, 0};

        for (int s = 0; s < SS; s += 4) {
            float4 vx = ((float4*)sx)[s >> 2], vy = ((float4*)sy)[s >> 2];
            float4 vz = ((float4*)sz)[s >> 2], vn = ((float4*)sn)[s >> 2];
            float t;
            t = fmaf(mxa, vx.x, vn.x); t = fmaf(mya, vy.x, t); t = fmaf(mza, vz.x, t); t3_ins(qa, t, s + 0);
            t = fmaf(mxa, vx.y, vn.y); t = fmaf(mya, vy.y, t); t = fmaf(mza, vz.y, t); t3_ins(qa, t, s + 1);
            t = fmaf(mxa, vx.z, vn.z); t = fmaf(mya, vy.z, t); t = fmaf(mza, vz.z, t); t3_ins(qa, t, s + 2);
            t = fmaf(mxa, vx.w, vn.w); t = fmaf(mya, vy.w, t); t = fmaf(mza, vz.w, t); t3_ins(qa, t, s + 3);
            t = fmaf(mxb, vx.x, vn.x); t = fmaf(myb, vy.x, t); t = fmaf(mzb, vz.x, t); t3_ins(qb, t, s + 0);
            t = fmaf(mxb, vx.y, vn.y); t = fmaf(myb, vy.y, t); t = fmaf(mzb, vz.y, t); t3_ins(qb, t, s + 1);
            t = fmaf(mxb, vx.z, vn.z); t = fmaf(myb, vy.z, t); t = fmaf(mzb, vz.z, t); t3_ins(qb, t, s + 2);
            t = fmaf(mxb, vx.w, vn.w); t = fmaf(myb, vy.w, t); t = fmaf(mzb, vz.w, t); t3_ins(qb, t, s + 3);
        }

        {
            size_t base = ((size_t)b * NN + na) * 3;
            float d0 = qa.d0 + n1a, d1 = qa.d1 + n1a, d2 = qa.d2 + n1a;
            float w0 = 1.0f / (d0 + 1e-8f), w1 = 1.0f / (d1 + 1e-8f), w2 = 1.0f / (d2 + 1e-8f);
            float inv = 1.0f / (w0 + w1 + w2);
            g_idx[base + 0] = qa.i0; g_idx[base + 1] = qa.i1; g_idx[base + 2] = qa.i2;
            g_wgt[base + 0] = w0 * inv; g_wgt[base + 1] = w1 * inv; g_wgt[base + 2] = w2 * inv;
        }
        {
            size_t base = ((size_t)b * NN + nb) * 3;
            float d0 = qb.d0 + n1b, d1 = qb.d1 + n1b, d2 = qb.d2 + n1b;
            float w0 = 1.0f / (d0 + 1e-8f), w1 = 1.0f / (d1 + 1e-8f), w2 = 1.0f / (d2 + 1e-8f);
            float inv = 1.0f / (w0 + w1 + w2);
            g_idx[base + 0] = qb.i0; g_idx[base + 1] = qb.i1; g_idx[base + 2] = qb.i2;
            g_wgt[base + 0] = w0 * inv; g_wgt[base + 1] = w1 * inv; g_wgt[base + 2] = w2 * inv;
        }
        return;
    }
    r -= NB_T3;
    if (r < NB_P2) {
        int b = r >> 10, y = (r >> 6) & 15, x = r & 63;
        int c0 = y * 32, s0 = x * 32;
        int tx = tid & 31, ty = tid >> 5;
        float (*t)[33] = (float(*)[33])sh;
#pragma unroll
        for (int j = ty; j < 32; j += 8)
            t[j][tx] = p2[((size_t)b * D2 + c0 + j) * SS + s0 + tx];
        __syncthreads();
#pragma unroll
        for (int j = ty; j < 32; j += 8)
            g_P2T[((size_t)b * SS + s0 + j) * D2 + c0 + tx] = t[tx][j];
        return;
    }
    r -= NB_P2;
    if (r < NB_P1) {
        int b = r >> 11, y = (r >> 8) & 7, x = r & 255;
        int c0 = y * 32, n0 = x * 32;
        int tx = tid & 31, ty = tid >> 5;
        float (*t)[33] = (float(*)[33])sh;
#pragma unroll
        for (int j = ty; j < 32; j += 8)
            t[j][tx] = p1[((size_t)b * D1 + c0 + j) * NN + n0 + tx];
        __syncthreads();
#pragma unroll
        for (int j = ty; j < 32; j += 8) {
            size_t off = ((size_t)b * NN + n0 + j) * CIN + c0 + tx;
            g_FT[off] = __float2half_rn(t[tx][j]);
        }
        return;
    }
    r -= NB_P1;
    if (r < NB_C0 + NB_C1) {
        const float* src;
        h16* dst;
        int i;
        if (r < NB_C0) { src = w0g; dst = g_W0; i = r * 1024 + tid * 4; }
        else { src = w1g; dst = g_W1; i = (r - NB_C0) * 1024 + tid * 4; }
        float4 v = *(const float4*)(src + i);
        *(uint2*)&dst[i] = make_uint2(
            pack2h(__float2half_rn(v.x), __float2half_rn(v.y)),
            pack2h(__float2half_rn(v.z), __float2half_rn(v.w)));
        return;
    }
    if (tid < 256) {
        g_sum0[tid] = 0.f; g_sum0[tid + 256] = 0.f;
        g_sq0[tid] = 0.f;  g_sq0[tid + 256] = 0.f;
        g_sum1[tid] = 0.f; g_sum1[tid + 256] = 0.f;
        g_sq1[tid] = 0.f;  g_sq1[tid + 256] = 0.f;
    }
}

// ---------------- gather + interpolate -> g_FT[:, :, 256:768] (fp16) ----------------
__global__ void gather_kernel() {
    int wglob = blockIdx.x * 8 + (threadIdx.x >> 5);
    int lane = threadIdx.x & 31;
    int b = wglob / NN;
    size_t base = (size_t)wglob * 3;
    int i0 = g_idx[base + 0], i1 = g_idx[base + 1], i2 = g_idx[base + 2];
    float w0 = g_wgt[base + 0], w1 = g_wgt[base + 1], w2 = g_wgt[base + 2];
    const float* r0 = g_P2T + ((size_t)b * SS + i0) * D2;
    const float* r1 = g_P2T + ((size_t)b * SS + i1) * D2;
    const float* r2 = g_P2T + ((size_t)b * SS + i2) * D2;
    size_t dbase = (size_t)wglob * CIN + D1;
#pragma unroll
    for (int c = lane * 4; c < D2; c += 128) {
        float4 v0 = *(const float4*)&r0[c];
        float4 v1 = *(const float4*)&r1[c];
        float4 v2 = *(const float4*)&r2[c];
        float o0 = w0 * v0.x + w1 * v1.x + w2 * v2.x;
        float o1 = w0 * v0.y + w1 * v1.y + w2 * v2.y;
        float o2 = w0 * v0.z + w1 * v1.z + w2 * v2.z;
        float o3 = w0 * v0.w + w1 * v1.w + w2 * v2.w;
        *(uint2*)&g_FT[dbase + c] = make_uint2(
            pack2h(__float2half_rn(o0), __float2half_rn(o1)),
            pack2h(__float2half_rn(o2), __float2half_rn(o3)));
    }
}

// ======================= HMMA GEMM 1 (pure fp16, 1 MMA/pair) =======================
#define T1 10240                          // bytes per tile (128 rows x 80B)
#define ST1 (2 * T1)                      // stage: A, B = 20480
static constexpr int G1_SMEM = 2 * ST1;   // 40960

__global__ __launch_bounds__(256, 2)
void hmma_gemm1(const h16* __restrict__ Ag, const h16* __restrict__ Bg,
                const float* __restrict__ bias, float* __restrict__ out) {
    extern __shared__ char smem[];
    const uint32_t sb = smem_u32(smem);
    const int tid = threadIdx.x, lane = tid & 31, wid = tid >> 5;
    const int m0 = blockIdx.x * 128, n0 = blockIdx.y * 128, b = blockIdx.z;
    const int wm = (wid & 3) * 32, wn = (wid >> 2) * 64;

    const h16* Arow = Ag + (size_t)m0 * CIN;
    const h16* Brow = Bg + ((size_t)b * NN + n0) * CIN;

    float acc[2][8][4];
#pragma unroll
    for (int i = 0; i < 2; i++)
#pragma unroll
        for (int j = 0; j < 8; j++)
#pragma unroll
            for (int q = 0; q < 4; q++) acc[i][j][q] = 0.f;

    const int row_l = tid >> 2, c16 = (tid & 3);
    auto issue = [&](int kb, uint32_t sbuf) {
#pragma unroll
        for (int t = 0; t < 2; t++) {
            int row = row_l + t * 64;
            uint32_t d = sbuf + row * 80 + c16 * 16;
            cpa16(d,      Arow + (size_t)row * CIN + kb + c16 * 8);
            cpa16(d + T1, Brow + (size_t)row * CIN + kb + c16 * 8);
        }
        CP_COMMIT();
    };

    const int KT = CIN / 32;   // 24
    issue(0, sb);

    for (int c = 0; c < KT; c++) {
        const int buf = c & 1;
        if (c + 1 < KT) {
            issue((c + 1) * 32, sb + (buf ^ 1) * ST1);
            CP_WAIT(1);
        } else {
            CP_WAIT(0);
        }
        __syncthreads();

        const uint32_t sA = sb + buf * ST1;
        const uint32_t sB = sA + T1;
#pragma unroll
        for (int ks = 0; ks < 2; ks++) {
            const int k16 = ks * 16;
            uint32_t ah[2][4];
#pragma unroll
            for (int mi = 0; mi < 2; mi++) {
                uint32_t ad = sA + (wm + mi * 16 + (lane & 15)) * 80
                                 + (k16 + ((lane >> 4) << 3)) * 2;
                ldsm4(ah[mi][0], ah[mi][1], ah[mi][2], ah[mi][3], ad);
            }
#pragma unroll
            for (int ng = 0; ng < 4; ng++) {
                uint32_t row = wn + ng * 16 + (lane & 7) + ((lane & 16) >> 1);
                uint32_t col = k16 + (lane & 8);
                uint32_t ad = sB + row * 80 + col * 2;
                uint32_t bh[4];
                ldsm4(bh[0], bh[1], bh[2], bh[3], ad);
#pragma unroll
                for (int mi = 0; mi < 2; mi++) {
                    mma16816(acc[mi][2 * ng],     ah[mi], bh);
                    mma16816(acc[mi][2 * ng + 1], ah[mi], bh + 2);
                }
            }
        }
        __syncthreads();
    }

    // epilogue -> out (b, m, n) + bias, fused channel stats via atomics
    const int gq = lane >> 2, tq = lane & 3;
#pragma unroll
    for (int mi = 0; mi < 2; mi++) {
        int r0 = m0 + wm + mi * 16 + gq;
        float bv0 = bias[r0], bv1 = bias[r0 + 8];
        float* o0 = out + ((size_t)b * HH + r0) * NN;
        float* o1 = o0 + (size_t)8 * NN;
        float s0 = 0.f, q0 = 0.f, s1 = 0.f, q1 = 0.f;
#pragma unroll
        for (int ni = 0; ni < 8; ni++) {
            int cc = n0 + wn + ni * 8 + tq * 2;
            float y0 = acc[mi][ni][0] + bv0, y1 = acc[mi][ni][1] + bv0;
            float y2 = acc[mi][ni][2] + bv1, y3 = acc[mi][ni][3] + bv1;
            *(float2*)&o0[cc] = make_float2(y0, y1);
            *(float2*)&o1[cc] = make_float2(y2, y3);
            s0 += y0 + y1; q0 += y0 * y0 + y1 * y1;
            s1 += y2 + y3; q1 += y2 * y2 + y3 * y3;
        }
#pragma unroll
        for (int o = 1; o <= 2; o <<= 1) {
            s0 += __shfl_xor_sync(~0u, s0, o);
            q0 += __shfl_xor_sync(~0u, q0, o);
            s1 += __shfl_xor_sync(~0u, s1, o);
            q1 += __shfl_xor_sync(~0u, q1, o);
        }
        if (tq == 0) {
            atomicAdd(&g_sum0[r0], s0);     atomicAdd(&g_sq0[r0], q0);
            atomicAdd(&g_sum0[r0 + 8], s1); atomicAdd(&g_sq0[r0 + 8], q1);
        }
    }
}

// ======================= HMMA GEMM 2 (pure fp16, fused BN+ReLU on B) =======================
#define AT2 10240                // A stage (single fp16)
#define BT2 8704                 // 32 * 272, single fp16
static constexpr int G2_SMEM = 2 * AT2 + 2 * BT2;  // 37888

__global__ __launch_bounds__(256, 2)
void hmma_gemm2(const h16* __restrict__ Ag,
                const float* __restrict__ X0,
                const float* __restrict__ scale, const float* __restrict__ shift,
                const float* __restrict__ bias, float* __restrict__ out) {
    extern __shared__ char smem[];
    const uint32_t sb = smem_u32(smem);
    const int tid = threadIdx.x, lane = tid & 31, wid = tid >> 5;
    const int m0 = blockIdx.x * 128, n0 = blockIdx.y * 128, b = blockIdx.z;
    const int wm = (wid & 3) * 32, wn = (wid >> 2) * 64;

    const h16* Arow = Ag + (size_t)m0 * HH;
    const float* Xb = X0 + (size_t)b * HH * NN + n0;

    float acc[2][8][4];
#pragma unroll
    for (int i = 0; i < 2; i++)
#pragma unroll
        for (int j = 0; j < 8; j++)
#pragma unroll
            for (int q = 0; q < 4; q++) acc[i][j][q] = 0.f;

    const int brow = tid >> 3, bcol = (tid & 7) * 16;
    float x[16];
    float scl, shf;

    const int row_l = tid >> 2, c16 = (tid & 3);
    auto issueA = [&](int kb, uint32_t sbuf) {
#pragma unroll
        for (int t = 0; t < 2; t++) {
            int row = row_l + t * 64;
            uint32_t d = sbuf + row * 80 + c16 * 16;
            cpa16(d, Arow + (size_t)row * HH + kb + c16 * 8);
        }
        CP_COMMIT();
    };

    {
        issueA(0, sb);
        const float* src = Xb + (size_t)brow * NN + bcol;
#pragma unroll
        for (int j = 0; j < 4; j++) {
            float4 v = *(const float4*)(src + j * 4);
            x[4 * j] = v.x; x[4 * j + 1] = v.y; x[4 * j + 2] = v.z; x[4 * j + 3] = v.w;
        }
        scl = scale[brow];
        shf = shift[brow];
    }

    const uint32_t sBoff = 2 * AT2;
    const int KT = HH / 32;  // 16
    for (int c = 0; c < KT; c++) {
        const int buf = c & 1;
        {
            uint32_t doff = sBoff + buf * BT2 + brow * 272 + bcol * 2;
#pragma unroll
            for (int j = 0; j < 4; j++) {
                float y0 = fmaxf(fmaf(x[4 * j + 0], scl, shf), 0.f);
                float y1 = fmaxf(fmaf(x[4 * j + 1], scl, shf), 0.f);
                float y2 = fmaxf(fmaf(x[4 * j + 2], scl, shf), 0.f);
                float y3 = fmaxf(fmaf(x[4 * j + 3], scl, shf), 0.f);
                *(uint2*)(smem + doff + j * 8) = make_uint2(
                    pack2h(__float2half_rn(y0), __float2half_rn(y1)),
                    pack2h(__float2half_rn(y2), __float2half_rn(y3)));
            }
        }
        if (c + 1 < KT) {
            const int kb = (c + 1) * 32;
            issueA(kb, sb + (buf ^ 1) * AT2);
            const float* src = Xb + (size_t)(kb + brow) * NN + bcol;
#pragma unroll
            for (int j = 0; j < 4; j++) {
                float4 v = *(const float4*)(src + j * 4);
                x[4 * j] = v.x; x[4 * j + 1] = v.y; x[4 * j + 2] = v.z; x[4 * j + 3] = v.w;
            }
            scl = scale[kb + brow];
            shf = shift[kb + brow];
            CP_WAIT(1);
        } else {
            CP_WAIT(0);
        }
        __syncthreads();

        const uint32_t sA = sb + buf * AT2;
        const uint32_t sB = sb + sBoff + buf * BT2;
#pragma unroll
        for (int ks = 0; ks < 2; ks++) {
            const int k16 = ks * 16;
            uint32_t ah[2][4];
#pragma unroll
            for (int mi = 0; mi < 2; mi++) {
                uint32_t ad = sA + (wm + mi * 16 + (lane & 15)) * 80
                                 + (k16 + ((lane >> 4) << 3)) * 2;
                ldsm4(ah[mi][0], ah[mi][1], ah[mi][2], ah[mi][3], ad);
            }
#pragma unroll
            for (int ng = 0; ng < 4; ng++) {
                uint32_t row = k16 + (lane & 7) + (lane & 8);
                uint32_t col = wn + ng * 16 + ((lane >> 4) << 3);
                uint32_t ad = sB + row * 272 + col * 2;
                uint32_t bh[4];
                ldsm4t(bh[0], bh[1], bh[2], bh[3], ad);
#pragma unroll
                for (int mi = 0; mi < 2; mi++) {
                    mma16816(acc[mi][2 * ng],     ah[mi], bh);
                    mma16816(acc[mi][2 * ng + 1], ah[mi], bh + 2);
                }
            }
        }
        __syncthreads();
    }

    const int gq = lane >> 2, tq = lane & 3;
#pragma unroll
    for (int mi = 0; mi < 2; mi++) {
        int r0 = m0 + wm + mi * 16 + gq;
        float bv0 = bias[r0], bv1 = bias[r0 + 8];
        float* o0 = out + ((size_t)b * HH + r0) * NN;
        float* o1 = o0 + (size_t)8 * NN;
        float s0 = 0.f, q0 = 0.f, s1 = 0.f, q1 = 0.f;
#pragma unroll
        for (int ni = 0; ni < 8; ni++) {
            int cc = n0 + wn + ni * 8 + tq * 2;
            float y0 = acc[mi][ni][0] + bv0, y1 = acc[mi][ni][1] + bv0;
            float y2 = acc[mi][ni][2] + bv1, y3 = acc[mi][ni][3] + bv1;
            *(float2*)&o0[cc] = make_float2(y0, y1);
            *(float2*)&o1[cc] = make_float2(y2, y3);
            s0 += y0 + y1; q0 += y0 * y0 + y1 * y1;
            s1 += y2 + y3; q1 += y2 * y2 + y3 * y3;
        }
#pragma unroll
        for (int o = 1; o <= 2; o <<= 1) {
            s0 += __shfl_xor_sync(~0u, s0, o);
            q0 += __shfl_xor_sync(~0u, q0, o);
            s1 += __shfl_xor_sync(~0u, s1, o);
            q1 += __shfl_xor_sync(~0u, q1, o);
        }
        if (tq == 0) {
            atomicAdd(&g_sum1[r0], s0);     atomicAdd(&g_sq1[r0], q0);
            atomicAdd(&g_sum1[r0 + 8], s1); atomicAdd(&g_sq1[r0 + 8], q1);
        }
    }
}

// ---------------- stats finalize ----------------
__global__ void stats_final_kernel(const float* __restrict__ gsum,
                                   const float* __restrict__ gsq,
                                   const float* __restrict__ g,
                                   const float* __restrict__ be,
                                   float* __restrict__ scale,
                                   float* __restrict__ shift) {
    const int c = threadIdx.x;
    const float inv = 1.f / (float)(BB * NN);
    float m = gsum[c] * inv;
    float var = gsq[c] * inv - m * m;
    float sc = g[c] * rsqrtf(var + 1e-5f);
    scale[c] = sc;
    shift[c] = be[c] - m * sc;
}

__global__ void apply_bn_kernel(float* __restrict__ X) {
    const size_t total4 = (size_t)BB * HH * NN / 4;
    for (size_t i = (size_t)blockIdx.x * blockDim.x + threadIdx.x; i < total4;
         i += (size_t)gridDim.x * blockDim.x) {
        float4 v = ((float4*)X)[i];
        int c = (int)((i * 4) >> 13) & (HH - 1);
        float s = g_scale1[c], h = g_shift1[c];
        v.x = fmaxf(fmaf(v.x, s, h), 0.f);
        v.y = fmaxf(fmaf(v.y, s, h), 0.f);
        v.z = fmaxf(fmaf(v.z, s, h), 0.f);
        v.w = fmaxf(fmaf(v.w, s, h), 0.f);
        ((float4*)X)[i] = v;
    }
}

// ======================= launcher =======================
extern "C" void kernel_launch(void* const* d_in, const int* in_sizes, int n_in,
                              void* d_out, int out_size) {
    const float* xyz1    = (const float*)d_in[0];
    const float* xyz2    = (const float*)d_in[1];
    const float* points1 = (const float*)d_in[2];
    const float* points2 = (const float*)d_in[3];
    const float* w0 = (const float*)d_in[4];
    const float* b0 = (const float*)d_in[5];
    const float* g0 = (const float*)d_in[6];
    const float* be0 = (const float*)d_in[7];
    const float* w1 = (const float*)d_in[8];
    const float* b1 = (const float*)d_in[9];
    const float* g1 = (const float*)d_in[10];
    const float* be1 = (const float*)d_in[11];
    float* out = (float*)d_out;

    float *p_scale0, *p_shift0, *p_scale1, *p_shift1, *p_X0;
    float *p_sum0, *p_sq0, *p_sum1, *p_sq1;
    h16 *p_W0, *p_W1, *p_FT;
    cudaGetSymbolAddress((void**)&p_scale0, g_scale0);
    cudaGetSymbolAddress((void**)&p_shift0, g_shift0);
    cudaGetSymbolAddress((void**)&p_scale1, g_scale1);
    cudaGetSymbolAddress((void**)&p_shift1, g_shift1);
    cudaGetSymbolAddress((void**)&p_X0, g_X0);
    cudaGetSymbolAddress((void**)&p_sum0, g_sum0);
    cudaGetSymbolAddress((void**)&p_sq0, g_sq0);
    cudaGetSymbolAddress((void**)&p_sum1, g_sum1);
    cudaGetSymbolAddress((void**)&p_sq1, g_sq1);
    cudaGetSymbolAddress((void**)&p_W0, g_W0);
    cudaGetSymbolAddress((void**)&p_W1, g_W1);
    cudaGetSymbolAddress((void**)&p_FT, g_FT);

    cudaFuncSetAttribute(hmma_gemm1, cudaFuncAttributeMaxDynamicSharedMemorySize, G1_SMEM);
    cudaFuncSetAttribute(hmma_gemm2, cudaFuncAttributeMaxDynamicSharedMemorySize, G2_SMEM);

    prep_kernel<<<NB_TOTAL, 256>>>(xyz1, xyz2, points1, points2, w0, w1);
    gather_kernel<<<BB * NN / 8, 256>>>();

    hmma_gemm1<<<dim3(HH / 128, NN / 128, BB), 256, G1_SMEM>>>(
        p_W0, p_FT, b0, p_X0);
    stats_final_kernel<<<1, HH>>>(p_sum0, p_sq0, g0, be0, p_scale0, p_shift0);

    hmma_gemm2<<<dim3(HH / 128, NN / 128, BB), 256, G2_SMEM>>>(
        p_W1, p_X0, p_scale0, p_shift0, b1, out);
    stats_final_kernel<<<1, HH>>>(p_sum1, p_sq1, g1, be1, p_scale1, p_shift1);
    apply_bn_kernel<<<4096, 256>>>(out);
}

// round 12
// speedup vs baseline: 1.9855x; 1.0160x over previous
#include <cuda_runtime.h>
#include <cuda_fp16.h>
#include <cstdint>

// Problem constants
#define BB 8
#define NN 8192
#define SS 2048
#define D1 256
#define D2 512
#define CIN 768
#define HH 512

typedef __half h16;

// ---------------- scratch (static device globals; no runtime alloc) ----------------
__device__ h16  g_P2T[(size_t)BB * SS * D2];           // fp16
__device__ int   g_idx[(size_t)BB * NN * 3];
__device__ float g_wgt[(size_t)BB * NN * 3];
__device__ h16  g_FT[(size_t)BB * NN * CIN];           // single fp16
__device__ h16  g_W0[HH * CIN];                        // single fp16
__device__ h16  g_W1[HH * HH];                         // single fp16
__device__ h16  g_X0[(size_t)BB * HH * NN];            // (b, c, n) fp16
__device__ float g_sum0[HH], g_sq0[HH], g_sum1[HH], g_sq1[HH];
__device__ float g_scale0[HH], g_shift0[HH], g_scale1[HH], g_shift1[HH];

// ======================= low-level helpers =======================
__device__ __forceinline__ uint32_t smem_u32(const void* p) {
    uint32_t a;
    asm("{ .reg .u64 t; cvta.to.shared.u64 t, %1; cvt.u32.u64 %0, t; }" : "=r"(a) : "l"(p));
    return a;
}
__device__ __forceinline__ void ldsm4(uint32_t& r0, uint32_t& r1, uint32_t& r2,
                                      uint32_t& r3, uint32_t a) {
    asm volatile("ldmatrix.sync.aligned.m8n8.x4.shared.b16 {%0,%1,%2,%3},[%4];"
                 : "=r"(r0), "=r"(r1), "=r"(r2), "=r"(r3) : "r"(a));
}
__device__ __forceinline__ void ldsm4t(uint32_t& r0, uint32_t& r1, uint32_t& r2,
                                       uint32_t& r3, uint32_t a) {
    asm volatile("ldmatrix.sync.aligned.m8n8.x4.trans.shared.b16 {%0,%1,%2,%3},[%4];"
                 : "=r"(r0), "=r"(r1), "=r"(r2), "=r"(r3) : "r"(a));
}
__device__ __forceinline__ void mma16816(float* d, const uint32_t* a, const uint32_t* b) {
    asm volatile(
        "mma.sync.aligned.m16n8k16.row.col.f32.f16.f16.f32 "
        "{%0,%1,%2,%3},{%4,%5,%6,%7},{%8,%9},{%0,%1,%2,%3};"
        : "+f"(d[0]), "+f"(d[1]), "+f"(d[2]), "+f"(d[3])
        : "r"(a[0]), "r"(a[1]), "r"(a[2]), "r"(a[3]), "r"(b[0]), "r"(b[1]));
}
__device__ __forceinline__ void cpa16(uint32_t dst, const void* src) {
    asm volatile("cp.async.cg.shared.global [%0],[%1],16;" :: "r"(dst), "l"(src));
}
#define CP_COMMIT() asm volatile("cp.async.commit_group;" ::: "memory")
#define CP_WAIT(n) asm volatile("cp.async.wait_group %0;" :: "n"(n) : "memory")

__device__ __forceinline__ uint32_t pack2h(h16 a, h16 b) {
    __half2 t = __halves2half2(a, b);
    return *reinterpret_cast<uint32_t*>(&t);
}
__device__ __forceinline__ float2 h2f2(uint32_t u) {
    return __half22float2(*reinterpret_cast<__half2*>(&u));
}

// ---------------- top-3 helper ----------------
struct Top3 { float d0, d1, d2; int i0, i1, i2; };
__device__ __forceinline__ void t3_ins(Top3& q, float t, int s) {
    if (t < q.d2) {
        if (t < q.d1) {
            q.d2 = q.d1; q.i2 = q.i1;
            if (t < q.d0) { q.d1 = q.d0; q.i1 = q.i0; q.d0 = t; q.i0 = s; }
            else          { q.d1 = t;    q.i1 = s; }
        } else { q.d2 = t; q.i2 = s; }
    }
}

// ======================= fused prep kernel =======================
#define NB_T3 128
#define NB_P2 8192
#define NB_P1 16384
#define NB_C0 (HH * CIN / 1024)
#define NB_C1 (HH * HH / 1024)
#define NB_TOTAL (NB_T3 + NB_P2 + NB_P1 + NB_C0 + NB_C1 + 1)

__global__ __launch_bounds__(256)
void prep_kernel(const float* __restrict__ xyz1, const float* __restrict__ xyz2,
                 const float* __restrict__ p1, const float* __restrict__ p2,
                 const float* __restrict__ w0g, const float* __restrict__ w1g) {
    __shared__ float sh[8192];
    int r = blockIdx.x;
    const int tid = threadIdx.x;

    if (r < NB_T3) {
        float* sx = sh;
        float* sy = sh + 2048;
        float* sz = sh + 4096;
        float* sn = sh + 6144;
        const int b = r >> 4;
        const int nbase = (r & 15) * 512;

        for (int i = tid; i < SS; i += 256) {
            float x = xyz2[((size_t)b * 3 + 0) * SS + i];
            float y = xyz2[((size_t)b * 3 + 1) * SS + i];
            float z = xyz2[((size_t)b * 3 + 2) * SS + i];
            sx[i] = x; sy[i] = y; sz[i] = z;
            sn[i] = x * x + y * y + z * z;
        }
        __syncthreads();

        const int na = nbase + tid;
        const int nb = nbase + 256 + tid;
        float xa = xyz1[((size_t)b * 3 + 0) * NN + na];
        float ya = xyz1[((size_t)b * 3 + 1) * NN + na];
        float za = xyz1[((size_t)b * 3 + 2) * NN + na];
        float xb = xyz1[((size_t)b * 3 + 0) * NN + nb];
        float yb = xyz1[((size_t)b * 3 + 1) * NN + nb];
        float zb = xyz1[((size_t)b * 3 + 2) * NN + nb];
        float n1a = xa * xa + ya * ya + za * za;
        float n1b = xb * xb + yb * yb + zb * zb;
        float mxa = -2.f * xa, mya = -2.f * ya, mza = -2.f * za;
        float mxb = -2.f * xb, myb = -2.f * yb, mzb = -2.f * zb;

        Top3 qa = {3.4e38f, 3.4e38f, 3.4e38f, 0, 0, 0};
        Top3 qb = {3.4e38f, 3.4e38f, 3.4e38f, 0, 0, 0};

        for (int s = 0; s < SS; s += 4) {
            float4 vx = ((float4*)sx)[s >> 2], vy = ((float4*)sy)[s >> 2];
            float4 vz = ((float4*)sz)[s >> 2], vn = ((float4*)sn)[s >> 2];
            float t;
            t = fmaf(mxa, vx.x, vn.x); t = fmaf(mya, vy.x, t); t = fmaf(mza, vz.x, t); t3_ins(qa, t, s + 0);
            t = fmaf(mxa, vx.y, vn.y); t = fmaf(mya, vy.y, t); t = fmaf(mza, vz.y, t); t3_ins(qa, t, s + 1);
            t = fmaf(mxa, vx.z, vn.z); t = fmaf(mya, vy.z, t); t = fmaf(mza, vz.z, t); t3_ins(qa, t, s + 2);
            t = fmaf(mxa, vx.w, vn.w); t = fmaf(mya, vy.w, t); t = fmaf(mza, vz.w, t); t3_ins(qa, t, s + 3);
            t = fmaf(mxb, vx.x, vn.x); t = fmaf(myb, vy.x, t); t = fmaf(mzb, vz.x, t); t3_ins(qb, t, s + 0);
            t = fmaf(mxb, vx.y, vn.y); t = fmaf(myb, vy.y, t); t = fmaf(mzb, vz.y, t); t3_ins(qb, t, s + 1);
            t = fmaf(mxb, vx.z, vn.z); t = fmaf(myb, vy.z, t); t = fmaf(mzb, vz.z, t); t3_ins(qb, t, s + 2);
            t = fmaf(mxb, vx.w, vn.w); t = fmaf(myb, vy.w, t); t = fmaf(mzb, vz.w, t); t3_ins(qb, t, s + 3);
        }

        {
            size_t base = ((size_t)b * NN + na) * 3;
            float d0 = qa.d0 + n1a, d1 = qa.d1 + n1a, d2 = qa.d2 + n1a;
            float w0 = 1.0f / (d0 + 1e-8f), w1 = 1.0f / (d1 + 1e-8f), w2 = 1.0f / (d2 + 1e-8f);
            float inv = 1.0f / (w0 + w1 + w2);
            g_idx[base + 0] = qa.i0; g_idx[base + 1] = qa.i1; g_idx[base + 2] = qa.i2;
            g_wgt[base + 0] = w0 * inv; g_wgt[base + 1] = w1 * inv; g_wgt[base + 2] = w2 * inv;
        }
        {
            size_t base = ((size_t)b * NN + nb) * 3;
            float d0 = qb.d0 + n1b, d1 = qb.d1 + n1b, d2 = qb.d2 + n1b;
            float w0 = 1.0f / (d0 + 1e-8f), w1 = 1.0f / (d1 + 1e-8f), w2 = 1.0f / (d2 + 1e-8f);
            float inv = 1.0f / (w0 + w1 + w2);
            g_idx[base + 0] = qb.i0; g_idx[base + 1] = qb.i1; g_idx[base + 2] = qb.i2;
            g_wgt[base + 0] = w0 * inv; g_wgt[base + 1] = w1 * inv; g_wgt[base + 2] = w2 * inv;
        }
        return;
    }
    r -= NB_T3;
    if (r < NB_P2) {
        int b = r >> 10, y = (r >> 6) & 15, x = r & 63;
        int c0 = y * 32, s0 = x * 32;
        int tx = tid & 31, ty = tid >> 5;
        float (*t)[33] = (float(*)[33])sh;
#pragma unroll
        for (int j = ty; j < 32; j += 8)
            t[j][tx] = p2[((size_t)b * D2 + c0 + j) * SS + s0 + tx];
        __syncthreads();
#pragma unroll
        for (int j = ty; j < 32; j += 8)
            g_P2T[((size_t)b * SS + s0 + j) * D2 + c0 + tx] = __float2half_rn(t[tx][j]);
        return;
    }
    r -= NB_P2;
    if (r < NB_P1) {
        int b = r >> 11, y = (r >> 8) & 7, x = r & 255;
        int c0 = y * 32, n0 = x * 32;
        int tx = tid & 31, ty = tid >> 5;
        float (*t)[33] = (float(*)[33])sh;
#pragma unroll
        for (int j = ty; j < 32; j += 8)
            t[j][tx] = p1[((size_t)b * D1 + c0 + j) * NN + n0 + tx];
        __syncthreads();
#pragma unroll
        for (int j = ty; j < 32; j += 8) {
            size_t off = ((size_t)b * NN + n0 + j) * CIN + c0 + tx;
            g_FT[off] = __float2half_rn(t[tx][j]);
        }
        return;
    }
    r -= NB_P1;
    if (r < NB_C0 + NB_C1) {
        const float* src;
        h16* dst;
        int i;
        if (r < NB_C0) { src = w0g; dst = g_W0; i = r * 1024 + tid * 4; }
        else { src = w1g; dst = g_W1; i = (r - NB_C0) * 1024 + tid * 4; }
        float4 v = *(const float4*)(src + i);
        *(uint2*)&dst[i] = make_uint2(
            pack2h(__float2half_rn(v.x), __float2half_rn(v.y)),
            pack2h(__float2half_rn(v.z), __float2half_rn(v.w)));
        return;
    }
    if (tid < 256) {
        g_sum0[tid] = 0.f; g_sum0[tid + 256] = 0.f;
        g_sq0[tid] = 0.f;  g_sq0[tid + 256] = 0.f;
        g_sum1[tid] = 0.f; g_sum1[tid + 256] = 0.f;
        g_sq1[tid] = 0.f;  g_sq1[tid + 256] = 0.f;
    }
}

// ---------------- gather + interpolate -> g_FT[:, :, 256:768] (fp16 in/out) ----------------
__global__ void gather_kernel() {
    int wglob = blockIdx.x * 8 + (threadIdx.x >> 5);
    int lane = threadIdx.x & 31;
    int b = wglob / NN;
    size_t base = (size_t)wglob * 3;
    int i0 = g_idx[base + 0], i1 = g_idx[base + 1], i2 = g_idx[base + 2];
    float w0 = g_wgt[base + 0], w1 = g_wgt[base + 1], w2 = g_wgt[base + 2];
    const h16* r0 = g_P2T + ((size_t)b * SS + i0) * D2;
    const h16* r1 = g_P2T + ((size_t)b * SS + i1) * D2;
    const h16* r2 = g_P2T + ((size_t)b * SS + i2) * D2;
    size_t dbase = (size_t)wglob * CIN + D1;
#pragma unroll
    for (int c = lane * 4; c < D2; c += 128) {
        uint2 u0 = *(const uint2*)&r0[c];
        uint2 u1 = *(const uint2*)&r1[c];
        uint2 u2 = *(const uint2*)&r2[c];
        float2 a0 = h2f2(u0.x), a1 = h2f2(u0.y);
        float2 b0 = h2f2(u1.x), b1 = h2f2(u1.y);
        float2 c0 = h2f2(u2.x), c1 = h2f2(u2.y);
        float o0 = w0 * a0.x + w1 * b0.x + w2 * c0.x;
        float o1 = w0 * a0.y + w1 * b0.y + w2 * c0.y;
        float o2 = w0 * a1.x + w1 * b1.x + w2 * c1.x;
        float o3 = w0 * a1.y + w1 * b1.y + w2 * c1.y;
        *(uint2*)&g_FT[dbase + c] = make_uint2(
            pack2h(__float2half_rn(o0), __float2half_rn(o1)),
            pack2h(__float2half_rn(o2), __float2half_rn(o3)));
    }
}

// ======================= HMMA GEMM 1 (pure fp16, X0 out fp16) =======================
#define T1 10240                          // bytes per tile (128 rows x 80B)
#define ST1 (2 * T1)                      // stage: A, B = 20480
static constexpr int G1_SMEM = 2 * ST1;   // 40960

__global__ __launch_bounds__(256, 2)
void hmma_gemm1(const h16* __restrict__ Ag, const h16* __restrict__ Bg,
                const float* __restrict__ bias, h16* __restrict__ out) {
    extern __shared__ char smem[];
    const uint32_t sb = smem_u32(smem);
    const int tid = threadIdx.x, lane = tid & 31, wid = tid >> 5;
    const int m0 = blockIdx.x * 128, n0 = blockIdx.y * 128, b = blockIdx.z;
    const int wm = (wid & 3) * 32, wn = (wid >> 2) * 64;

    const h16* Arow = Ag + (size_t)m0 * CIN;
    const h16* Brow = Bg + ((size_t)b * NN + n0) * CIN;

    float acc[2][8][4];
#pragma unroll
    for (int i = 0; i < 2; i++)
#pragma unroll
        for (int j = 0; j < 8; j++)
#pragma unroll
            for (int q = 0; q < 4; q++) acc[i][j][q] = 0.f;

    const int row_l = tid >> 2, c16 = (tid & 3);
    auto issue = [&](int kb, uint32_t sbuf) {
#pragma unroll
        for (int t = 0; t < 2; t++) {
            int row = row_l + t * 64;
            uint32_t d = sbuf + row * 80 + c16 * 16;
            cpa16(d,      Arow + (size_t)row * CIN + kb + c16 * 8);
            cpa16(d + T1, Brow + (size_t)row * CIN + kb + c16 * 8);
        }
        CP_COMMIT();
    };

    const int KT = CIN / 32;   // 24
    issue(0, sb);

    for (int c = 0; c < KT; c++) {
        const int buf = c & 1;
        if (c + 1 < KT) {
            issue((c + 1) * 32, sb + (buf ^ 1) * ST1);
            CP_WAIT(1);
        } else {
            CP_WAIT(0);
        }
        __syncthreads();

        const uint32_t sA = sb + buf * ST1;
        const uint32_t sB = sA + T1;
#pragma unroll
        for (int ks = 0; ks < 2; ks++) {
            const int k16 = ks * 16;
            uint32_t ah[2][4];
#pragma unroll
            for (int mi = 0; mi < 2; mi++) {
                uint32_t ad = sA + (wm + mi * 16 + (lane & 15)) * 80
                                 + (k16 + ((lane >> 4) << 3)) * 2;
                ldsm4(ah[mi][0], ah[mi][1], ah[mi][2], ah[mi][3], ad);
            }
#pragma unroll
            for (int ng = 0; ng < 4; ng++) {
                uint32_t row = wn + ng * 16 + (lane & 7) + ((lane & 16) >> 1);
                uint32_t col = k16 + (lane & 8);
                uint32_t ad = sB + row * 80 + col * 2;
                uint32_t bh[4];
                ldsm4(bh[0], bh[1], bh[2], bh[3], ad);
#pragma unroll
                for (int mi = 0; mi < 2; mi++) {
                    mma16816(acc[mi][2 * ng],     ah[mi], bh);
                    mma16816(acc[mi][2 * ng + 1], ah[mi], bh + 2);
                }
            }
        }
        __syncthreads();
    }

    // epilogue -> out fp16 (b, m, n) + bias, fused channel stats via atomics
    const int gq = lane >> 2, tq = lane & 3;
#pragma unroll
    for (int mi = 0; mi < 2; mi++) {
        int r0 = m0 + wm + mi * 16 + gq;
        float bv0 = bias[r0], bv1 = bias[r0 + 8];
        h16* o0 = out + ((size_t)b * HH + r0) * NN;
        h16* o1 = o0 + (size_t)8 * NN;
        float s0 = 0.f, q0 = 0.f, s1 = 0.f, q1 = 0.f;
#pragma unroll
        for (int ni = 0; ni < 8; ni++) {
            int cc = n0 + wn + ni * 8 + tq * 2;
            float y0 = acc[mi][ni][0] + bv0, y1 = acc[mi][ni][1] + bv0;
            float y2 = acc[mi][ni][2] + bv1, y3 = acc[mi][ni][3] + bv1;
            *(uint32_t*)&o0[cc] = pack2h(__float2half_rn(y0), __float2half_rn(y1));
            *(uint32_t*)&o1[cc] = pack2h(__float2half_rn(y2), __float2half_rn(y3));
            s0 += y0 + y1; q0 += y0 * y0 + y1 * y1;
            s1 += y2 + y3; q1 += y2 * y2 + y3 * y3;
        }
#pragma unroll
        for (int o = 1; o <= 2; o <<= 1) {
            s0 += __shfl_xor_sync(~0u, s0, o);
            q0 += __shfl_xor_sync(~0u, q0, o);
            s1 += __shfl_xor_sync(~0u, s1, o);
            q1 += __shfl_xor_sync(~0u, q1, o);
        }
        if (tq == 0) {
            atomicAdd(&g_sum0[r0], s0);     atomicAdd(&g_sq0[r0], q0);
            atomicAdd(&g_sum0[r0 + 8], s1); atomicAdd(&g_sq0[r0 + 8], q1);
        }
    }
}

// ======================= HMMA GEMM 2 (pure fp16, X0 fp16 in, fused BN+ReLU) =======================
#define AT2 10240                // A stage (single fp16)
#define BT2 8704                 // 32 * 272, single fp16
static constexpr int G2_SMEM = 2 * AT2 + 2 * BT2;  // 37888

__global__ __launch_bounds__(256, 2)
void hmma_gemm2(const h16* __restrict__ Ag,
                const h16* __restrict__ X0,
                const float* __restrict__ scale, const float* __restrict__ shift,
                const float* __restrict__ bias, float* __restrict__ out) {
    extern __shared__ char smem[];
    const uint32_t sb = smem_u32(smem);
    const int tid = threadIdx.x, lane = tid & 31, wid = tid >> 5;
    const int m0 = blockIdx.x * 128, n0 = blockIdx.y * 128, b = blockIdx.z;
    const int wm = (wid & 3) * 32, wn = (wid >> 2) * 64;

    const h16* Arow = Ag + (size_t)m0 * HH;
    const h16* Xb = X0 + (size_t)b * HH * NN + n0;

    float acc[2][8][4];
#pragma unroll
    for (int i = 0; i < 2; i++)
#pragma unroll
        for (int j = 0; j < 8; j++)
#pragma unroll
            for (int q = 0; q < 4; q++) acc[i][j][q] = 0.f;

    const int brow = tid >> 3, bcol = (tid & 7) * 16;
    float x[16];
    float scl, shf;

    const int row_l = tid >> 2, c16 = (tid & 3);
    auto issueA = [&](int kb, uint32_t sbuf) {
#pragma unroll
        for (int t = 0; t < 2; t++) {
            int row = row_l + t * 64;
            uint32_t d = sbuf + row * 80 + c16 * 16;
            cpa16(d, Arow + (size_t)row * HH + kb + c16 * 8);
        }
        CP_COMMIT();
    };
    auto loadX = [&](int kb) {
        const h16* src = Xb + (size_t)(kb + brow) * NN + bcol;
        uint4 u0 = *(const uint4*)src;
        uint4 u1 = *(const uint4*)(src + 8);
        float2 p;
        p = h2f2(u0.x); x[0] = p.x; x[1] = p.y;
        p = h2f2(u0.y); x[2] = p.x; x[3] = p.y;
        p = h2f2(u0.z); x[4] = p.x; x[5] = p.y;
        p = h2f2(u0.w); x[6] = p.x; x[7] = p.y;
        p = h2f2(u1.x); x[8] = p.x; x[9] = p.y;
        p = h2f2(u1.y); x[10] = p.x; x[11] = p.y;
        p = h2f2(u1.z); x[12] = p.x; x[13] = p.y;
        p = h2f2(u1.w); x[14] = p.x; x[15] = p.y;
        scl = scale[kb + brow];
        shf = shift[kb + brow];
    };

    {
        issueA(0, sb);
        loadX(0);
    }

    const uint32_t sBoff = 2 * AT2;
    const int KT = HH / 32;  // 16
    for (int c = 0; c < KT; c++) {
        const int buf = c & 1;
        {
            uint32_t doff = sBoff + buf * BT2 + brow * 272 + bcol * 2;
#pragma unroll
            for (int j = 0; j < 4; j++) {
                float y0 = fmaxf(fmaf(x[4 * j + 0], scl, shf), 0.f);
                float y1 = fmaxf(fmaf(x[4 * j + 1], scl, shf), 0.f);
                float y2 = fmaxf(fmaf(x[4 * j + 2], scl, shf), 0.f);
                float y3 = fmaxf(fmaf(x[4 * j + 3], scl, shf), 0.f);
                *(uint2*)(smem + doff + j * 8) = make_uint2(
                    pack2h(__float2half_rn(y0), __float2half_rn(y1)),
                    pack2h(__float2half_rn(y2), __float2half_rn(y3)));
            }
        }
        if (c + 1 < KT) {
            issueA((c + 1) * 32, sb + (buf ^ 1) * AT2);
            loadX((c + 1) * 32);
            CP_WAIT(1);
        } else {
            CP_WAIT(0);
        }
        __syncthreads();

        const uint32_t sA = sb + buf * AT2;
        const uint32_t sB = sb + sBoff + buf * BT2;
#pragma unroll
        for (int ks = 0; ks < 2; ks++) {
            const int k16 = ks * 16;
            uint32_t ah[2][4];
#pragma unroll
            for (int mi = 0; mi < 2; mi++) {
                uint32_t ad = sA + (wm + mi * 16 + (lane & 15)) * 80
                                 + (k16 + ((lane >> 4) << 3)) * 2;
                ldsm4(ah[mi][0], ah[mi][1], ah[mi][2], ah[mi][3], ad);
            }
#pragma unroll
            for (int ng = 0; ng < 4; ng++) {
                uint32_t row = k16 + (lane & 7) + (lane & 8);
                uint32_t col = wn + ng * 16 + ((lane >> 4) << 3);
                uint32_t ad = sB + row * 272 + col * 2;
                uint32_t bh[4];
                ldsm4t(bh[0], bh[1], bh[2], bh[3], ad);
#pragma unroll
                for (int mi = 0; mi < 2; mi++) {
                    mma16816(acc[mi][2 * ng],     ah[mi], bh);
                    mma16816(acc[mi][2 * ng + 1], ah[mi], bh + 2);
                }
            }
        }
        __syncthreads();
    }

    const int gq = lane >> 2, tq = lane & 3;
#pragma unroll
    for (int mi = 0; mi < 2; mi++) {
        int r0 = m0 + wm + mi * 16 + gq;
        float bv0 = bias[r0], bv1 = bias[r0 + 8];
        float* o0 = out + ((size_t)b * HH + r0) * NN;
        float* o1 = o0 + (size_t)8 * NN;
        float s0 = 0.f, q0 = 0.f, s1 = 0.f, q1 = 0.f;
#pragma unroll
        for (int ni = 0; ni < 8; ni++) {
            int cc = n0 + wn + ni * 8 + tq * 2;
            float y0 = acc[mi][ni][0] + bv0, y1 = acc[mi][ni][1] + bv0;
            float y2 = acc[mi][ni][2] + bv1, y3 = acc[mi][ni][3] + bv1;
            *(float2*)&o0[cc] = make_float2(y0, y1);
            *(float2*)&o1[cc] = make_float2(y2, y3);
            s0 += y0 + y1; q0 += y0 * y0 + y1 * y1;
            s1 += y2 + y3; q1 += y2 * y2 + y3 * y3;
        }
#pragma unroll
        for (int o = 1; o <= 2; o <<= 1) {
            s0 += __shfl_xor_sync(~0u, s0, o);
            q0 += __shfl_xor_sync(~0u, q0, o);
            s1 += __shfl_xor_sync(~0u, s1, o);
            q1 += __shfl_xor_sync(~0u, q1, o);
        }
        if (tq == 0) {
            atomicAdd(&g_sum1[r0], s0);     atomicAdd(&g_sq1[r0], q0);
            atomicAdd(&g_sum1[r0 + 8], s1); atomicAdd(&g_sq1[r0 + 8], q1);
        }
    }
}

// ---------------- stats finalize ----------------
__global__ void stats_final_kernel(const float* __restrict__ gsum,
                                   const float* __restrict__ gsq,
                                   const float* __restrict__ g,
                                   const float* __restrict__ be,
                                   float* __restrict__ scale,
                                   float* __restrict__ shift) {
    const int c = threadIdx.x;
    const float inv = 1.f / (float)(BB * NN);
    float m = gsum[c] * inv;
    float var = gsq[c] * inv - m * m;
    float sc = g[c] * rsqrtf(var + 1e-5f);
    scale[c] = sc;
    shift[c] = be[c] - m * sc;
}

__global__ void apply_bn_kernel(float* __restrict__ X) {
    const size_t total4 = (size_t)BB * HH * NN / 4;
    for (size_t i = (size_t)blockIdx.x * blockDim.x + threadIdx.x; i < total4;
         i += (size_t)gridDim.x * blockDim.x) {
        float4 v = __ldcs(&((float4*)X)[i]);
        int c = (int)((i * 4) >> 13) & (HH - 1);
        float s = g_scale1[c], h = g_shift1[c];
        v.x = fmaxf(fmaf(v.x, s, h), 0.f);
        v.y = fmaxf(fmaf(v.y, s, h), 0.f);
        v.z = fmaxf(fmaf(v.z, s, h), 0.f);
        v.w = fmaxf(fmaf(v.w, s, h), 0.f);
        __stcs(&((float4*)X)[i], v);
    }
}

// ======================= launcher =======================
extern "C" void kernel_launch(void* const* d_in, const int* in_sizes, int n_in,
                              void* d_out, int out_size) {
    const float* xyz1    = (const float*)d_in[0];
    const float* xyz2    = (const float*)d_in[1];
    const float* points1 = (const float*)d_in[2];
    const float* points2 = (const float*)d_in[3];
    const float* w0 = (const float*)d_in[4];
    const float* b0 = (const float*)d_in[5];
    const float* g0 = (const float*)d_in[6];
    const float* be0 = (const float*)d_in[7];
    const float* w1 = (const float*)d_in[8];
    const float* b1 = (const float*)d_in[9];
    const float* g1 = (const float*)d_in[10];
    const float* be1 = (const float*)d_in[11];
    float* out = (float*)d_out;

    float *p_scale0, *p_shift0, *p_scale1, *p_shift1;
    float *p_sum0, *p_sq0, *p_sum1, *p_sq1;
    h16 *p_W0, *p_W1, *p_FT, *p_X0;
    cudaGetSymbolAddress((void**)&p_scale0, g_scale0);
    cudaGetSymbolAddress((void**)&p_shift0, g_shift0);
    cudaGetSymbolAddress((void**)&p_scale1, g_scale1);
    cudaGetSymbolAddress((void**)&p_shift1, g_shift1);
    cudaGetSymbolAddress((void**)&p_X0, g_X0);
    cudaGetSymbolAddress((void**)&p_sum0, g_sum0);
    cudaGetSymbolAddress((void**)&p_sq0, g_sq0);
    cudaGetSymbolAddress((void**)&p_sum1, g_sum1);
    cudaGetSymbolAddress((void**)&p_sq1, g_sq1);
    cudaGetSymbolAddress((void**)&p_W0, g_W0);
    cudaGetSymbolAddress((void**)&p_W1, g_W1);
    cudaGetSymbolAddress((void**)&p_FT, g_FT);

    cudaFuncSetAttribute(hmma_gemm1, cudaFuncAttributeMaxDynamicSharedMemorySize, G1_SMEM);
    cudaFuncSetAttribute(hmma_gemm2, cudaFuncAttributeMaxDynamicSharedMemorySize, G2_SMEM);

    prep_kernel<<<NB_TOTAL, 256>>>(xyz1, xyz2, points1, points2, w0, w1);
    gather_kernel<<<BB * NN / 8, 256>>>();

    hmma_gemm1<<<dim3(HH / 128, NN / 128, BB), 256, G1_SMEM>>>(
        p_W0, p_FT, b0, p_X0);
    stats_final_kernel<<<1, HH>>>(p_sum0, p_sq0, g0, be0, p_scale0, p_shift0);

    hmma_gemm2<<<dim3(HH / 128, NN / 128, BB), 256, G2_SMEM>>>(
        p_W1, p_X0, p_scale0, p_shift0, b1, out);
    stats_final_kernel<<<1, HH>>>(p_sum1, p_sq1, g1, be1, p_scale1, p_shift1);
    apply_bn_kernel<<<4096, 256>>>(out);
}

// round 13
// speedup vs baseline: 2.0279x; 1.0213x over previous
#include <cuda_runtime.h>
#include <cuda_fp16.h>
#include <cstdint>

// Problem constants
#define BB 8
#define NN 8192
#define SS 2048
#define D1 256
#define D2 512
#define CIN 768
#define HH 512

typedef __half h16;

// ---------------- scratch (static device globals; no runtime alloc) ----------------
__device__ h16  g_P2T[(size_t)BB * SS * D2];           // fp16
__device__ int   g_idx[(size_t)BB * NN * 3];
__device__ float g_wgt[(size_t)BB * NN * 3];
__device__ h16  g_FT[(size_t)BB * NN * CIN];           // single fp16
__device__ h16  g_W0[HH * CIN];                        // single fp16
__device__ h16  g_W1[HH * HH];                         // single fp16
__device__ h16  g_X0[(size_t)BB * HH * NN];            // (b, c, n) fp16
__device__ float g_sum0[HH], g_sq0[HH], g_sum1[HH], g_sq1[HH];

// ======================= low-level helpers =======================
__device__ __forceinline__ uint32_t smem_u32(const void* p) {
    uint32_t a;
    asm("{ .reg .u64 t; cvta.to.shared.u64 t, %1; cvt.u32.u64 %0, t; }" : "=r"(a) : "l"(p));
    return a;
}
__device__ __forceinline__ void ldsm4(uint32_t& r0, uint32_t& r1, uint32_t& r2,
                                      uint32_t& r3, uint32_t a) {
    asm volatile("ldmatrix.sync.aligned.m8n8.x4.shared.b16 {%0,%1,%2,%3},[%4];"
                 : "=r"(r0), "=r"(r1), "=r"(r2), "=r"(r3) : "r"(a));
}
__device__ __forceinline__ void ldsm4t(uint32_t& r0, uint32_t& r1, uint32_t& r2,
                                       uint32_t& r3, uint32_t a) {
    asm volatile("ldmatrix.sync.aligned.m8n8.x4.trans.shared.b16 {%0,%1,%2,%3},[%4];"
                 : "=r"(r0), "=r"(r1), "=r"(r2), "=r"(r3) : "r"(a));
}
__device__ __forceinline__ void mma16816(float* d, const uint32_t* a, const uint32_t* b) {
    asm volatile(
        "mma.sync.aligned.m16n8k16.row.col.f32.f16.f16.f32 "
        "{%0,%1,%2,%3},{%4,%5,%6,%7},{%8,%9},{%0,%1,%2,%3};"
        : "+f"(d[0]), "+f"(d[1]), "+f"(d[2]), "+f"(d[3])
        : "r"(a[0]), "r"(a[1]), "r"(a[2]), "r"(a[3]), "r"(b[0]), "r"(b[1]));
}
__device__ __forceinline__ void cpa16(uint32_t dst, const void* src) {
    asm volatile("cp.async.cg.shared.global [%0],[%1],16;" :: "r"(dst), "l"(src));
}
#define CP_COMMIT() asm volatile("cp.async.commit_group;" ::: "memory")
#define CP_WAIT(n) asm volatile("cp.async.wait_group %0;" :: "n"(n) : "memory")

__device__ __forceinline__ uint32_t pack2h(h16 a, h16 b) {
    __half2 t = __halves2half2(a, b);
    return *reinterpret_cast<uint32_t*>(&t);
}
__device__ __forceinline__ float2 h2f2(uint32_t u) {
    return __half22float2(*reinterpret_cast<__half2*>(&u));
}

// ---------------- top-3 helper ----------------
struct Top3 { float d0, d1, d2; int i0, i1, i2; };
__device__ __forceinline__ void t3_ins(Top3& q, float t, int s) {
    if (t < q.d2) {
        if (t < q.d1) {
            q.d2 = q.d1; q.i2 = q.i1;
            if (t < q.d0) { q.d1 = q.d0; q.i1 = q.i0; q.d0 = t; q.i0 = s; }
            else          { q.d1 = t;    q.i1 = s; }
        } else { q.d2 = t; q.i2 = s; }
    }
}

// ======================= fused prep kernel =======================
#define NB_T3 128
#define NB_P2 8192
#define NB_P1 16384
#define NB_C0 (HH * CIN / 1024)
#define NB_C1 (HH * HH / 1024)
#define NB_TOTAL (NB_T3 + NB_P2 + NB_P1 + NB_C0 + NB_C1 + 1)

__global__ __launch_bounds__(256)
void prep_kernel(const float* __restrict__ xyz1, const float* __restrict__ xyz2,
                 const float* __restrict__ p1, const float* __restrict__ p2,
                 const float* __restrict__ w0g, const float* __restrict__ w1g) {
    __shared__ float sh[8192];
    int r = blockIdx.x;
    const int tid = threadIdx.x;

    if (r < NB_T3) {
        float* sx = sh;
        float* sy = sh + 2048;
        float* sz = sh + 4096;
        float* sn = sh + 6144;
        const int b = r >> 4;
        const int nbase = (r & 15) * 512;

        for (int i = tid; i < SS; i += 256) {
            float x = xyz2[((size_t)b * 3 + 0) * SS + i];
            float y = xyz2[((size_t)b * 3 + 1) * SS + i];
            float z = xyz2[((size_t)b * 3 + 2) * SS + i];
            sx[i] = x; sy[i] = y; sz[i] = z;
            sn[i] = x * x + y * y + z * z;
        }
        __syncthreads();

        const int na = nbase + tid;
        const int nb = nbase + 256 + tid;
        float xa = xyz1[((size_t)b * 3 + 0) * NN + na];
        float ya = xyz1[((size_t)b * 3 + 1) * NN + na];
        float za = xyz1[((size_t)b * 3 + 2) * NN + na];
        float xb = xyz1[((size_t)b * 3 + 0) * NN + nb];
        float yb = xyz1[((size_t)b * 3 + 1) * NN + nb];
        float zb = xyz1[((size_t)b * 3 + 2) * NN + nb];
        float n1a = xa * xa + ya * ya + za * za;
        float n1b = xb * xb + yb * yb + zb * zb;
        float mxa = -2.f * xa, mya = -2.f * ya, mza = -2.f * za;
        float mxb = -2.f * xb, myb = -2.f * yb, mzb = -2.f * zb;

        Top3 qa = {3.4e38f, 3.4e38f, 3.4e38f, 0, 0, 0};
        Top3 qb = {3.4e38f, 3.4e38f, 3.4e38f, 0, 0, 0};

        for (int s = 0; s < SS; s += 4) {
            float4 vx = ((float4*)sx)[s >> 2], vy = ((float4*)sy)[s >> 2];
            float4 vz = ((float4*)sz)[s >> 2], vn = ((float4*)sn)[s >> 2];
            float t;
            t = fmaf(mxa, vx.x, vn.x); t = fmaf(mya, vy.x, t); t = fmaf(mza, vz.x, t); t3_ins(qa, t, s + 0);
            t = fmaf(mxa, vx.y, vn.y); t = fmaf(mya, vy.y, t); t = fmaf(mza, vz.y, t); t3_ins(qa, t, s + 1);
            t = fmaf(mxa, vx.z, vn.z); t = fmaf(mya, vy.z, t); t = fmaf(mza, vz.z, t); t3_ins(qa, t, s + 2);
            t = fmaf(mxa, vx.w, vn.w); t = fmaf(mya, vy.w, t); t = fmaf(mza, vz.w, t); t3_ins(qa, t, s + 3);
            t = fmaf(mxb, vx.x, vn.x); t = fmaf(myb, vy.x, t); t = fmaf(mzb, vz.x, t); t3_ins(qb, t, s + 0);
            t = fmaf(mxb, vx.y, vn.y); t = fmaf(myb, vy.y, t); t = fmaf(mzb, vz.y, t); t3_ins(qb, t, s + 1);
            t = fmaf(mxb, vx.z, vn.z); t = fmaf(myb, vy.z, t); t = fmaf(mzb, vz.z, t); t3_ins(qb, t, s + 2);
            t = fmaf(mxb, vx.w, vn.w); t = fmaf(myb, vy.w, t); t = fmaf(mzb, vz.w, t); t3_ins(qb, t, s + 3);
        }

        {
            size_t base = ((size_t)b * NN + na) * 3;
            float d0 = qa.d0 + n1a, d1 = qa.d1 + n1a, d2 = qa.d2 + n1a;
            float w0 = 1.0f / (d0 + 1e-8f), w1 = 1.0f / (d1 + 1e-8f), w2 = 1.0f / (d2 + 1e-8f);
            float inv = 1.0f / (w0 + w1 + w2);
            g_idx[base + 0] = qa.i0; g_idx[base + 1] = qa.i1; g_idx[base + 2] = qa.i2;
            g_wgt[base + 0] = w0 * inv; g_wgt[base + 1] = w1 * inv; g_wgt[base + 2] = w2 * inv;
        }
        {
            size_t base = ((size_t)b * NN + nb) * 3;
            float d0 = qb.d0 + n1b, d1 = qb.d1 + n1b, d2 = qb.d2 + n1b;
            float w0 = 1.0f / (d0 + 1e-8f), w1 = 1.0f / (d1 + 1e-8f), w2 = 1.0f / (d2 + 1e-8f);
            float inv = 1.0f / (w0 + w1 + w2);
            g_idx[base + 0] = qb.i0; g_idx[base + 1] = qb.i1; g_idx[base + 2] = qb.i2;
            g_wgt[base + 0] = w0 * inv; g_wgt[base + 1] = w1 * inv; g_wgt[base + 2] = w2 * inv;
        }
        return;
    }
    r -= NB_T3;
    if (r < NB_P2) {
        int b = r >> 10, y = (r >> 6) & 15, x = r & 63;
        int c0 = y * 32, s0 = x * 32;
        int tx = tid & 31, ty = tid >> 5;
        float (*t)[33] = (float(*)[33])sh;
#pragma unroll
        for (int j = ty; j < 32; j += 8)
            t[j][tx] = p2[((size_t)b * D2 + c0 + j) * SS + s0 + tx];
        __syncthreads();
#pragma unroll
        for (int j = ty; j < 32; j += 8)
            g_P2T[((size_t)b * SS + s0 + j) * D2 + c0 + tx] = __float2half_rn(t[tx][j]);
        return;
    }
    r -= NB_P2;
    if (r < NB_P1) {
        int b = r >> 11, y = (r >> 8) & 7, x = r & 255;
        int c0 = y * 32, n0 = x * 32;
        int tx = tid & 31, ty = tid >> 5;
        float (*t)[33] = (float(*)[33])sh;
#pragma unroll
        for (int j = ty; j < 32; j += 8)
            t[j][tx] = p1[((size_t)b * D1 + c0 + j) * NN + n0 + tx];
        __syncthreads();
#pragma unroll
        for (int j = ty; j < 32; j += 8) {
            size_t off = ((size_t)b * NN + n0 + j) * CIN + c0 + tx;
            g_FT[off] = __float2half_rn(t[tx][j]);
        }
        return;
    }
    r -= NB_P1;
    if (r < NB_C0 + NB_C1) {
        const float* src;
        h16* dst;
        int i;
        if (r < NB_C0) { src = w0g; dst = g_W0; i = r * 1024 + tid * 4; }
        else { src = w1g; dst = g_W1; i = (r - NB_C0) * 1024 + tid * 4; }
        float4 v = *(const float4*)(src + i);
        *(uint2*)&dst[i] = make_uint2(
            pack2h(__float2half_rn(v.x), __float2half_rn(v.y)),
            pack2h(__float2half_rn(v.z), __float2half_rn(v.w)));
        return;
    }
    if (tid < 256) {
        g_sum0[tid] = 0.f; g_sum0[tid + 256] = 0.f;
        g_sq0[tid] = 0.f;  g_sq0[tid + 256] = 0.f;
        g_sum1[tid] = 0.f; g_sum1[tid + 256] = 0.f;
        g_sq1[tid] = 0.f;  g_sq1[tid + 256] = 0.f;
    }
}

// ---------------- gather + interpolate -> g_FT[:, :, 256:768] (fp16 in/out) ----------------
__global__ void gather_kernel() {
    int wglob = blockIdx.x * 8 + (threadIdx.x >> 5);
    int lane = threadIdx.x & 31;
    int b = wglob / NN;
    size_t base = (size_t)wglob * 3;
    int i0 = g_idx[base + 0], i1 = g_idx[base + 1], i2 = g_idx[base + 2];
    float w0 = g_wgt[base + 0], w1 = g_wgt[base + 1], w2 = g_wgt[base + 2];
    const h16* r0 = g_P2T + ((size_t)b * SS + i0) * D2;
    const h16* r1 = g_P2T + ((size_t)b * SS + i1) * D2;
    const h16* r2 = g_P2T + ((size_t)b * SS + i2) * D2;
    size_t dbase = (size_t)wglob * CIN + D1;
#pragma unroll
    for (int c = lane * 4; c < D2; c += 128) {
        uint2 u0 = *(const uint2*)&r0[c];
        uint2 u1 = *(const uint2*)&r1[c];
        uint2 u2 = *(const uint2*)&r2[c];
        float2 a0 = h2f2(u0.x), a1 = h2f2(u0.y);
        float2 b0 = h2f2(u1.x), b1 = h2f2(u1.y);
        float2 c0 = h2f2(u2.x), c1 = h2f2(u2.y);
        float o0 = w0 * a0.x + w1 * b0.x + w2 * c0.x;
        float o1 = w0 * a0.y + w1 * b0.y + w2 * c0.y;
        float o2 = w0 * a1.x + w1 * b1.x + w2 * c1.x;
        float o3 = w0 * a1.y + w1 * b1.y + w2 * c1.y;
        *(uint2*)&g_FT[dbase + c] = make_uint2(
            pack2h(__float2half_rn(o0), __float2half_rn(o1)),
            pack2h(__float2half_rn(o2), __float2half_rn(o3)));
    }
}

// ======================= HMMA GEMM 1 (pure fp16, ring-3, R5 sync scheme) =======================
#define T1 10240                          // bytes per tile (128 rows x 80B)
#define ST1 (2 * T1)                      // stage: A, B = 20480
static constexpr int G1_SMEM = 3 * ST1;   // 61440 -> 2 CTAs/SM

__global__ __launch_bounds__(256, 2)
void hmma_gemm1(const h16* __restrict__ Ag, const h16* __restrict__ Bg,
                const float* __restrict__ bias, h16* __restrict__ out) {
    extern __shared__ char smem[];
    const uint32_t sb = smem_u32(smem);
    const int tid = threadIdx.x, lane = tid & 31, wid = tid >> 5;
    const int m0 = blockIdx.x * 128, n0 = blockIdx.y * 128, b = blockIdx.z;
    const int wm = (wid & 3) * 32, wn = (wid >> 2) * 64;

    const h16* Arow = Ag + (size_t)m0 * CIN;
    const h16* Brow = Bg + ((size_t)b * NN + n0) * CIN;

    float acc[2][8][4];
#pragma unroll
    for (int i = 0; i < 2; i++)
#pragma unroll
        for (int j = 0; j < 8; j++)
#pragma unroll
            for (int q = 0; q < 4; q++) acc[i][j][q] = 0.f;

    const int row_l = tid >> 2, c16 = (tid & 3);
    auto issue = [&](int kc) {
        const int kb = kc * 32;
        const uint32_t sbuf = sb + (kc % 3) * ST1;
#pragma unroll
        for (int t = 0; t < 2; t++) {
            int row = row_l + t * 64;
            uint32_t d = sbuf + row * 80 + c16 * 16;
            cpa16(d,      Arow + (size_t)row * CIN + kb + c16 * 8);
            cpa16(d + T1, Brow + (size_t)row * CIN + kb + c16 * 8);
        }
        CP_COMMIT();
    };

    const int KT = CIN / 32;   // 24
    issue(0);
    issue(1);

    for (int c = 0; c < KT; c++) {
        if (c + 2 < KT) {
            issue(c + 2);      // buffer (c+2)%3 == (c-1)%3, freed by trailing sync of c-1
            CP_WAIT(2);        // group c complete; c+1, c+2 in flight
        } else if (c + 1 < KT) {
            CP_WAIT(1);
        } else {
            CP_WAIT(0);
        }
        __syncthreads();

        const uint32_t sA = sb + (c % 3) * ST1;
        const uint32_t sB = sA + T1;
#pragma unroll
        for (int ks = 0; ks < 2; ks++) {
            const int k16 = ks * 16;
            uint32_t ah[2][4];
#pragma unroll
            for (int mi = 0; mi < 2; mi++) {
                uint32_t ad = sA + (wm + mi * 16 + (lane & 15)) * 80
                                 + (k16 + ((lane >> 4) << 3)) * 2;
                ldsm4(ah[mi][0], ah[mi][1], ah[mi][2], ah[mi][3], ad);
            }
#pragma unroll
            for (int ng = 0; ng < 4; ng++) {
                uint32_t row = wn + ng * 16 + (lane & 7) + ((lane & 16) >> 1);
                uint32_t col = k16 + (lane & 8);
                uint32_t ad = sB + row * 80 + col * 2;
                uint32_t bh[4];
                ldsm4(bh[0], bh[1], bh[2], bh[3], ad);
#pragma unroll
                for (int mi = 0; mi < 2; mi++) {
                    mma16816(acc[mi][2 * ng],     ah[mi], bh);
                    mma16816(acc[mi][2 * ng + 1], ah[mi], bh + 2);
                }
            }
        }
        __syncthreads();
    }

    // epilogue -> out fp16 (b, m, n) + bias, fused channel stats via atomics
    const int gq = lane >> 2, tq = lane & 3;
#pragma unroll
    for (int mi = 0; mi < 2; mi++) {
        int r0 = m0 + wm + mi * 16 + gq;
        float bv0 = bias[r0], bv1 = bias[r0 + 8];
        h16* o0 = out + ((size_t)b * HH + r0) * NN;
        h16* o1 = o0 + (size_t)8 * NN;
        float s0 = 0.f, q0 = 0.f, s1 = 0.f, q1 = 0.f;
#pragma unroll
        for (int ni = 0; ni < 8; ni++) {
            int cc = n0 + wn + ni * 8 + tq * 2;
            float y0 = acc[mi][ni][0] + bv0, y1 = acc[mi][ni][1] + bv0;
            float y2 = acc[mi][ni][2] + bv1, y3 = acc[mi][ni][3] + bv1;
            *(uint32_t*)&o0[cc] = pack2h(__float2half_rn(y0), __float2half_rn(y1));
            *(uint32_t*)&o1[cc] = pack2h(__float2half_rn(y2), __float2half_rn(y3));
            s0 += y0 + y1; q0 += y0 * y0 + y1 * y1;
            s1 += y2 + y3; q1 += y2 * y2 + y3 * y3;
        }
#pragma unroll
        for (int o = 1; o <= 2; o <<= 1) {
            s0 += __shfl_xor_sync(~0u, s0, o);
            q0 += __shfl_xor_sync(~0u, q0, o);
            s1 += __shfl_xor_sync(~0u, s1, o);
            q1 += __shfl_xor_sync(~0u, q1, o);
        }
        if (tq == 0) {
            atomicAdd(&g_sum0[r0], s0);     atomicAdd(&g_sq0[r0], q0);
            atomicAdd(&g_sum0[r0 + 8], s1); atomicAdd(&g_sq0[r0 + 8], q1);
        }
    }
}

// ======================= HMMA GEMM 2 (pure fp16, ring-3 A, in-kernel BN coeffs) =======================
#define AT2 10240                // A stage (single fp16)
#define BT2 8704                 // 32 * 272, single fp16
#define SC2_OFF (3 * AT2 + 2 * BT2)                  // scale/shift smem offset
static constexpr int G2_SMEM = SC2_OFF + 2 * HH * 4; // 48128 + 4096 = 52224

__global__ __launch_bounds__(256, 2)
void hmma_gemm2(const h16* __restrict__ Ag,
                const h16* __restrict__ X0,
                const float* __restrict__ gsum, const float* __restrict__ gsq,
                const float* __restrict__ g0, const float* __restrict__ be0,
                const float* __restrict__ bias, float* __restrict__ out) {
    extern __shared__ char smem[];
    const uint32_t sb = smem_u32(smem);
    const int tid = threadIdx.x, lane = tid & 31, wid = tid >> 5;
    const int m0 = blockIdx.x * 128, n0 = blockIdx.y * 128, b = blockIdx.z;
    const int wm = (wid & 3) * 32, wn = (wid >> 2) * 64;

    float* sScale = (float*)(smem + SC2_OFF);
    float* sShift = sScale + HH;

    const h16* Arow = Ag + (size_t)m0 * HH;
    const h16* Xb = X0 + (size_t)b * HH * NN + n0;

    float acc[2][8][4];
#pragma unroll
    for (int i = 0; i < 2; i++)
#pragma unroll
        for (int j = 0; j < 8; j++)
#pragma unroll
            for (int q = 0; q < 4; q++) acc[i][j][q] = 0.f;

    const int brow = tid >> 3, bcol = (tid & 7) * 16;
    float x[16];
    float scl, shf;

    const int row_l = tid >> 2, c16 = (tid & 3);
    auto issueA = [&](int kc) {
        const int kb = kc * 32;
        const uint32_t sbuf = sb + (kc % 3) * AT2;
#pragma unroll
        for (int t = 0; t < 2; t++) {
            int row = row_l + t * 64;
            uint32_t d = sbuf + row * 80 + c16 * 16;
            cpa16(d, Arow + (size_t)row * HH + kb + c16 * 8);
        }
        CP_COMMIT();
    };
    auto loadX = [&](int kb) {
        const h16* src = Xb + (size_t)(kb + brow) * NN + bcol;
        uint4 u0 = *(const uint4*)src;
        uint4 u1 = *(const uint4*)(src + 8);
        float2 p;
        p = h2f2(u0.x); x[0] = p.x; x[1] = p.y;
        p = h2f2(u0.y); x[2] = p.x; x[3] = p.y;
        p = h2f2(u0.z); x[4] = p.x; x[5] = p.y;
        p = h2f2(u0.w); x[6] = p.x; x[7] = p.y;
        p = h2f2(u1.x); x[8] = p.x; x[9] = p.y;
        p = h2f2(u1.y); x[10] = p.x; x[11] = p.y;
        p = h2f2(u1.z); x[12] = p.x; x[13] = p.y;
        p = h2f2(u1.w); x[14] = p.x; x[15] = p.y;
        scl = sScale[kb + brow];
        shf = sShift[kb + brow];
    };

    // prologue: BN coefficients for layer 0 -> smem (from fused GEMM1 stats)
    {
        const float inv = 1.f / (float)(BB * NN);
#pragma unroll
        for (int i = tid; i < HH; i += 256) {
            float m = gsum[i] * inv;
            float var = gsq[i] * inv - m * m;
            float sc = g0[i] * rsqrtf(var + 1e-5f);
            sScale[i] = sc;
            sShift[i] = be0[i] - m * sc;
        }
        issueA(0);
        issueA(1);
        __syncthreads();   // sScale/sShift visible before loadX
        loadX(0);
    }

    const uint32_t sBoff = 3 * AT2;
    const int KT = HH / 32;  // 16
    for (int c = 0; c < KT; c++) {
        const int buf = c & 1;
        {
            uint32_t doff = sBoff + buf * BT2 + brow * 272 + bcol * 2;
#pragma unroll
            for (int j = 0; j < 4; j++) {
                float y0 = fmaxf(fmaf(x[4 * j + 0], scl, shf), 0.f);
                float y1 = fmaxf(fmaf(x[4 * j + 1], scl, shf), 0.f);
                float y2 = fmaxf(fmaf(x[4 * j + 2], scl, shf), 0.f);
                float y3 = fmaxf(fmaf(x[4 * j + 3], scl, shf), 0.f);
                *(uint2*)(smem + doff + j * 8) = make_uint2(
                    pack2h(__float2half_rn(y0), __float2half_rn(y1)),
                    pack2h(__float2half_rn(y2), __float2half_rn(y3)));
            }
        }
        if (c + 2 < KT) {
            issueA(c + 2);
            loadX((c + 1) * 32);
            CP_WAIT(2);
        } else if (c + 1 < KT) {
            loadX((c + 1) * 32);
            CP_WAIT(1);
        } else {
            CP_WAIT(0);
        }
        __syncthreads();

        const uint32_t sA = sb + (c % 3) * AT2;
        const uint32_t sB = sb + sBoff + buf * BT2;
#pragma unroll
        for (int ks = 0; ks < 2; ks++) {
            const int k16 = ks * 16;
            uint32_t ah[2][4];
#pragma unroll
            for (int mi = 0; mi < 2; mi++) {
                uint32_t ad = sA + (wm + mi * 16 + (lane & 15)) * 80
                                 + (k16 + ((lane >> 4) << 3)) * 2;
                ldsm4(ah[mi][0], ah[mi][1], ah[mi][2], ah[mi][3], ad);
            }
#pragma unroll
            for (int ng = 0; ng < 4; ng++) {
                uint32_t row = k16 + (lane & 7) + (lane & 8);
                uint32_t col = wn + ng * 16 + ((lane >> 4) << 3);
                uint32_t ad = sB + row * 272 + col * 2;
                uint32_t bh[4];
                ldsm4t(bh[0], bh[1], bh[2], bh[3], ad);
#pragma unroll
                for (int mi = 0; mi < 2; mi++) {
                    mma16816(acc[mi][2 * ng],     ah[mi], bh);
                    mma16816(acc[mi][2 * ng + 1], ah[mi], bh + 2);
                }
            }
        }
        __syncthreads();
    }

    const int gq = lane >> 2, tq = lane & 3;
#pragma unroll
    for (int mi = 0; mi < 2; mi++) {
        int r0 = m0 + wm + mi * 16 + gq;
        float bv0 = bias[r0], bv1 = bias[r0 + 8];
        float* o0 = out + ((size_t)b * HH + r0) * NN;
        float* o1 = o0 + (size_t)8 * NN;
        float s0 = 0.f, q0 = 0.f, s1 = 0.f, q1 = 0.f;
#pragma unroll
        for (int ni = 0; ni < 8; ni++) {
            int cc = n0 + wn + ni * 8 + tq * 2;
            float y0 = acc[mi][ni][0] + bv0, y1 = acc[mi][ni][1] + bv0;
            float y2 = acc[mi][ni][2] + bv1, y3 = acc[mi][ni][3] + bv1;
            *(float2*)&o0[cc] = make_float2(y0, y1);
            *(float2*)&o1[cc] = make_float2(y2, y3);
            s0 += y0 + y1; q0 += y0 * y0 + y1 * y1;
            s1 += y2 + y3; q1 += y2 * y2 + y3 * y3;
        }
#pragma unroll
        for (int o = 1; o <= 2; o <<= 1) {
            s0 += __shfl_xor_sync(~0u, s0, o);
            q0 += __shfl_xor_sync(~0u, q0, o);
            s1 += __shfl_xor_sync(~0u, s1, o);
            q1 += __shfl_xor_sync(~0u, q1, o);
        }
        if (tq == 0) {
            atomicAdd(&g_sum1[r0], s0);     atomicAdd(&g_sq1[r0], q0);
            atomicAdd(&g_sum1[r0 + 8], s1); atomicAdd(&g_sq1[r0 + 8], q1);
        }
    }
}

// ---------------- apply BN layer1 (coeffs computed in-kernel) ----------------
__global__ __launch_bounds__(256)
void apply_bn_kernel(float* __restrict__ X,
                     const float* __restrict__ g1, const float* __restrict__ be1) {
    __shared__ float sScale[HH], sShift[HH];
    const float inv = 1.f / (float)(BB * NN);
#pragma unroll
    for (int i = threadIdx.x; i < HH; i += 256) {
        float m = g_sum1[i] * inv;
        float var = g_sq1[i] * inv - m * m;
        float sc = g1[i] * rsqrtf(var + 1e-5f);
        sScale[i] = sc;
        sShift[i] = be1[i] - m * sc;
    }
    __syncthreads();
    const size_t total4 = (size_t)BB * HH * NN / 4;
    for (size_t i = (size_t)blockIdx.x * blockDim.x + threadIdx.x; i < total4;
         i += (size_t)gridDim.x * blockDim.x) {
        float4 v = __ldcs(&((float4*)X)[i]);
        int c = (int)((i * 4) >> 13) & (HH - 1);
        float s = sScale[c], h = sShift[c];
        v.x = fmaxf(fmaf(v.x, s, h), 0.f);
        v.y = fmaxf(fmaf(v.y, s, h), 0.f);
        v.z = fmaxf(fmaf(v.z, s, h), 0.f);
        v.w = fmaxf(fmaf(v.w, s, h), 0.f);
        __stcs(&((float4*)X)[i], v);
    }
}

// ======================= launcher =======================
extern "C" void kernel_launch(void* const* d_in, const int* in_sizes, int n_in,
                              void* d_out, int out_size) {
    const float* xyz1    = (const float*)d_in[0];
    const float* xyz2    = (const float*)d_in[1];
    const float* points1 = (const float*)d_in[2];
    const float* points2 = (const float*)d_in[3];
    const float* w0 = (const float*)d_in[4];
    const float* b0 = (const float*)d_in[5];
    const float* g0 = (const float*)d_in[6];
    const float* be0 = (const float*)d_in[7];
    const float* w1 = (const float*)d_in[8];
    const float* b1 = (const float*)d_in[9];
    const float* g1 = (const float*)d_in[10];
    const float* be1 = (const float*)d_in[11];
    float* out = (float*)d_out;

    float *p_sum0, *p_sq0;
    h16 *p_W0, *p_W1, *p_FT, *p_X0;
    cudaGetSymbolAddress((void**)&p_X0, g_X0);
    cudaGetSymbolAddress((void**)&p_sum0, g_sum0);
    cudaGetSymbolAddress((void**)&p_sq0, g_sq0);
    cudaGetSymbolAddress((void**)&p_W0, g_W0);
    cudaGetSymbolAddress((void**)&p_W1, g_W1);
    cudaGetSymbolAddress((void**)&p_FT, g_FT);

    cudaFuncSetAttribute(hmma_gemm1, cudaFuncAttributeMaxDynamicSharedMemorySize, G1_SMEM);
    cudaFuncSetAttribute(hmma_gemm2, cudaFuncAttributeMaxDynamicSharedMemorySize, G2_SMEM);

    prep_kernel<<<NB_TOTAL, 256>>>(xyz1, xyz2, points1, points2, w0, w1);
    gather_kernel<<<BB * NN / 8, 256>>>();

    hmma_gemm1<<<dim3(HH / 128, NN / 128, BB), 256, G1_SMEM>>>(
        p_W0, p_FT, b0, p_X0);

    hmma_gemm2<<<dim3(HH / 128, NN / 128, BB), 256, G2_SMEM>>>(
        p_W1, p_X0, p_sum0, p_sq0, g0, be0, b1, out);

    apply_bn_kernel<<<4096, 256>>>(out, g1, be1);
}

// round 14
// speedup vs baseline: 2.2428x; 1.1060x over previous
#include <cuda_runtime.h>
#include <cuda_fp16.h>
#include <cstdint>

// Problem constants
#define BB 8
#define NN 8192
#define SS 2048
#define D1 256
#define D2 512
#define CIN 768
#define HH 512

typedef __half h16;

// ---------------- scratch (static device globals; no runtime alloc) ----------------
__device__ h16  g_P2T[(size_t)BB * SS * D2];           // fp16
__device__ int   g_idx[(size_t)BB * NN * 3];
__device__ float g_wgt[(size_t)BB * NN * 3];
__device__ h16  g_FT[(size_t)BB * NN * CIN];           // single fp16
__device__ h16  g_W0[HH * CIN];                        // single fp16
__device__ h16  g_W1[HH * HH];                         // single fp16
__device__ h16  g_X0[(size_t)BB * HH * NN];            // (b, c, n) fp16
__device__ float g_sum0[HH], g_sq0[HH], g_sum1[HH], g_sq1[HH];

// ======================= low-level helpers =======================
__device__ __forceinline__ uint32_t smem_u32(const void* p) {
    uint32_t a;
    asm("{ .reg .u64 t; cvta.to.shared.u64 t, %1; cvt.u32.u64 %0, t; }" : "=r"(a) : "l"(p));
    return a;
}
__device__ __forceinline__ void ldsm4(uint32_t& r0, uint32_t& r1, uint32_t& r2,
                                      uint32_t& r3, uint32_t a) {
    asm volatile("ldmatrix.sync.aligned.m8n8.x4.shared.b16 {%0,%1,%2,%3},[%4];"
                 : "=r"(r0), "=r"(r1), "=r"(r2), "=r"(r3) : "r"(a));
}
__device__ __forceinline__ void ldsm4t(uint32_t& r0, uint32_t& r1, uint32_t& r2,
                                       uint32_t& r3, uint32_t a) {
    asm volatile("ldmatrix.sync.aligned.m8n8.x4.trans.shared.b16 {%0,%1,%2,%3},[%4];"
                 : "=r"(r0), "=r"(r1), "=r"(r2), "=r"(r3) : "r"(a));
}
__device__ __forceinline__ void mma16816(float* d, const uint32_t* a, const uint32_t* b) {
    asm volatile(
        "mma.sync.aligned.m16n8k16.row.col.f32.f16.f16.f32 "
        "{%0,%1,%2,%3},{%4,%5,%6,%7},{%8,%9},{%0,%1,%2,%3};"
        : "+f"(d[0]), "+f"(d[1]), "+f"(d[2]), "+f"(d[3])
        : "r"(a[0]), "r"(a[1]), "r"(a[2]), "r"(a[3]), "r"(b[0]), "r"(b[1]));
}
__device__ __forceinline__ void cpa16(uint32_t dst, const void* src) {
    asm volatile("cp.async.cg.shared.global [%0],[%1],16;" :: "r"(dst), "l"(src));
}
#define CP_COMMIT() asm volatile("cp.async.commit_group;" ::: "memory")
#define CP_WAIT(n) asm volatile("cp.async.wait_group %0;" :: "n"(n) : "memory")

__device__ __forceinline__ uint32_t pack2h(h16 a, h16 b) {
    __half2 t = __halves2half2(a, b);
    return *reinterpret_cast<uint32_t*>(&t);
}
__device__ __forceinline__ float2 h2f2(uint32_t u) {
    return __half22float2(*reinterpret_cast<__half2*>(&u));
}

// ---------------- top-3 helper ----------------
struct Top3 { float d0, d1, d2; int i0, i1, i2; };
__device__ __forceinline__ void t3_ins(Top3& q, float t, int s) {
    if (t < q.d2) {
        if (t < q.d1) {
            q.d2 = q.d1; q.i2 = q.i1;
            if (t < q.d0) { q.d1 = q.d0; q.i1 = q.i0; q.d0 = t; q.i0 = s; }
            else          { q.d1 = t;    q.i1 = s; }
        } else { q.d2 = t; q.i2 = s; }
    }
}

// ======================= fused prep kernel =======================
#define NB_T3 128
#define NB_P2 8192
#define NB_P1 16384
#define NB_C0 (HH * CIN / 1024)
#define NB_C1 (HH * HH / 1024)
#define NB_TOTAL (NB_T3 + NB_P2 + NB_P1 + NB_C0 + NB_C1 + 1)

__global__ __launch_bounds__(256)
void prep_kernel(const float* __restrict__ xyz1, const float* __restrict__ xyz2,
                 const float* __restrict__ p1, const float* __restrict__ p2,
                 const float* __restrict__ w0g, const float* __restrict__ w1g) {
    __shared__ float sh[8192];
    int r = blockIdx.x;
    const int tid = threadIdx.x;

    if (r < NB_T3) {
        float* sx = sh;
        float* sy = sh + 2048;
        float* sz = sh + 4096;
        float* sn = sh + 6144;
        const int b = r >> 4;
        const int nbase = (r & 15) * 512;

        for (int i = tid; i < SS; i += 256) {
            float x = xyz2[((size_t)b * 3 + 0) * SS + i];
            float y = xyz2[((size_t)b * 3 + 1) * SS + i];
            float z = xyz2[((size_t)b * 3 + 2) * SS + i];
            sx[i] = x; sy[i] = y; sz[i] = z;
            sn[i] = x * x + y * y + z * z;
        }
        __syncthreads();

        const int na = nbase + tid;
        const int nb = nbase + 256 + tid;
        float xa = xyz1[((size_t)b * 3 + 0) * NN + na];
        float ya = xyz1[((size_t)b * 3 + 1) * NN + na];
        float za = xyz1[((size_t)b * 3 + 2) * NN + na];
        float xb = xyz1[((size_t)b * 3 + 0) * NN + nb];
        float yb = xyz1[((size_t)b * 3 + 1) * NN + nb];
        float zb = xyz1[((size_t)b * 3 + 2) * NN + nb];
        float n1a = xa * xa + ya * ya + za * za;
        float n1b = xb * xb + yb * yb + zb * zb;
        float mxa = -2.f * xa, mya = -2.f * ya, mza = -2.f * za;
        float mxb = -2.f * xb, myb = -2.f * yb, mzb = -2.f * zb;

        Top3 qa = {3.4e38f, 3.4e38f, 3.4e38f, 0, 0, 0};
        Top3 qb = {3.4e38f, 3.4e38f, 3.4e38f, 0, 0, 0};

        for (int s = 0; s < SS; s += 4) {
            float4 vx = ((float4*)sx)[s >> 2], vy = ((float4*)sy)[s >> 2];
            float4 vz = ((float4*)sz)[s >> 2], vn = ((float4*)sn)[s >> 2];
            float t;
            t = fmaf(mxa, vx.x, vn.x); t = fmaf(mya, vy.x, t); t = fmaf(mza, vz.x, t); t3_ins(qa, t, s + 0);
            t = fmaf(mxa, vx.y, vn.y); t = fmaf(mya, vy.y, t); t = fmaf(mza, vz.y, t); t3_ins(qa, t, s + 1);
            t = fmaf(mxa, vx.z, vn.z); t = fmaf(mya, vy.z, t); t = fmaf(mza, vz.z, t); t3_ins(qa, t, s + 2);
            t = fmaf(mxa, vx.w, vn.w); t = fmaf(mya, vy.w, t); t = fmaf(mza, vz.w, t); t3_ins(qa, t, s + 3);
            t = fmaf(mxb, vx.x, vn.x); t = fmaf(myb, vy.x, t); t = fmaf(mzb, vz.x, t); t3_ins(qb, t, s + 0);
            t = fmaf(mxb, vx.y, vn.y); t = fmaf(myb, vy.y, t); t = fmaf(mzb, vz.y, t); t3_ins(qb, t, s + 1);
            t = fmaf(mxb, vx.z, vn.z); t = fmaf(myb, vy.z, t); t = fmaf(mzb, vz.z, t); t3_ins(qb, t, s + 2);
            t = fmaf(mxb, vx.w, vn.w); t = fmaf(myb, vy.w, t); t = fmaf(mzb, vz.w, t); t3_ins(qb, t, s + 3);
        }

        {
            size_t base = ((size_t)b * NN + na) * 3;
            float d0 = qa.d0 + n1a, d1 = qa.d1 + n1a, d2 = qa.d2 + n1a;
            float w0 = 1.0f / (d0 + 1e-8f), w1 = 1.0f / (d1 + 1e-8f), w2 = 1.0f / (d2 + 1e-8f);
            float inv = 1.0f / (w0 + w1 + w2);
            g_idx[base + 0] = qa.i0; g_idx[base + 1] = qa.i1; g_idx[base + 2] = qa.i2;
            g_wgt[base + 0] = w0 * inv; g_wgt[base + 1] = w1 * inv; g_wgt[base + 2] = w2 * inv;
        }
        {
            size_t base = ((size_t)b * NN + nb) * 3;
            float d0 = qb.d0 + n1b, d1 = qb.d1 + n1b, d2 = qb.d2 + n1b;
            float w0 = 1.0f / (d0 + 1e-8f), w1 = 1.0f / (d1 + 1e-8f), w2 = 1.0f / (d2 + 1e-8f);
            float inv = 1.0f / (w0 + w1 + w2);
            g_idx[base + 0] = qb.i0; g_idx[base + 1] = qb.i1; g_idx[base + 2] = qb.i2;
            g_wgt[base + 0] = w0 * inv; g_wgt[base + 1] = w1 * inv; g_wgt[base + 2] = w2 * inv;
        }
        return;
    }
    r -= NB_T3;
    if (r < NB_P2) {
        int b = r >> 10, y = (r >> 6) & 15, x = r & 63;
        int c0 = y * 32, s0 = x * 32;
        int tx = tid & 31, ty = tid >> 5;
        float (*t)[33] = (float(*)[33])sh;
#pragma unroll
        for (int j = ty; j < 32; j += 8)
            t[j][tx] = p2[((size_t)b * D2 + c0 + j) * SS + s0 + tx];
        __syncthreads();
#pragma unroll
        for (int j = ty; j < 32; j += 8)
            g_P2T[((size_t)b * SS + s0 + j) * D2 + c0 + tx] = __float2half_rn(t[tx][j]);
        return;
    }
    r -= NB_P2;
    if (r < NB_P1) {
        int b = r >> 11, y = (r >> 8) & 7, x = r & 255;
        int c0 = y * 32, n0 = x * 32;
        int tx = tid & 31, ty = tid >> 5;
        float (*t)[33] = (float(*)[33])sh;
#pragma unroll
        for (int j = ty; j < 32; j += 8)
            t[j][tx] = p1[((size_t)b * D1 + c0 + j) * NN + n0 + tx];
        __syncthreads();
#pragma unroll
        for (int j = ty; j < 32; j += 8) {
            size_t off = ((size_t)b * NN + n0 + j) * CIN + c0 + tx;
            g_FT[off] = __float2half_rn(t[tx][j]);
        }
        return;
    }
    r -= NB_P1;
    if (r < NB_C0 + NB_C1) {
        const float* src;
        h16* dst;
        int i;
        if (r < NB_C0) { src = w0g; dst = g_W0; i = r * 1024 + tid * 4; }
        else { src = w1g; dst = g_W1; i = (r - NB_C0) * 1024 + tid * 4; }
        float4 v = *(const float4*)(src + i);
        *(uint2*)&dst[i] = make_uint2(
            pack2h(__float2half_rn(v.x), __float2half_rn(v.y)),
            pack2h(__float2half_rn(v.z), __float2half_rn(v.w)));
        return;
    }
    if (tid < 256) {
        g_sum0[tid] = 0.f; g_sum0[tid + 256] = 0.f;
        g_sq0[tid] = 0.f;  g_sq0[tid + 256] = 0.f;
        g_sum1[tid] = 0.f; g_sum1[tid + 256] = 0.f;
        g_sq1[tid] = 0.f;  g_sq1[tid + 256] = 0.f;
    }
}

// ---------------- gather + interpolate -> g_FT[:, :, 256:768] (fp16 in/out) ----------------
__global__ void gather_kernel() {
    int wglob = blockIdx.x * 8 + (threadIdx.x >> 5);
    int lane = threadIdx.x & 31;
    int b = wglob / NN;
    size_t base = (size_t)wglob * 3;
    int i0 = g_idx[base + 0], i1 = g_idx[base + 1], i2 = g_idx[base + 2];
    float w0 = g_wgt[base + 0], w1 = g_wgt[base + 1], w2 = g_wgt[base + 2];
    const h16* r0 = g_P2T + ((size_t)b * SS + i0) * D2;
    const h16* r1 = g_P2T + ((size_t)b * SS + i1) * D2;
    const h16* r2 = g_P2T + ((size_t)b * SS + i2) * D2;
    size_t dbase = (size_t)wglob * CIN + D1;
#pragma unroll
    for (int c = lane * 4; c < D2; c += 128) {
        uint2 u0 = *(const uint2*)&r0[c];
        uint2 u1 = *(const uint2*)&r1[c];
        uint2 u2 = *(const uint2*)&r2[c];
        float2 a0 = h2f2(u0.x), a1 = h2f2(u0.y);
        float2 b0 = h2f2(u1.x), b1 = h2f2(u1.y);
        float2 c0 = h2f2(u2.x), c1 = h2f2(u2.y);
        float o0 = w0 * a0.x + w1 * b0.x + w2 * c0.x;
        float o1 = w0 * a0.y + w1 * b0.y + w2 * c0.y;
        float o2 = w0 * a1.x + w1 * b1.x + w2 * c1.x;
        float o3 = w0 * a1.y + w1 * b1.y + w2 * c1.y;
        *(uint2*)&g_FT[dbase + c] = make_uint2(
            pack2h(__float2half_rn(o0), __float2half_rn(o1)),
            pack2h(__float2half_rn(o2), __float2half_rn(o3)));
    }
}

// ======================= HMMA GEMM 1 (fp16, K-chunk 64, ring-2) =======================
#define T1B 18432                         // 128 rows x 144B (64 fp16 + 8 pad)
#define ST1 (2 * T1B)                     // stage: A, B = 36864
static constexpr int G1_SMEM = 2 * ST1;   // 73728 -> 2 CTAs/SM

__global__ __launch_bounds__(256, 2)
void hmma_gemm1(const h16* __restrict__ Ag, const h16* __restrict__ Bg,
                const float* __restrict__ bias, h16* __restrict__ out) {
    extern __shared__ char smem[];
    const uint32_t sb = smem_u32(smem);
    const int tid = threadIdx.x, lane = tid & 31, wid = tid >> 5;
    const int m0 = blockIdx.x * 128, n0 = blockIdx.y * 128, b = blockIdx.z;
    const int wm = (wid & 3) * 32, wn = (wid >> 2) * 64;

    const h16* Arow = Ag + (size_t)m0 * CIN;
    const h16* Brow = Bg + ((size_t)b * NN + n0) * CIN;

    float acc[2][8][4];
#pragma unroll
    for (int i = 0; i < 2; i++)
#pragma unroll
        for (int j = 0; j < 8; j++)
#pragma unroll
            for (int q = 0; q < 4; q++) acc[i][j][q] = 0.f;

    const int row_l = tid >> 3, seg = tid & 7;
    auto issue = [&](int kc) {
        const int kb = kc * 64;
        const uint32_t sbuf = sb + (kc & 1) * ST1;
#pragma unroll
        for (int t = 0; t < 4; t++) {
            int row = row_l + t * 32;
            uint32_t d = sbuf + row * 144 + seg * 16;
            cpa16(d,       Arow + (size_t)row * CIN + kb + seg * 8);
            cpa16(d + T1B, Brow + (size_t)row * CIN + kb + seg * 8);
        }
        CP_COMMIT();
    };

    const int KT = CIN / 64;   // 12
    issue(0);

    for (int c = 0; c < KT; c++) {
        const int buf = c & 1;
        if (c + 1 < KT) {
            issue(c + 1);
            CP_WAIT(1);
        } else {
            CP_WAIT(0);
        }
        __syncthreads();

        const uint32_t sA = sb + buf * ST1;
        const uint32_t sB = sA + T1B;
#pragma unroll
        for (int ks = 0; ks < 4; ks++) {
            const int k16 = ks * 16;
            uint32_t ah[2][4];
#pragma unroll
            for (int mi = 0; mi < 2; mi++) {
                uint32_t ad = sA + (wm + mi * 16 + (lane & 15)) * 144
                                 + (k16 + ((lane >> 4) << 3)) * 2;
                ldsm4(ah[mi][0], ah[mi][1], ah[mi][2], ah[mi][3], ad);
            }
#pragma unroll
            for (int ng = 0; ng < 4; ng++) {
                uint32_t row = wn + ng * 16 + (lane & 7) + ((lane & 16) >> 1);
                uint32_t col = k16 + (lane & 8);
                uint32_t ad = sB + row * 144 + col * 2;
                uint32_t bh[4];
                ldsm4(bh[0], bh[1], bh[2], bh[3], ad);
#pragma unroll
                for (int mi = 0; mi < 2; mi++) {
                    mma16816(acc[mi][2 * ng],     ah[mi], bh);
                    mma16816(acc[mi][2 * ng + 1], ah[mi], bh + 2);
                }
            }
        }
        __syncthreads();
    }

    // epilogue -> out fp16 (b, m, n) + bias, fused channel stats via atomics
    const int gq = lane >> 2, tq = lane & 3;
#pragma unroll
    for (int mi = 0; mi < 2; mi++) {
        int r0 = m0 + wm + mi * 16 + gq;
        float bv0 = bias[r0], bv1 = bias[r0 + 8];
        h16* o0 = out + ((size_t)b * HH + r0) * NN;
        h16* o1 = o0 + (size_t)8 * NN;
        float s0 = 0.f, q0 = 0.f, s1 = 0.f, q1 = 0.f;
#pragma unroll
        for (int ni = 0; ni < 8; ni++) {
            int cc = n0 + wn + ni * 8 + tq * 2;
            float y0 = acc[mi][ni][0] + bv0, y1 = acc[mi][ni][1] + bv0;
            float y2 = acc[mi][ni][2] + bv1, y3 = acc[mi][ni][3] + bv1;
            *(uint32_t*)&o0[cc] = pack2h(__float2half_rn(y0), __float2half_rn(y1));
            *(uint32_t*)&o1[cc] = pack2h(__float2half_rn(y2), __float2half_rn(y3));
            s0 += y0 + y1; q0 += y0 * y0 + y1 * y1;
            s1 += y2 + y3; q1 += y2 * y2 + y3 * y3;
        }
#pragma unroll
        for (int o = 1; o <= 2; o <<= 1) {
            s0 += __shfl_xor_sync(~0u, s0, o);
            q0 += __shfl_xor_sync(~0u, q0, o);
            s1 += __shfl_xor_sync(~0u, s1, o);
            q1 += __shfl_xor_sync(~0u, q1, o);
        }
        if (tq == 0) {
            atomicAdd(&g_sum0[r0], s0);     atomicAdd(&g_sq0[r0], q0);
            atomicAdd(&g_sum0[r0 + 8], s1); atomicAdd(&g_sq0[r0 + 8], q1);
        }
    }
}

// ======================= HMMA GEMM 2 (fp16, K-chunk 64, in-kernel BN coeffs) =======================
#define AT2 18432                // A stage: 128 x 144B
#define BT2 17408                // B stage: 64 k-rows x 272B
#define SC2_OFF (2 * AT2 + 2 * BT2)                  // 71680
static constexpr int G2_SMEM = SC2_OFF + 2 * HH * 4; // 75776 -> 2 CTAs/SM

__global__ __launch_bounds__(256, 2)
void hmma_gemm2(const h16* __restrict__ Ag,
                const h16* __restrict__ X0,
                const float* __restrict__ gsum, const float* __restrict__ gsq,
                const float* __restrict__ g0, const float* __restrict__ be0,
                const float* __restrict__ bias, float* __restrict__ out) {
    extern __shared__ char smem[];
    const uint32_t sb = smem_u32(smem);
    const int tid = threadIdx.x, lane = tid & 31, wid = tid >> 5;
    const int m0 = blockIdx.x * 128, n0 = blockIdx.y * 128, b = blockIdx.z;
    const int wm = (wid & 3) * 32, wn = (wid >> 2) * 64;

    float* sScale = (float*)(smem + SC2_OFF);
    float* sShift = sScale + HH;

    const h16* Arow = Ag + (size_t)m0 * HH;
    const h16* Xb = X0 + (size_t)b * HH * NN + n0;

    float acc[2][8][4];
#pragma unroll
    for (int i = 0; i < 2; i++)
#pragma unroll
        for (int j = 0; j < 8; j++)
#pragma unroll
            for (int q = 0; q < 4; q++) acc[i][j][q] = 0.f;

    const int brow = tid >> 3, bcol = (tid & 7) * 16;
    uint4 xr[2][2];
    float scl[2], shf[2];

    const int row_l = tid >> 3, seg = tid & 7;
    auto issueA = [&](int kc) {
        const int kb = kc * 64;
        const uint32_t sbuf = sb + (kc & 1) * AT2;
#pragma unroll
        for (int t = 0; t < 4; t++) {
            int row = row_l + t * 32;
            uint32_t d = sbuf + row * 144 + seg * 16;
            cpa16(d, Arow + (size_t)row * HH + kb + seg * 8);
        }
        CP_COMMIT();
    };
    auto loadX = [&](int kb) {
#pragma unroll
        for (int half = 0; half < 2; half++) {
            int k = kb + brow + half * 32;
            const h16* src = Xb + (size_t)k * NN + bcol;
            xr[half][0] = *(const uint4*)src;
            xr[half][1] = *(const uint4*)(src + 8);
            scl[half] = sScale[k];
            shf[half] = sShift[k];
        }
    };

    // prologue: BN coefficients for layer 0 -> smem
    {
        const float inv = 1.f / (float)(BB * NN);
#pragma unroll
        for (int i = tid; i < HH; i += 256) {
            float m = gsum[i] * inv;
            float var = gsq[i] * inv - m * m;
            float sc = g0[i] * rsqrtf(var + 1e-5f);
            sScale[i] = sc;
            sShift[i] = be0[i] - m * sc;
        }
        issueA(0);
        __syncthreads();   // sScale/sShift visible before loadX
        loadX(0);
    }

    const uint32_t sBoff = 2 * AT2;
    const int KT = HH / 64;  // 8
    for (int c = 0; c < KT; c++) {
        const int buf = c & 1;
        // STS-transform chunk c into B buf (64 k-rows x 128 n)
        {
#pragma unroll
            for (int half = 0; half < 2; half++) {
                uint32_t doff = sBoff + buf * BT2 + (brow + half * 32) * 272 + bcol * 2;
                float s = scl[half], h = shf[half];
#pragma unroll
                for (int j = 0; j < 4; j++) {
                    float2 p = h2f2(j < 2 ? (j == 0 ? xr[half][0].x : xr[half][0].z)
                                          : (j == 2 ? xr[half][1].x : xr[half][1].z));
                    float2 q = h2f2(j < 2 ? (j == 0 ? xr[half][0].y : xr[half][0].w)
                                          : (j == 2 ? xr[half][1].y : xr[half][1].w));
                    float y0 = fmaxf(fmaf(p.x, s, h), 0.f);
                    float y1 = fmaxf(fmaf(p.y, s, h), 0.f);
                    float y2 = fmaxf(fmaf(q.x, s, h), 0.f);
                    float y3 = fmaxf(fmaf(q.y, s, h), 0.f);
                    *(uint2*)(smem + doff + j * 8) = make_uint2(
                        pack2h(__float2half_rn(y0), __float2half_rn(y1)),
                        pack2h(__float2half_rn(y2), __float2half_rn(y3)));
                }
            }
        }
        if (c + 1 < KT) {
            issueA(c + 1);
            loadX((c + 1) * 64);
            CP_WAIT(1);
        } else {
            CP_WAIT(0);
        }
        __syncthreads();

        const uint32_t sA = sb + buf * AT2;
        const uint32_t sB = sb + sBoff + buf * BT2;
#pragma unroll
        for (int ks = 0; ks < 4; ks++) {
            const int k16 = ks * 16;
            uint32_t ah[2][4];
#pragma unroll
            for (int mi = 0; mi < 2; mi++) {
                uint32_t ad = sA + (wm + mi * 16 + (lane & 15)) * 144
                                 + (k16 + ((lane >> 4) << 3)) * 2;
                ldsm4(ah[mi][0], ah[mi][1], ah[mi][2], ah[mi][3], ad);
            }
#pragma unroll
            for (int ng = 0; ng < 4; ng++) {
                uint32_t row = k16 + (lane & 7) + (lane & 8);
                uint32_t col = wn + ng * 16 + ((lane >> 4) << 3);
                uint32_t ad = sB + row * 272 + col * 2;
                uint32_t bh[4];
                ldsm4t(bh[0], bh[1], bh[2], bh[3], ad);
#pragma unroll
                for (int mi = 0; mi < 2; mi++) {
                    mma16816(acc[mi][2 * ng],     ah[mi], bh);
                    mma16816(acc[mi][2 * ng + 1], ah[mi], bh + 2);
                }
            }
        }
        __syncthreads();
    }

    const int gq = lane >> 2, tq = lane & 3;
#pragma unroll
    for (int mi = 0; mi < 2; mi++) {
        int r0 = m0 + wm + mi * 16 + gq;
        float bv0 = bias[r0], bv1 = bias[r0 + 8];
        float* o0 = out + ((size_t)b * HH + r0) * NN;
        float* o1 = o0 + (size_t)8 * NN;
        float s0 = 0.f, q0 = 0.f, s1 = 0.f, q1 = 0.f;
#pragma unroll
        for (int ni = 0; ni < 8; ni++) {
            int cc = n0 + wn + ni * 8 + tq * 2;
            float y0 = acc[mi][ni][0] + bv0, y1 = acc[mi][ni][1] + bv0;
            float y2 = acc[mi][ni][2] + bv1, y3 = acc[mi][ni][3] + bv1;
            *(float2*)&o0[cc] = make_float2(y0, y1);
            *(float2*)&o1[cc] = make_float2(y2, y3);
            s0 += y0 + y1; q0 += y0 * y0 + y1 * y1;
            s1 += y2 + y3; q1 += y2 * y2 + y3 * y3;
        }
#pragma unroll
        for (int o = 1; o <= 2; o <<= 1) {
            s0 += __shfl_xor_sync(~0u, s0, o);
            q0 += __shfl_xor_sync(~0u, q0, o);
            s1 += __shfl_xor_sync(~0u, s1, o);
            q1 += __shfl_xor_sync(~0u, q1, o);
        }
        if (tq == 0) {
            atomicAdd(&g_sum1[r0], s0);     atomicAdd(&g_sq1[r0], q0);
            atomicAdd(&g_sum1[r0 + 8], s1); atomicAdd(&g_sq1[r0 + 8], q1);
        }
    }
}

// ---------------- apply BN layer1 (coeffs computed in-kernel) ----------------
__global__ __launch_bounds__(256)
void apply_bn_kernel(float* __restrict__ X,
                     const float* __restrict__ g1, const float* __restrict__ be1) {
    __shared__ float sScale[HH], sShift[HH];
    const float inv = 1.f / (float)(BB * NN);
#pragma unroll
    for (int i = threadIdx.x; i < HH; i += 256) {
        float m = g_sum1[i] * inv;
        float var = g_sq1[i] * inv - m * m;
        float sc = g1[i] * rsqrtf(var + 1e-5f);
        sScale[i] = sc;
        sShift[i] = be1[i] - m * sc;
    }
    __syncthreads();
    const size_t total4 = (size_t)BB * HH * NN / 4;
    for (size_t i = (size_t)blockIdx.x * blockDim.x + threadIdx.x; i < total4;
         i += (size_t)gridDim.x * blockDim.x) {
        float4 v = __ldcs(&((float4*)X)[i]);
        int c = (int)((i * 4) >> 13) & (HH - 1);
        float s = sScale[c], h = sShift[c];
        v.x = fmaxf(fmaf(v.x, s, h), 0.f);
        v.y = fmaxf(fmaf(v.y, s, h), 0.f);
        v.z = fmaxf(fmaf(v.z, s, h), 0.f);
        v.w = fmaxf(fmaf(v.w, s, h), 0.f);
        __stcs(&((float4*)X)[i], v);
    }
}

// ======================= launcher =======================
extern "C" void kernel_launch(void* const* d_in, const int* in_sizes, int n_in,
                              void* d_out, int out_size) {
    const float* xyz1    = (const float*)d_in[0];
    const float* xyz2    = (const float*)d_in[1];
    const float* points1 = (const float*)d_in[2];
    const float* points2 = (const float*)d_in[3];
    const float* w0 = (const float*)d_in[4];
    const float* b0 = (const float*)d_in[5];
    const float* g0 = (const float*)d_in[6];
    const float* be0 = (const float*)d_in[7];
    const float* w1 = (const float*)d_in[8];
    const float* b1 = (const float*)d_in[9];
    const float* g1 = (const float*)d_in[10];
    const float* be1 = (const float*)d_in[11];
    float* out = (float*)d_out;

    float *p_sum0, *p_sq0;
    h16 *p_W0, *p_W1, *p_FT, *p_X0;
    cudaGetSymbolAddress((void**)&p_X0, g_X0);
    cudaGetSymbolAddress((void**)&p_sum0, g_sum0);
    cudaGetSymbolAddress((void**)&p_sq0, g_sq0);
    cudaGetSymbolAddress((void**)&p_W0, g_W0);
    cudaGetSymbolAddress((void**)&p_W1, g_W1);
    cudaGetSymbolAddress((void**)&p_FT, g_FT);

    cudaFuncSetAttribute(hmma_gemm1, cudaFuncAttributeMaxDynamicSharedMemorySize, G1_SMEM);
    cudaFuncSetAttribute(hmma_gemm2, cudaFuncAttributeMaxDynamicSharedMemorySize, G2_SMEM);

    prep_kernel<<<NB_TOTAL, 256>>>(xyz1, xyz2, points1, points2, w0, w1);
    gather_kernel<<<BB * NN / 8, 256>>>();

    hmma_gemm1<<<dim3(HH / 128, NN / 128, BB), 256, G1_SMEM>>>(
        p_W0, p_FT, b0, p_X0);

    hmma_gemm2<<<dim3(HH / 128, NN / 128, BB), 256, G2_SMEM>>>(
        p_W1, p_X0, p_sum0, p_sq0, g0, be0, b1, out);

    apply_bn_kernel<<<4096, 256>>>(out, g1, be1);
}